// round 1
// baseline (speedup 1.0000x reference)
#include <cuda_runtime.h>
#include <cuda_bf16.h>
#include <math.h>
#include <stddef.h>

#define S 4096
#define H 256
#define NH 6
#define G3 768
#define EPS 1e-5f

// ---------------- scratch (static device arrays; no allocation) ----------------
__device__ float g_x[S * H];            // embedded tokens
__device__ float g_q[NH * S * H];
__device__ float g_k[NH * S * H];
__device__ float g_v[NH * S * H];
__device__ float g_o[NH * S * H];       // attention output per head
__device__ float g_ypre[S * H];         // x + attn_proj (pre-LN)
__device__ float g_y[S * H];            // post-LN
__device__ float g_gi[S * G3];          // y @ W_ih^T + b_ih
__device__ float g_h[2][H];             // GRU hidden double buffer
#define RNN_B 16
#define RNN_T 384
__device__ int g_flags[RNN_B];

// ---------------- init (must re-run every graph replay) ----------------
__global__ void init_kernel() {
    int t = threadIdx.x;
    if (t < H) { g_h[0][t] = 0.f; g_h[1][t] = 0.f; }
    if (t < RNN_B) g_flags[t] = 0;
}

// ---------------- embedding gather ----------------
__global__ void embed_kernel(const int* __restrict__ tokens,
                             const float* __restrict__ emb) {
    int s = blockIdx.x;
    int tok = tokens[s];
    const float4* src = (const float4*)(emb + (size_t)tok * H);
    float4* dst = (float4*)(g_x + (size_t)s * H);
    dst[threadIdx.x] = src[threadIdx.x];   // 64 threads * 4
}

// ---------------- generic tiled GEMM (64x64 tile, 256 threads, 4x4 micro) ----
// MODE 0: C[z] = X @ W[z] + bias[z]         (QKV; K=256, N=256, z=head)
// MODE 1: C = gather(g_o) @ Wo + bo + g_x   (out-proj + residual; K=1536, N=256)
// MODE 2: C = y @ W_ih^T + b_ih             (K=256, N=768, B transposed)
template <int MODE>
__global__ __launch_bounds__(256) void gemm_k(const float* __restrict__ A,
                                              const float* __restrict__ B,
                                              const float* __restrict__ bias,
                                              const float* __restrict__ resid,
                                              float* __restrict__ C) {
    const int KTOT = (MODE == 1) ? 1536 : 256;
    const int NTOT = (MODE == 2) ? 768 : 256;
    __shared__ float As[64][65];
    __shared__ float Bs[64][65];
    int tid = threadIdx.x;
    int m0 = blockIdx.y * 64, n0 = blockIdx.x * 64;
    int z = blockIdx.z;
    const float* Bb = (MODE == 0) ? (B + (size_t)z * 256 * 256) : B;

    float acc[4][4];
#pragma unroll
    for (int i = 0; i < 4; i++)
#pragma unroll
        for (int j = 0; j < 4; j++) acc[i][j] = 0.f;

    int ty = tid >> 4, tx = tid & 15;

    for (int k0 = 0; k0 < KTOT; k0 += 64) {
        // --- load A tile ---
        const float* Asrc;
        if (MODE == 1) {
            int head = k0 >> 8;
            int d0 = k0 & 255;
            Asrc = A + (size_t)head * (S * 256) + d0;
        } else {
            Asrc = A + k0;
        }
#pragma unroll
        for (int i = 0; i < 16; i++) {
            int lin = i * 256 + tid;
            int m = lin >> 6, kk = lin & 63;
            As[m][kk] = Asrc[(size_t)(m0 + m) * 256 + kk];
        }
        // --- load B tile ---
        if (MODE == 2) {
#pragma unroll
            for (int i = 0; i < 16; i++) {
                int lin = i * 256 + tid;
                int n = lin >> 6, kk = lin & 63;
                Bs[kk][n] = Bb[(size_t)(n0 + n) * 256 + (k0 + kk)];
            }
        } else {
#pragma unroll
            for (int i = 0; i < 16; i++) {
                int lin = i * 256 + tid;
                int kk = lin >> 6, n = lin & 63;
                Bs[kk][n] = Bb[(size_t)(k0 + kk) * NTOT + n0 + n];
            }
        }
        __syncthreads();
#pragma unroll 8
        for (int kk = 0; kk < 64; kk++) {
            float a[4], b[4];
#pragma unroll
            for (int i = 0; i < 4; i++) a[i] = As[ty * 4 + i][kk];
#pragma unroll
            for (int j = 0; j < 4; j++) b[j] = Bs[kk][tx * 4 + j];
#pragma unroll
            for (int i = 0; i < 4; i++)
#pragma unroll
                for (int j = 0; j < 4; j++) acc[i][j] += a[i] * b[j];
        }
        __syncthreads();
    }

    // --- epilogue ---
#pragma unroll
    for (int i = 0; i < 4; i++) {
        int m = m0 + ty * 4 + i;
#pragma unroll
        for (int j = 0; j < 4; j++) {
            int n = n0 + tx * 4 + j;
            float v = acc[i][j];
            if (MODE == 0) {
                v += bias[z * 256 + n];
                C[(size_t)z * S * 256 + (size_t)m * 256 + n] = v;
            } else if (MODE == 1) {
                v += bias[n] + resid[(size_t)m * 256 + n];
                C[(size_t)m * 256 + n] = v;
            } else {
                v += bias[n];
                C[(size_t)m * 768 + n] = v;
            }
        }
    }
}

// ---------------- streaming attention (no-max softmax; scores are tiny) ------
// block: 256 threads, 64 queries, head dim 256, K tiles of 64
#define ATT_PAD 257
__global__ __launch_bounds__(256) void attn_kernel(const float* __restrict__ Q,
                                                   const float* __restrict__ K,
                                                   const float* __restrict__ V,
                                                   float* __restrict__ O) {
    extern __shared__ float sm[];
    float* Qs = sm;                         // 64 * 257
    float* Ks = Qs + 64 * ATT_PAD;          // 64 * 257
    float* Vs = Ks + 64 * ATT_PAD;          // 64 * 257
    float* Ps = Vs + 64 * ATT_PAD;          // 64 * 65

    int h = blockIdx.y;
    int q0 = blockIdx.x * 64;
    int tid = threadIdx.x;
    int ty = tid >> 4, tx = tid & 15;

    const float* Qg = Q + ((size_t)h * S + q0) * H;
    const float* Kg = K + (size_t)h * S * H;
    const float* Vg = V + (size_t)h * S * H;

    // load Q tile (transpose-free row-major, padded)
    for (int i = tid; i < 64 * 64; i += 256) {     // 64*64 float4 = 64x256 floats
        int q = i >> 6, d4 = i & 63;
        float4 val = ((const float4*)(Qg + (size_t)q * H))[d4];
        float* dst = Qs + q * ATT_PAD + d4 * 4;
        dst[0] = val.x; dst[1] = val.y; dst[2] = val.z; dst[3] = val.w;
    }

    float o[4][16];
#pragma unroll
    for (int i = 0; i < 4; i++)
#pragma unroll
        for (int j = 0; j < 16; j++) o[i][j] = 0.f;
    float l[4] = {0.f, 0.f, 0.f, 0.f};

    const float inv_scale = 0.0625f;  // 1/sqrt(256)

    for (int kt = 0; kt < S / 64; kt++) {
        __syncthreads();
        // load K/V tiles
        for (int i = tid; i < 64 * 64; i += 256) {
            int r = i >> 6, d4 = i & 63;
            float4 kv = ((const float4*)(Kg + (size_t)(kt * 64 + r) * H))[d4];
            float* kd = Ks + r * ATT_PAD + d4 * 4;
            kd[0] = kv.x; kd[1] = kv.y; kd[2] = kv.z; kd[3] = kv.w;
            float4 vv = ((const float4*)(Vg + (size_t)(kt * 64 + r) * H))[d4];
            float* vd = Vs + r * ATT_PAD + d4 * 4;
            vd[0] = vv.x; vd[1] = vv.y; vd[2] = vv.z; vd[3] = vv.w;
        }
        __syncthreads();

        // scores: 4x4 per thread
        float p[4][4];
#pragma unroll
        for (int i = 0; i < 4; i++)
#pragma unroll
            for (int j = 0; j < 4; j++) p[i][j] = 0.f;
#pragma unroll 4
        for (int d = 0; d < H; d++) {
            float a[4], b[4];
#pragma unroll
            for (int i = 0; i < 4; i++) a[i] = Qs[(ty * 4 + i) * ATT_PAD + d];
#pragma unroll
            for (int j = 0; j < 4; j++) b[j] = Ks[(tx * 4 + j) * ATT_PAD + d];
#pragma unroll
            for (int i = 0; i < 4; i++)
#pragma unroll
                for (int j = 0; j < 4; j++) p[i][j] += a[i] * b[j];
        }
        // exp (scores tiny -> no max subtraction needed) + row-sum + stash
#pragma unroll
        for (int i = 0; i < 4; i++) {
#pragma unroll
            for (int j = 0; j < 4; j++) {
                float e = __expf(p[i][j] * inv_scale);
                p[i][j] = e;
                l[i] += e;
                Ps[(ty * 4 + i) * 65 + tx * 4 + j] = e;
            }
        }
        __syncthreads();

        // o += P @ V   (thread: 4 queries x 16 dims, dims = tx*16..)
#pragma unroll 2
        for (int k = 0; k < 64; k++) {
            float pv[4];
#pragma unroll
            for (int i = 0; i < 4; i++) pv[i] = Ps[(ty * 4 + i) * 65 + k];
            const float* vrow = Vs + k * ATT_PAD + tx * 16;
#pragma unroll
            for (int j = 0; j < 16; j++) {
                float vv = vrow[j];
#pragma unroll
                for (int i = 0; i < 4; i++) o[i][j] += pv[i] * vv;
            }
        }
    }

    // reduce l across the 16 tx lanes (same query rows)
#pragma unroll
    for (int i = 0; i < 4; i++) {
        float s = l[i];
        s += __shfl_xor_sync(0xffffffffu, s, 1);
        s += __shfl_xor_sync(0xffffffffu, s, 2);
        s += __shfl_xor_sync(0xffffffffu, s, 4);
        s += __shfl_xor_sync(0xffffffffu, s, 8);
        l[i] = 1.f / s;
    }

    float* Og = O + ((size_t)h * S + q0) * H;
#pragma unroll
    for (int i = 0; i < 4; i++) {
        float* orow = Og + (size_t)(ty * 4 + i) * H + tx * 16;
#pragma unroll
        for (int j = 0; j < 16; j++) orow[j] = o[i][j] * l[i];
    }
}

// ---------------- LayerNorm (one warp per row) ----------------
__global__ __launch_bounds__(256) void ln_kernel(const float* __restrict__ yin,
                                                 const float* __restrict__ g,
                                                 const float* __restrict__ b,
                                                 float* __restrict__ yout) {
    int row = blockIdx.x * 8 + (threadIdx.x >> 5);
    int lane = threadIdx.x & 31;
    const float* yr = yin + (size_t)row * H;
    float v[8], s = 0.f, sq = 0.f;
#pragma unroll
    for (int i = 0; i < 8; i++) {
        v[i] = yr[lane + i * 32];
        s += v[i];
        sq += v[i] * v[i];
    }
#pragma unroll
    for (int m = 16; m >= 1; m >>= 1) {
        s += __shfl_xor_sync(0xffffffffu, s, m);
        sq += __shfl_xor_sync(0xffffffffu, sq, m);
    }
    float mu = s * (1.f / H);
    float var = sq * (1.f / H) - mu * mu;
    float rstd = rsqrtf(var + EPS);
    float* yo = yout + (size_t)row * H;
#pragma unroll
    for (int i = 0; i < 8; i++) {
        int c = lane + i * 32;
        yo[c] = (v[i] - mu) * rstd * g[c] + b[c];
    }
}

// ---------------- GRU recurrence: 16 CTAs, register-resident W_hh ------------
// thread layout: 48 groups x 8 lanes; group = gate*16 + jj; each lane holds 32
// weights of W_hh[row]. Per step: dot -> shfl reduce -> gate math (16 threads)
// -> h exchange via L2 (st + fence + per-block flag; ld.cv spin).
__global__ __launch_bounds__(RNN_T, 1) void rnn_kernel(const float* __restrict__ gi,
                                                       const float* __restrict__ Whh,
                                                       const float* __restrict__ bhh,
                                                       float* __restrict__ out,
                                                       int out_size) {
    int blk = blockIdx.x;
    int tid = threadIdx.x;
    int group = tid >> 3, lane = tid & 7;
    int gate = group >> 4, jj = group & 15;
    int row = gate * 256 + blk * 16 + jj;
    int col0 = lane * 32;

    float w[32];
#pragma unroll
    for (int i = 0; i < 32; i++) w[i] = Whh[(size_t)row * 256 + col0 + i];

    __shared__ float smg[48];

    int j = blk * 16 + tid;  // valid for tid<16
    float ir = 0.f, iz = 0.f, inn = 0.f, bh_r = 0.f, bh_z = 0.f, bh_n = 0.f;
    if (tid < 16) {
        ir = gi[j];
        iz = gi[256 + j];
        inn = gi[512 + j];
        bh_r = bhh[j];
        bh_z = bhh[256 + j];
        bh_n = bhh[512 + j];
    }

    for (int t = 0; t < S; t++) {
        int p = t & 1;
        const float4* hb = (const float4*)(&g_h[p][col0]);
        float acc = 0.f;
#pragma unroll
        for (int i = 0; i < 8; i++) {
            float4 hv = __ldcv(hb + i);
            acc += w[4 * i + 0] * hv.x + w[4 * i + 1] * hv.y +
                   w[4 * i + 2] * hv.z + w[4 * i + 3] * hv.w;
        }
        acc += __shfl_xor_sync(0xffffffffu, acc, 1);
        acc += __shfl_xor_sync(0xffffffffu, acc, 2);
        acc += __shfl_xor_sync(0xffffffffu, acc, 4);
        if (lane == 0) smg[group] = acc;
        __syncthreads();

        if (tid < 16) {
            float ghr = smg[tid] + bh_r;
            float ghz = smg[16 + tid] + bh_z;
            float ghn = smg[32 + tid] + bh_n;
            float hold = __ldcv(&g_h[p][j]);
            float r = 1.f / (1.f + __expf(-(ir + ghr)));
            float z = 1.f / (1.f + __expf(-(iz + ghz)));
            float n = tanhf(inn + r * ghn);
            float hnew = (1.f - z) * n + z * hold;
            g_h[p ^ 1][j] = hnew;
            __threadfence();
            // prefetch next token's gi (latency hidden by barrier round-trip)
            int tn = (t + 1 < S) ? (t + 1) : t;
            ir = gi[(size_t)tn * G3 + j];
            iz = gi[(size_t)tn * G3 + 256 + j];
            inn = gi[(size_t)tn * G3 + 512 + j];
        }
        __syncthreads();
        if (tid == 0) *((volatile int*)&g_flags[blk]) = t + 1;
        if (tid < RNN_B) {
            while (*((volatile int*)&g_flags[tid]) < t + 1) {}
        }
        __threadfence();
        __syncthreads();
    }

    if (blk == 0) {
        for (int i = tid; i < out_size; i += RNN_T)
            out[i] = __ldcv(&g_h[0][i & 255]);
    }
}

// ---------------- host launcher ----------------
extern "C" void kernel_launch(void* const* d_in, const int* in_sizes, int n_in,
                              void* d_out, int out_size) {
    const int* tokens = (const int*)d_in[0];
    const float* emb = (const float*)d_in[1];
    const float* Wq = (const float*)d_in[2];
    const float* bq = (const float*)d_in[3];
    const float* Wk = (const float*)d_in[4];
    const float* bk = (const float*)d_in[5];
    const float* Wv = (const float*)d_in[6];
    const float* bv = (const float*)d_in[7];
    const float* Wo = (const float*)d_in[8];
    const float* bo = (const float*)d_in[9];
    const float* ln_g = (const float*)d_in[10];
    const float* ln_b = (const float*)d_in[11];
    const float* W_ih = (const float*)d_in[12];
    const float* W_hh = (const float*)d_in[13];
    const float* b_ih = (const float*)d_in[14];
    const float* b_hh = (const float*)d_in[15];
    float* out = (float*)d_out;

    float* px; cudaGetSymbolAddress((void**)&px, g_x);
    float* pq; cudaGetSymbolAddress((void**)&pq, g_q);
    float* pk; cudaGetSymbolAddress((void**)&pk, g_k);
    float* pv; cudaGetSymbolAddress((void**)&pv, g_v);
    float* po; cudaGetSymbolAddress((void**)&po, g_o);
    float* pypre; cudaGetSymbolAddress((void**)&pypre, g_ypre);
    float* py; cudaGetSymbolAddress((void**)&py, g_y);
    float* pgi; cudaGetSymbolAddress((void**)&pgi, g_gi);

    size_t attn_smem = (size_t)(3 * 64 * ATT_PAD + 64 * 65) * sizeof(float);
    cudaFuncSetAttribute(attn_kernel, cudaFuncAttributeMaxDynamicSharedMemorySize,
                         (int)attn_smem);

    init_kernel<<<1, 256>>>();
    embed_kernel<<<S, 64>>>(tokens, emb);

    dim3 gqkv(4, 64, NH);
    gemm_k<0><<<gqkv, 256>>>(px, Wq, bq, nullptr, pq);
    gemm_k<0><<<gqkv, 256>>>(px, Wk, bk, nullptr, pk);
    gemm_k<0><<<gqkv, 256>>>(px, Wv, bv, nullptr, pv);

    dim3 gatt(S / 64, NH);
    attn_kernel<<<gatt, 256, attn_smem>>>(pq, pk, pv, po);

    dim3 gop(4, 64, 1);
    gemm_k<1><<<gop, 256>>>(po, Wo, bo, px, pypre);

    ln_kernel<<<S / 8, 256>>>(pypre, ln_g, ln_b, py);

    dim3 ggi(12, 64, 1);
    gemm_k<2><<<ggi, 256>>>(py, W_ih, b_ih, nullptr, pgi);

    rnn_kernel<<<RNN_B, RNN_T>>>(pgi, W_hh, b_hh, out, out_size);
}

// round 2
// speedup vs baseline: 1.0502x; 1.0502x over previous
#include <cuda_runtime.h>
#include <cuda_bf16.h>
#include <math.h>
#include <stddef.h>

#define S 4096
#define H 256
#define NH 6
#define G3 768
#define EPS 1e-5f

// ---------------- scratch (static device arrays; no allocation) ----------------
__device__ float g_x[S * H];            // embedded tokens
__device__ float g_q[NH * S * H];
__device__ float g_k[NH * S * H];
__device__ float g_v[NH * S * H];
__device__ float g_o[NH * S * H];       // attention output per head
__device__ float g_ypre[S * H];         // x + attn_proj (pre-LN)
__device__ float g_y[S * H];            // post-LN
__device__ float g_gi[S * G3];          // y @ W_ih^T + b_ih

// ---------------- embedding gather ----------------
__global__ void embed_kernel(const int* __restrict__ tokens,
                             const float* __restrict__ emb) {
    int s = blockIdx.x;
    int tok = tokens[s];
    const float4* src = (const float4*)(emb + (size_t)tok * H);
    float4* dst = (float4*)(g_x + (size_t)s * H);
    dst[threadIdx.x] = src[threadIdx.x];   // 64 threads * 4
}

// ---------------- generic tiled GEMM (64x64 tile, 256 threads, 4x4 micro) ----
// MODE 0: C[z] = X @ W[z] + bias[z]         (QKV; K=256, N=256, z=head)
// MODE 1: C = gather(g_o) @ Wo + bo + g_x   (out-proj + residual; K=1536, N=256)
// MODE 2: C = y @ W_ih^T + b_ih             (K=256, N=768, B transposed)
template <int MODE>
__global__ __launch_bounds__(256) void gemm_k(const float* __restrict__ A,
                                              const float* __restrict__ B,
                                              const float* __restrict__ bias,
                                              const float* __restrict__ resid,
                                              float* __restrict__ C) {
    const int KTOT = (MODE == 1) ? 1536 : 256;
    const int NTOT = (MODE == 2) ? 768 : 256;
    __shared__ float As[64][65];
    __shared__ float Bs[64][65];
    int tid = threadIdx.x;
    int m0 = blockIdx.y * 64, n0 = blockIdx.x * 64;
    int z = blockIdx.z;
    const float* Bb = (MODE == 0) ? (B + (size_t)z * 256 * 256) : B;

    float acc[4][4];
#pragma unroll
    for (int i = 0; i < 4; i++)
#pragma unroll
        for (int j = 0; j < 4; j++) acc[i][j] = 0.f;

    int ty = tid >> 4, tx = tid & 15;

    for (int k0 = 0; k0 < KTOT; k0 += 64) {
        const float* Asrc;
        if (MODE == 1) {
            int head = k0 >> 8;
            int d0 = k0 & 255;
            Asrc = A + (size_t)head * (S * 256) + d0;
        } else {
            Asrc = A + k0;
        }
#pragma unroll
        for (int i = 0; i < 16; i++) {
            int lin = i * 256 + tid;
            int m = lin >> 6, kk = lin & 63;
            As[m][kk] = Asrc[(size_t)(m0 + m) * 256 + kk];
        }
        if (MODE == 2) {
#pragma unroll
            for (int i = 0; i < 16; i++) {
                int lin = i * 256 + tid;
                int n = lin >> 6, kk = lin & 63;
                Bs[kk][n] = Bb[(size_t)(n0 + n) * 256 + (k0 + kk)];
            }
        } else {
#pragma unroll
            for (int i = 0; i < 16; i++) {
                int lin = i * 256 + tid;
                int kk = lin >> 6, n = lin & 63;
                Bs[kk][n] = Bb[(size_t)(k0 + kk) * NTOT + n0 + n];
            }
        }
        __syncthreads();
#pragma unroll 8
        for (int kk = 0; kk < 64; kk++) {
            float a[4], b[4];
#pragma unroll
            for (int i = 0; i < 4; i++) a[i] = As[ty * 4 + i][kk];
#pragma unroll
            for (int j = 0; j < 4; j++) b[j] = Bs[kk][tx * 4 + j];
#pragma unroll
            for (int i = 0; i < 4; i++)
#pragma unroll
                for (int j = 0; j < 4; j++) acc[i][j] += a[i] * b[j];
        }
        __syncthreads();
    }

#pragma unroll
    for (int i = 0; i < 4; i++) {
        int m = m0 + ty * 4 + i;
#pragma unroll
        for (int j = 0; j < 4; j++) {
            int n = n0 + tx * 4 + j;
            float v = acc[i][j];
            if (MODE == 0) {
                v += bias[z * 256 + n];
                C[(size_t)z * S * 256 + (size_t)m * 256 + n] = v;
            } else if (MODE == 1) {
                v += bias[n] + resid[(size_t)m * 256 + n];
                C[(size_t)m * 256 + n] = v;
            } else {
                v += bias[n];
                C[(size_t)m * 768 + n] = v;
            }
        }
    }
}

// ---------------- streaming attention (no-max softmax; scores are tiny) ------
#define ATT_PAD 257
__global__ __launch_bounds__(256) void attn_kernel(const float* __restrict__ Q,
                                                   const float* __restrict__ K,
                                                   const float* __restrict__ V,
                                                   float* __restrict__ O) {
    extern __shared__ float sm[];
    float* Qs = sm;                         // 64 * 257
    float* Ks = Qs + 64 * ATT_PAD;          // 64 * 257
    float* Vs = Ks + 64 * ATT_PAD;          // 64 * 257
    float* Ps = Vs + 64 * ATT_PAD;          // 64 * 65

    int h = blockIdx.y;
    int q0 = blockIdx.x * 64;
    int tid = threadIdx.x;
    int ty = tid >> 4, tx = tid & 15;

    const float* Qg = Q + ((size_t)h * S + q0) * H;
    const float* Kg = K + (size_t)h * S * H;
    const float* Vg = V + (size_t)h * S * H;

    for (int i = tid; i < 64 * 64; i += 256) {
        int q = i >> 6, d4 = i & 63;
        float4 val = ((const float4*)(Qg + (size_t)q * H))[d4];
        float* dst = Qs + q * ATT_PAD + d4 * 4;
        dst[0] = val.x; dst[1] = val.y; dst[2] = val.z; dst[3] = val.w;
    }

    float o[4][16];
#pragma unroll
    for (int i = 0; i < 4; i++)
#pragma unroll
        for (int j = 0; j < 16; j++) o[i][j] = 0.f;
    float l[4] = {0.f, 0.f, 0.f, 0.f};

    const float inv_scale = 0.0625f;  // 1/sqrt(256)

    for (int kt = 0; kt < S / 64; kt++) {
        __syncthreads();
        for (int i = tid; i < 64 * 64; i += 256) {
            int r = i >> 6, d4 = i & 63;
            float4 kv = ((const float4*)(Kg + (size_t)(kt * 64 + r) * H))[d4];
            float* kd = Ks + r * ATT_PAD + d4 * 4;
            kd[0] = kv.x; kd[1] = kv.y; kd[2] = kv.z; kd[3] = kv.w;
            float4 vv = ((const float4*)(Vg + (size_t)(kt * 64 + r) * H))[d4];
            float* vd = Vs + r * ATT_PAD + d4 * 4;
            vd[0] = vv.x; vd[1] = vv.y; vd[2] = vv.z; vd[3] = vv.w;
        }
        __syncthreads();

        float p[4][4];
#pragma unroll
        for (int i = 0; i < 4; i++)
#pragma unroll
            for (int j = 0; j < 4; j++) p[i][j] = 0.f;
#pragma unroll 4
        for (int d = 0; d < H; d++) {
            float a[4], b[4];
#pragma unroll
            for (int i = 0; i < 4; i++) a[i] = Qs[(ty * 4 + i) * ATT_PAD + d];
#pragma unroll
            for (int j = 0; j < 4; j++) b[j] = Ks[(tx * 4 + j) * ATT_PAD + d];
#pragma unroll
            for (int i = 0; i < 4; i++)
#pragma unroll
                for (int j = 0; j < 4; j++) p[i][j] += a[i] * b[j];
        }
#pragma unroll
        for (int i = 0; i < 4; i++) {
#pragma unroll
            for (int j = 0; j < 4; j++) {
                float e = __expf(p[i][j] * inv_scale);
                p[i][j] = e;
                l[i] += e;
                Ps[(ty * 4 + i) * 65 + tx * 4 + j] = e;
            }
        }
        __syncthreads();

#pragma unroll 2
        for (int k = 0; k < 64; k++) {
            float pv[4];
#pragma unroll
            for (int i = 0; i < 4; i++) pv[i] = Ps[(ty * 4 + i) * 65 + k];
            const float* vrow = Vs + k * ATT_PAD + tx * 16;
#pragma unroll
            for (int j = 0; j < 16; j++) {
                float vv = vrow[j];
#pragma unroll
                for (int i = 0; i < 4; i++) o[i][j] += pv[i] * vv;
            }
        }
    }

#pragma unroll
    for (int i = 0; i < 4; i++) {
        float s = l[i];
        s += __shfl_xor_sync(0xffffffffu, s, 1);
        s += __shfl_xor_sync(0xffffffffu, s, 2);
        s += __shfl_xor_sync(0xffffffffu, s, 4);
        s += __shfl_xor_sync(0xffffffffu, s, 8);
        l[i] = 1.f / s;
    }

    float* Og = O + ((size_t)h * S + q0) * H;
#pragma unroll
    for (int i = 0; i < 4; i++) {
        float* orow = Og + (size_t)(ty * 4 + i) * H + tx * 16;
#pragma unroll
        for (int j = 0; j < 16; j++) orow[j] = o[i][j] * l[i];
    }
}

// ---------------- LayerNorm (one warp per row) ----------------
__global__ __launch_bounds__(256) void ln_kernel(const float* __restrict__ yin,
                                                 const float* __restrict__ g,
                                                 const float* __restrict__ b,
                                                 float* __restrict__ yout) {
    int row = blockIdx.x * 8 + (threadIdx.x >> 5);
    int lane = threadIdx.x & 31;
    const float* yr = yin + (size_t)row * H;
    float v[8], s = 0.f, sq = 0.f;
#pragma unroll
    for (int i = 0; i < 8; i++) {
        v[i] = yr[lane + i * 32];
        s += v[i];
        sq += v[i] * v[i];
    }
#pragma unroll
    for (int m = 16; m >= 1; m >>= 1) {
        s += __shfl_xor_sync(0xffffffffu, s, m);
        sq += __shfl_xor_sync(0xffffffffu, sq, m);
    }
    float mu = s * (1.f / H);
    float var = sq * (1.f / H) - mu * mu;
    float rstd = rsqrtf(var + EPS);
    float* yo = yout + (size_t)row * H;
#pragma unroll
    for (int i = 0; i < 8; i++) {
        int c = lane + i * 32;
        yo[c] = (v[i] - mu) * rstd * g[c] + b[c];
    }
}

// ---------------- GRU recurrence: 8-CTA cluster, DSMEM h-exchange ------------
// Each CTA owns 32 h-dims (all 3 gates = 96 rows of W_hh) in registers (f32x2
// packed). Hidden state double-buffered in EACH CTA's own smem. After gate
// math, 32 threads broadcast new h values to all 8 CTAs via st.shared::cluster;
// one barrier.cluster per step provides ordering (arrive=release, wait=acquire).
#define RB 8
#define RT 768

__device__ __forceinline__ void cluster_arrive_wait() {
    asm volatile("barrier.cluster.arrive.aligned;" ::: "memory");
    asm volatile("barrier.cluster.wait.aligned;" ::: "memory");
}

__global__ void __cluster_dims__(RB, 1, 1) __launch_bounds__(RT, 1)
rnn_kernel(const float* __restrict__ gi,
           const float* __restrict__ Whh,
           const float* __restrict__ bhh,
           float* __restrict__ out,
           int out_size) {
    __shared__ __align__(16) float hbuf[2][H];
    __shared__ float smg[96];

    int blk = blockIdx.x;           // == cluster rank (grid = one cluster)
    int tid = threadIdx.x;
    int grp = tid >> 3, lane = tid & 7;
    int gate = grp >> 5, jj = grp & 31;
    int row = gate * 256 + blk * 32 + jj;
    int col0 = lane * 32;

    // register-resident W_hh slice, packed f32x2 (16 x b64 = 32 floats)
    unsigned long long w2[16];
    {
        const unsigned long long* wsrc =
            (const unsigned long long*)(Whh + (size_t)row * H + col0);
#pragma unroll
        for (int i = 0; i < 16; i++) w2[i] = wsrc[i];
    }

    // zero both h buffers (own copy)
    for (int i = tid; i < 2 * H; i += RT) ((float*)hbuf)[i] = 0.f;

    int j = blk * 32 + tid;  // valid for tid < 32
    float ir = 0.f, iz = 0.f, inn = 0.f, bh_r = 0.f, bh_z = 0.f, bh_n = 0.f;
    unsigned int laddr0 = 0, laddr1 = 0;
    if (tid < 32) {
        ir = gi[j];
        iz = gi[256 + j];
        inn = gi[512 + j];
        bh_r = bhh[j];
        bh_z = bhh[256 + j];
        bh_n = bhh[512 + j];
        unsigned int a0, a1;
        asm("{ .reg .u64 t; cvta.to.shared.u64 t, %1; cvt.u32.u64 %0, t; }"
            : "=r"(a0) : "l"(&hbuf[0][j]));
        asm("{ .reg .u64 t; cvta.to.shared.u64 t, %1; cvt.u32.u64 %0, t; }"
            : "=r"(a1) : "l"(&hbuf[1][j]));
        laddr0 = a0; laddr1 = a1;
    }
    __syncthreads();
    cluster_arrive_wait();   // all CTAs' buffers zeroed before anyone writes peers

    for (int t = 0; t < S; t++) {
        int p = t & 1;

        // dot: w2 . h  (packed f32x2)
        const unsigned long long* hq =
            (const unsigned long long*)(&hbuf[p][col0]);
        unsigned long long acc2 = 0ull;   // bit pattern == (0.f, 0.f)
#pragma unroll
        for (int i = 0; i < 16; i++) {
            asm("fma.rn.f32x2 %0, %1, %2, %0;"
                : "+l"(acc2) : "l"(w2[i]), "l"(hq[i]));
        }
        float lo, hi;
        asm("mov.b64 {%0, %1}, %2;" : "=f"(lo), "=f"(hi) : "l"(acc2));
        float acc = lo + hi;
        acc += __shfl_xor_sync(0xffffffffu, acc, 1);
        acc += __shfl_xor_sync(0xffffffffu, acc, 2);
        acc += __shfl_xor_sync(0xffffffffu, acc, 4);
        if (lane == 0) smg[grp] = acc;
        __syncthreads();

        if (tid < 32) {
            float ghr = smg[tid] + bh_r;
            float ghz = smg[32 + tid] + bh_z;
            float ghn = smg[64 + tid] + bh_n;
            float hold = hbuf[p][j];
            float r = 1.f / (1.f + __expf(-(ir + ghr)));
            float z = 1.f / (1.f + __expf(-(iz + ghz)));
            float narg = inn + r * ghn;
            // tanh(x) = 1 - 2/(1+exp(2x))
            float n = 1.f - 2.f / (1.f + __expf(2.f * narg));
            float hnew = (1.f - z) * n + z * hold;

            // broadcast to all 8 CTAs' hbuf[p^1][j]
            unsigned int la = p ? laddr0 : laddr1;
#pragma unroll
            for (int r2 = 0; r2 < RB; r2++) {
                unsigned int pa;
                asm volatile("mapa.shared::cluster.u32 %0, %1, %2;"
                             : "=r"(pa) : "r"(la), "r"(r2));
                asm volatile("st.shared::cluster.f32 [%0], %1;"
                             :: "r"(pa), "f"(hnew) : "memory");
            }
            // prefetch next token's gi
            int tn = (t + 1 < S) ? (t + 1) : t;
            ir = gi[(size_t)tn * G3 + j];
            iz = gi[(size_t)tn * G3 + 256 + j];
            inn = gi[(size_t)tn * G3 + 512 + j];
        }
        __syncthreads();
        cluster_arrive_wait();   // release own h-slice writes; acquire peers'
    }

    // final h lives in hbuf[0] (step 4095: p=1, wrote buffer 0)
    if (blk == 0) {
        for (int i = tid; i < out_size; i += RT)
            out[i] = hbuf[0][i & 255];
    }
}

// ---------------- host launcher ----------------
extern "C" void kernel_launch(void* const* d_in, const int* in_sizes, int n_in,
                              void* d_out, int out_size) {
    const int* tokens = (const int*)d_in[0];
    const float* emb = (const float*)d_in[1];
    const float* Wq = (const float*)d_in[2];
    const float* bq = (const float*)d_in[3];
    const float* Wk = (const float*)d_in[4];
    const float* bk = (const float*)d_in[5];
    const float* Wv = (const float*)d_in[6];
    const float* bv = (const float*)d_in[7];
    const float* Wo = (const float*)d_in[8];
    const float* bo = (const float*)d_in[9];
    const float* ln_g = (const float*)d_in[10];
    const float* ln_b = (const float*)d_in[11];
    const float* W_ih = (const float*)d_in[12];
    const float* W_hh = (const float*)d_in[13];
    const float* b_ih = (const float*)d_in[14];
    const float* b_hh = (const float*)d_in[15];
    float* out = (float*)d_out;

    float* px; cudaGetSymbolAddress((void**)&px, g_x);
    float* pq; cudaGetSymbolAddress((void**)&pq, g_q);
    float* pk; cudaGetSymbolAddress((void**)&pk, g_k);
    float* pv; cudaGetSymbolAddress((void**)&pv, g_v);
    float* po; cudaGetSymbolAddress((void**)&po, g_o);
    float* pypre; cudaGetSymbolAddress((void**)&pypre, g_ypre);
    float* py; cudaGetSymbolAddress((void**)&py, g_y);
    float* pgi; cudaGetSymbolAddress((void**)&pgi, g_gi);

    size_t attn_smem = (size_t)(3 * 64 * ATT_PAD + 64 * 65) * sizeof(float);
    cudaFuncSetAttribute(attn_kernel, cudaFuncAttributeMaxDynamicSharedMemorySize,
                         (int)attn_smem);

    embed_kernel<<<S, 64>>>(tokens, emb);

    dim3 gqkv(4, 64, NH);
    gemm_k<0><<<gqkv, 256>>>(px, Wq, bq, nullptr, pq);
    gemm_k<0><<<gqkv, 256>>>(px, Wk, bk, nullptr, pk);
    gemm_k<0><<<gqkv, 256>>>(px, Wv, bv, nullptr, pv);

    dim3 gatt(S / 64, NH);
    attn_kernel<<<gatt, 256, attn_smem>>>(pq, pk, pv, po);

    dim3 gop(4, 64, 1);
    gemm_k<1><<<gop, 256>>>(po, Wo, bo, px, pypre);

    ln_kernel<<<S / 8, 256>>>(pypre, ln_g, ln_b, py);

    dim3 ggi(12, 64, 1);
    gemm_k<2><<<ggi, 256>>>(py, W_ih, b_ih, nullptr, pgi);

    rnn_kernel<<<RB, RT>>>(pgi, W_hh, b_hh, out, out_size);
}

// round 3
// speedup vs baseline: 1.3287x; 1.2651x over previous
#include <cuda_runtime.h>
#include <cuda_bf16.h>
#include <math.h>
#include <stddef.h>

#define S 4096
#define H 256
#define NH 6
#define G3 768
#define EPS 1e-5f

// ---------------- scratch (static device arrays; no allocation) ----------------
__device__ float g_x[S * H];            // embedded tokens
__device__ float g_q[NH * S * H];
__device__ float g_k[NH * S * H];
__device__ float g_v[NH * S * H];
__device__ float g_o[NH * S * H];       // attention output per head
__device__ float g_ypre[S * H];         // x + attn_proj (pre-LN)
__device__ float g_y[S * H];            // post-LN
__device__ float g_gi[S * G3];          // y @ W_ih^T + b_ih

// ---------------- embedding gather ----------------
__global__ void embed_kernel(const int* __restrict__ tokens,
                             const float* __restrict__ emb) {
    int s = blockIdx.x;
    int tok = tokens[s];
    const float4* src = (const float4*)(emb + (size_t)tok * H);
    float4* dst = (float4*)(g_x + (size_t)s * H);
    dst[threadIdx.x] = src[threadIdx.x];   // 64 threads * 4
}

// ---------------- generic tiled GEMM (64x64 tile, 256 threads, 4x4 micro) ----
template <int MODE>
__global__ __launch_bounds__(256) void gemm_k(const float* __restrict__ A,
                                              const float* __restrict__ B,
                                              const float* __restrict__ bias,
                                              const float* __restrict__ resid,
                                              float* __restrict__ C) {
    const int KTOT = (MODE == 1) ? 1536 : 256;
    const int NTOT = (MODE == 2) ? 768 : 256;
    __shared__ float As[64][65];
    __shared__ float Bs[64][65];
    int tid = threadIdx.x;
    int m0 = blockIdx.y * 64, n0 = blockIdx.x * 64;
    int z = blockIdx.z;
    const float* Bb = (MODE == 0) ? (B + (size_t)z * 256 * 256) : B;

    float acc[4][4];
#pragma unroll
    for (int i = 0; i < 4; i++)
#pragma unroll
        for (int j = 0; j < 4; j++) acc[i][j] = 0.f;

    int ty = tid >> 4, tx = tid & 15;

    for (int k0 = 0; k0 < KTOT; k0 += 64) {
        const float* Asrc;
        if (MODE == 1) {
            int head = k0 >> 8;
            int d0 = k0 & 255;
            Asrc = A + (size_t)head * (S * 256) + d0;
        } else {
            Asrc = A + k0;
        }
#pragma unroll
        for (int i = 0; i < 16; i++) {
            int lin = i * 256 + tid;
            int m = lin >> 6, kk = lin & 63;
            As[m][kk] = Asrc[(size_t)(m0 + m) * 256 + kk];
        }
        if (MODE == 2) {
#pragma unroll
            for (int i = 0; i < 16; i++) {
                int lin = i * 256 + tid;
                int n = lin >> 6, kk = lin & 63;
                Bs[kk][n] = Bb[(size_t)(n0 + n) * 256 + (k0 + kk)];
            }
        } else {
#pragma unroll
            for (int i = 0; i < 16; i++) {
                int lin = i * 256 + tid;
                int kk = lin >> 6, n = lin & 63;
                Bs[kk][n] = Bb[(size_t)(k0 + kk) * NTOT + n0 + n];
            }
        }
        __syncthreads();
#pragma unroll 8
        for (int kk = 0; kk < 64; kk++) {
            float a[4], b[4];
#pragma unroll
            for (int i = 0; i < 4; i++) a[i] = As[ty * 4 + i][kk];
#pragma unroll
            for (int j = 0; j < 4; j++) b[j] = Bs[kk][tx * 4 + j];
#pragma unroll
            for (int i = 0; i < 4; i++)
#pragma unroll
                for (int j = 0; j < 4; j++) acc[i][j] += a[i] * b[j];
        }
        __syncthreads();
    }

#pragma unroll
    for (int i = 0; i < 4; i++) {
        int m = m0 + ty * 4 + i;
#pragma unroll
        for (int j = 0; j < 4; j++) {
            int n = n0 + tx * 4 + j;
            float v = acc[i][j];
            if (MODE == 0) {
                v += bias[z * 256 + n];
                C[(size_t)z * S * 256 + (size_t)m * 256 + n] = v;
            } else if (MODE == 1) {
                v += bias[n] + resid[(size_t)m * 256 + n];
                C[(size_t)m * 256 + n] = v;
            } else {
                v += bias[n];
                C[(size_t)m * 768 + n] = v;
            }
        }
    }
}

// ---------------- streaming attention (no-max softmax; scores are tiny) ------
// Q/V tiles padded to 260 floats/row (16B-aligned -> float4); K padded to 257
// (scalar loads, benign 2-way). PV output dims interleaved (j*16+tx) so Vs
// loads are lane-consecutive (conflict-free, was 16-way).
#define PAD_QV 260
#define PAD_K 257
__global__ __launch_bounds__(256) void attn_kernel(const float* __restrict__ Q,
                                                   const float* __restrict__ K,
                                                   const float* __restrict__ V,
                                                   float* __restrict__ O) {
    extern __shared__ float sm[];
    float* Qs = sm;                          // 64 * 260
    float* Ks = Qs + 64 * PAD_QV;            // 64 * 257
    float* Vs = Ks + 64 * PAD_K;             // 64 * 260
    float* Ps = Vs + 64 * PAD_QV;            // 64 * 65

    int h = blockIdx.y;
    int q0 = blockIdx.x * 64;
    int tid = threadIdx.x;
    int ty = tid >> 4, tx = tid & 15;

    const float* Qg = Q + ((size_t)h * S + q0) * H;
    const float* Kg = K + (size_t)h * S * H;
    const float* Vg = V + (size_t)h * S * H;

    // load Q tile (float4, rows 16B-aligned)
    for (int i = tid; i < 64 * 64; i += 256) {
        int q = i >> 6, d4 = i & 63;
        float4 val = ((const float4*)(Qg + (size_t)q * H))[d4];
        ((float4*)(Qs + q * PAD_QV))[d4] = val;
    }

    float o[4][16];
#pragma unroll
    for (int i = 0; i < 4; i++)
#pragma unroll
        for (int j = 0; j < 16; j++) o[i][j] = 0.f;
    float l[4] = {0.f, 0.f, 0.f, 0.f};

    const float inv_scale = 0.0625f;  // 1/sqrt(256)

    for (int kt = 0; kt < S / 64; kt++) {
        __syncthreads();
        for (int i = tid; i < 64 * 64; i += 256) {
            int r = i >> 6, d4 = i & 63;
            float4 kv = ((const float4*)(Kg + (size_t)(kt * 64 + r) * H))[d4];
            float* kd = Ks + r * PAD_K + d4 * 4;
            kd[0] = kv.x; kd[1] = kv.y; kd[2] = kv.z; kd[3] = kv.w;
            float4 vv = ((const float4*)(Vg + (size_t)(kt * 64 + r) * H))[d4];
            ((float4*)(Vs + r * PAD_QV))[d4] = vv;
        }
        __syncthreads();

        // scores: 4x4 per thread; Q via float4, K scalar
        float p[4][4];
#pragma unroll
        for (int i = 0; i < 4; i++)
#pragma unroll
            for (int j = 0; j < 4; j++) p[i][j] = 0.f;
#pragma unroll 2
        for (int d4 = 0; d4 < 64; d4++) {
            float a[4][4];
#pragma unroll
            for (int i = 0; i < 4; i++)
                *(float4*)&a[i][0] = ((const float4*)(Qs + (ty * 4 + i) * PAD_QV))[d4];
#pragma unroll
            for (int c = 0; c < 4; c++) {
                float b[4];
#pragma unroll
                for (int j = 0; j < 4; j++)
                    b[j] = Ks[(tx * 4 + j) * PAD_K + d4 * 4 + c];
#pragma unroll
                for (int i = 0; i < 4; i++)
#pragma unroll
                    for (int j = 0; j < 4; j++) p[i][j] += a[i][c] * b[j];
            }
        }
#pragma unroll
        for (int i = 0; i < 4; i++) {
#pragma unroll
            for (int j = 0; j < 4; j++) {
                float e = __expf(p[i][j] * inv_scale);
                p[i][j] = e;
                l[i] += e;
                Ps[(ty * 4 + i) * 65 + tx * 4 + j] = e;
            }
        }
        __syncthreads();

        // o += P @ V   (thread covers dims j*16+tx -> conflict-free Vs loads)
#pragma unroll 2
        for (int k = 0; k < 64; k++) {
            float pv[4];
#pragma unroll
            for (int i = 0; i < 4; i++) pv[i] = Ps[(ty * 4 + i) * 65 + k];
            const float* vrow = Vs + k * PAD_QV + tx;
#pragma unroll
            for (int j = 0; j < 16; j++) {
                float vv = vrow[j * 16];
#pragma unroll
                for (int i = 0; i < 4; i++) o[i][j] += pv[i] * vv;
            }
        }
    }

#pragma unroll
    for (int i = 0; i < 4; i++) {
        float s = l[i];
        s += __shfl_xor_sync(0xffffffffu, s, 1);
        s += __shfl_xor_sync(0xffffffffu, s, 2);
        s += __shfl_xor_sync(0xffffffffu, s, 4);
        s += __shfl_xor_sync(0xffffffffu, s, 8);
        l[i] = 1.f / s;
    }

    float* Og = O + ((size_t)h * S + q0) * H;
#pragma unroll
    for (int i = 0; i < 4; i++) {
        float* orow = Og + (size_t)(ty * 4 + i) * H + tx;
#pragma unroll
        for (int j = 0; j < 16; j++) orow[j * 16] = o[i][j] * l[i];
    }
}

// ---------------- LayerNorm (one warp per row) ----------------
__global__ __launch_bounds__(256) void ln_kernel(const float* __restrict__ yin,
                                                 const float* __restrict__ g,
                                                 const float* __restrict__ b,
                                                 float* __restrict__ yout) {
    int row = blockIdx.x * 8 + (threadIdx.x >> 5);
    int lane = threadIdx.x & 31;
    const float* yr = yin + (size_t)row * H;
    float v[8], s = 0.f, sq = 0.f;
#pragma unroll
    for (int i = 0; i < 8; i++) {
        v[i] = yr[lane + i * 32];
        s += v[i];
        sq += v[i] * v[i];
    }
#pragma unroll
    for (int m = 16; m >= 1; m >>= 1) {
        s += __shfl_xor_sync(0xffffffffu, s, m);
        sq += __shfl_xor_sync(0xffffffffu, sq, m);
    }
    float mu = s * (1.f / H);
    float var = sq * (1.f / H) - mu * mu;
    float rstd = rsqrtf(var + EPS);
    float* yo = yout + (size_t)row * H;
#pragma unroll
    for (int i = 0; i < 8; i++) {
        int c = lane + i * 32;
        yo[c] = (v[i] - mu) * rstd * g[c] + b[c];
    }
}

// ---------------- GRU recurrence: 8-CTA cluster, DSMEM h-exchange ------------
#define RB 8
#define RT 768

__device__ __forceinline__ void cluster_arrive_wait() {
    asm volatile("barrier.cluster.arrive.aligned;" ::: "memory");
    asm volatile("barrier.cluster.wait.aligned;" ::: "memory");
}

__global__ void __cluster_dims__(RB, 1, 1) __launch_bounds__(RT, 1)
rnn_kernel(const float* __restrict__ gi,
           const float* __restrict__ Whh,
           const float* __restrict__ bhh,
           float* __restrict__ out,
           int out_size) {
    __shared__ __align__(16) float hbuf[2][H];
    __shared__ float smg[96];

    int blk = blockIdx.x;
    int tid = threadIdx.x;
    int grp = tid >> 3, lane = tid & 7;
    int gate = grp >> 5, jj = grp & 31;
    int row = gate * 256 + blk * 32 + jj;
    int col0 = lane * 32;

    unsigned long long w2[16];
    {
        const unsigned long long* wsrc =
            (const unsigned long long*)(Whh + (size_t)row * H + col0);
#pragma unroll
        for (int i = 0; i < 16; i++) w2[i] = wsrc[i];
    }

    for (int i = tid; i < 2 * H; i += RT) ((float*)hbuf)[i] = 0.f;

    int j = blk * 32 + tid;
    float ir = 0.f, iz = 0.f, inn = 0.f, bh_r = 0.f, bh_z = 0.f, bh_n = 0.f;
    unsigned int laddr0 = 0, laddr1 = 0;
    if (tid < 32) {
        ir = gi[j];
        iz = gi[256 + j];
        inn = gi[512 + j];
        bh_r = bhh[j];
        bh_z = bhh[256 + j];
        bh_n = bhh[512 + j];
        unsigned int a0, a1;
        asm("{ .reg .u64 t; cvta.to.shared.u64 t, %1; cvt.u32.u64 %0, t; }"
            : "=r"(a0) : "l"(&hbuf[0][j]));
        asm("{ .reg .u64 t; cvta.to.shared.u64 t, %1; cvt.u32.u64 %0, t; }"
            : "=r"(a1) : "l"(&hbuf[1][j]));
        laddr0 = a0; laddr1 = a1;
    }
    __syncthreads();
    cluster_arrive_wait();

    for (int t = 0; t < S; t++) {
        int p = t & 1;

        const unsigned long long* hq =
            (const unsigned long long*)(&hbuf[p][col0]);
        unsigned long long acc2 = 0ull;
#pragma unroll
        for (int i = 0; i < 16; i++) {
            asm("fma.rn.f32x2 %0, %1, %2, %0;"
                : "+l"(acc2) : "l"(w2[i]), "l"(hq[i]));
        }
        float lo, hi;
        asm("mov.b64 {%0, %1}, %2;" : "=f"(lo), "=f"(hi) : "l"(acc2));
        float acc = lo + hi;
        acc += __shfl_xor_sync(0xffffffffu, acc, 1);
        acc += __shfl_xor_sync(0xffffffffu, acc, 2);
        acc += __shfl_xor_sync(0xffffffffu, acc, 4);
        if (lane == 0) smg[grp] = acc;
        __syncthreads();

        if (tid < 32) {
            float ghr = smg[tid] + bh_r;
            float ghz = smg[32 + tid] + bh_z;
            float ghn = smg[64 + tid] + bh_n;
            float hold = hbuf[p][j];
            float r = 1.f / (1.f + __expf(-(ir + ghr)));
            float z = 1.f / (1.f + __expf(-(iz + ghz)));
            float narg = inn + r * ghn;
            float n = 1.f - 2.f / (1.f + __expf(2.f * narg));
            float hnew = (1.f - z) * n + z * hold;

            unsigned int la = p ? laddr0 : laddr1;
#pragma unroll
            for (int r2 = 0; r2 < RB; r2++) {
                unsigned int pa;
                asm volatile("mapa.shared::cluster.u32 %0, %1, %2;"
                             : "=r"(pa) : "r"(la), "r"(r2));
                asm volatile("st.shared::cluster.f32 [%0], %1;"
                             :: "r"(pa), "f"(hnew) : "memory");
            }
            int tn = (t + 1 < S) ? (t + 1) : t;
            ir = gi[(size_t)tn * G3 + j];
            iz = gi[(size_t)tn * G3 + 256 + j];
            inn = gi[(size_t)tn * G3 + 512 + j];
        }
        // no CTA barrier needed here: cluster arrive/wait below orders the
        // producers' DSMEM stores against every CTA's next-step reads.
        cluster_arrive_wait();
    }

    if (blk == 0) {
        for (int i = tid; i < out_size; i += RT)
            out[i] = hbuf[0][i & 255];
    }
}

// ---------------- host launcher ----------------
extern "C" void kernel_launch(void* const* d_in, const int* in_sizes, int n_in,
                              void* d_out, int out_size) {
    const int* tokens = (const int*)d_in[0];
    const float* emb = (const float*)d_in[1];
    const float* Wq = (const float*)d_in[2];
    const float* bq = (const float*)d_in[3];
    const float* Wk = (const float*)d_in[4];
    const float* bk = (const float*)d_in[5];
    const float* Wv = (const float*)d_in[6];
    const float* bv = (const float*)d_in[7];
    const float* Wo = (const float*)d_in[8];
    const float* bo = (const float*)d_in[9];
    const float* ln_g = (const float*)d_in[10];
    const float* ln_b = (const float*)d_in[11];
    const float* W_ih = (const float*)d_in[12];
    const float* W_hh = (const float*)d_in[13];
    const float* b_ih = (const float*)d_in[14];
    const float* b_hh = (const float*)d_in[15];
    float* out = (float*)d_out;

    float* px; cudaGetSymbolAddress((void**)&px, g_x);
    float* pq; cudaGetSymbolAddress((void**)&pq, g_q);
    float* pk; cudaGetSymbolAddress((void**)&pk, g_k);
    float* pv; cudaGetSymbolAddress((void**)&pv, g_v);
    float* po; cudaGetSymbolAddress((void**)&po, g_o);
    float* pypre; cudaGetSymbolAddress((void**)&pypre, g_ypre);
    float* py; cudaGetSymbolAddress((void**)&py, g_y);
    float* pgi; cudaGetSymbolAddress((void**)&pgi, g_gi);

    size_t attn_smem = (size_t)(64 * PAD_QV * 2 + 64 * PAD_K + 64 * 65) * sizeof(float);
    cudaFuncSetAttribute(attn_kernel, cudaFuncAttributeMaxDynamicSharedMemorySize,
                         (int)attn_smem);

    embed_kernel<<<S, 64>>>(tokens, emb);

    dim3 gqkv(4, 64, NH);
    gemm_k<0><<<gqkv, 256>>>(px, Wq, bq, nullptr, pq);
    gemm_k<0><<<gqkv, 256>>>(px, Wk, bk, nullptr, pk);
    gemm_k<0><<<gqkv, 256>>>(px, Wv, bv, nullptr, pv);

    dim3 gatt(S / 64, NH);
    attn_kernel<<<gatt, 256, attn_smem>>>(pq, pk, pv, po);

    dim3 gop(4, 64, 1);
    gemm_k<1><<<gop, 256>>>(po, Wo, bo, px, pypre);

    ln_kernel<<<S / 8, 256>>>(pypre, ln_g, ln_b, py);

    dim3 ggi(12, 64, 1);
    gemm_k<2><<<ggi, 256>>>(py, W_ih, b_ih, nullptr, pgi);

    rnn_kernel<<<RB, RT>>>(pgi, W_hh, b_hh, out, out_size);
}

// round 4
// speedup vs baseline: 1.4039x; 1.0567x over previous
#include <cuda_runtime.h>
#include <cuda_bf16.h>
#include <mma.h>
#include <math.h>
#include <stddef.h>

using namespace nvcuda;

#define S 4096
#define H 256
#define NH 6
#define G3 768
#define EPS 1e-5f

// ---------------- scratch (static device arrays; no allocation) ----------------
__device__ float g_x[S * H];            // embedded tokens
__device__ float g_q[NH * S * H];
__device__ float g_k[NH * S * H];
__device__ float g_v[NH * S * H];
__device__ float g_o[NH * S * H];       // attention output per head
__device__ float g_ypre[S * H];         // x + attn_proj (pre-LN)
__device__ float g_y[S * H];            // post-LN
__device__ float g_gi[S * G3];          // y @ W_ih^T + b_ih

// ---------------- embedding gather ----------------
__global__ void embed_kernel(const int* __restrict__ tokens,
                             const float* __restrict__ emb) {
    int s = blockIdx.x;
    int tok = tokens[s];
    const float4* src = (const float4*)(emb + (size_t)tok * H);
    float4* dst = (float4*)(g_x + (size_t)s * H);
    dst[threadIdx.x] = src[threadIdx.x];   // 64 threads * 4
}

// ---------------- generic tiled GEMM (64x64 tile, 256 threads, 4x4 micro) ----
template <int MODE>
__global__ __launch_bounds__(256) void gemm_k(const float* __restrict__ A,
                                              const float* __restrict__ B,
                                              const float* __restrict__ bias,
                                              const float* __restrict__ resid,
                                              float* __restrict__ C) {
    const int KTOT = (MODE == 1) ? 1536 : 256;
    const int NTOT = (MODE == 2) ? 768 : 256;
    __shared__ float As[64][65];
    __shared__ float Bs[64][65];
    int tid = threadIdx.x;
    int m0 = blockIdx.y * 64, n0 = blockIdx.x * 64;
    int z = blockIdx.z;
    const float* Bb = (MODE == 0) ? (B + (size_t)z * 256 * 256) : B;

    float acc[4][4];
#pragma unroll
    for (int i = 0; i < 4; i++)
#pragma unroll
        for (int j = 0; j < 4; j++) acc[i][j] = 0.f;

    int ty = tid >> 4, tx = tid & 15;

    for (int k0 = 0; k0 < KTOT; k0 += 64) {
        const float* Asrc;
        if (MODE == 1) {
            int head = k0 >> 8;
            int d0 = k0 & 255;
            Asrc = A + (size_t)head * (S * 256) + d0;
        } else {
            Asrc = A + k0;
        }
#pragma unroll
        for (int i = 0; i < 16; i++) {
            int lin = i * 256 + tid;
            int m = lin >> 6, kk = lin & 63;
            As[m][kk] = Asrc[(size_t)(m0 + m) * 256 + kk];
        }
        if (MODE == 2) {
#pragma unroll
            for (int i = 0; i < 16; i++) {
                int lin = i * 256 + tid;
                int n = lin >> 6, kk = lin & 63;
                Bs[kk][n] = Bb[(size_t)(n0 + n) * 256 + (k0 + kk)];
            }
        } else {
#pragma unroll
            for (int i = 0; i < 16; i++) {
                int lin = i * 256 + tid;
                int kk = lin >> 6, n = lin & 63;
                Bs[kk][n] = Bb[(size_t)(k0 + kk) * NTOT + n0 + n];
            }
        }
        __syncthreads();
#pragma unroll 8
        for (int kk = 0; kk < 64; kk++) {
            float a[4], b[4];
#pragma unroll
            for (int i = 0; i < 4; i++) a[i] = As[ty * 4 + i][kk];
#pragma unroll
            for (int j = 0; j < 4; j++) b[j] = Bs[kk][tx * 4 + j];
#pragma unroll
            for (int i = 0; i < 4; i++)
#pragma unroll
                for (int j = 0; j < 4; j++) acc[i][j] += a[i] * b[j];
        }
        __syncthreads();
    }

#pragma unroll
    for (int i = 0; i < 4; i++) {
        int m = m0 + ty * 4 + i;
#pragma unroll
        for (int j = 0; j < 4; j++) {
            int n = n0 + tx * 4 + j;
            float v = acc[i][j];
            if (MODE == 0) {
                v += bias[z * 256 + n];
                C[(size_t)z * S * 256 + (size_t)m * 256 + n] = v;
            } else if (MODE == 1) {
                v += bias[n] + resid[(size_t)m * 256 + n];
                C[(size_t)m * 256 + n] = v;
            } else {
                v += bias[n];
                C[(size_t)m * 768 + n] = v;
            }
        }
    }
}

// ---------------- WMMA tf32 streaming attention ------------------------------
// 64 queries per CTA, 8 warps (4 m-tiles x 2 n-groups). Scores via m16n16k8
// tf32 MMA, exp in-place in smem (no-max softmax: scores tiny), PV accumulated
// in register fragments across all K-tiles, one normalize at the end.
#define LDQ 268     // Q/K/V smem row pitch (floats): 268%32=12 -> <=2-way conflicts
#define LDP 76      // S/P smem row pitch
__global__ __launch_bounds__(256) void attn_kernel(const float* __restrict__ Q,
                                                   const float* __restrict__ K,
                                                   const float* __restrict__ V,
                                                   float* __restrict__ O) {
    extern __shared__ float sm[];
    float* Qs = sm;                     // 64 * LDQ
    float* Ks = Qs + 64 * LDQ;          // 64 * LDQ
    float* Vs = Ks + 64 * LDQ;          // 64 * LDQ
    float* Ps = Vs + 64 * LDQ;          // 64 * LDP  (S then exp in place)
    float* Ls = Ps + 64 * LDP;          // 64 row sums

    int h = blockIdx.y;
    int q0 = blockIdx.x * 64;
    int tid = threadIdx.x;
    int warp = tid >> 5;
    int wm = warp & 3;                  // m-tile: rows wm*16..wm*16+15
    int wn = warp >> 2;                 // n-group (0..1)

    const float* Qg = Q + ((size_t)h * S + q0) * H;
    const float* Kg = K + (size_t)h * S * H;
    const float* Vg = V + (size_t)h * S * H;

    // load Q tile (float4)
    for (int i = tid; i < 64 * 64; i += 256) {
        int q = i >> 6, d4 = i & 63;
        ((float4*)(Qs + q * LDQ))[d4] = ((const float4*)(Qg + (size_t)q * H))[d4];
    }

    // PV accumulators: each warp covers m16 x n128 (8 frags of n16)
    wmma::fragment<wmma::accumulator, 16, 16, 8, float> o_frag[8];
#pragma unroll
    for (int f = 0; f < 8; f++) wmma::fill_fragment(o_frag[f], 0.0f);

    int lrow = tid >> 2;                // row owned for exp/rowsum
    int lcol0 = (tid & 3) * 16;
    float l_part = 0.f;
    const float inv_scale = 0.0625f;    // 1/sqrt(256)

    for (int kt = 0; kt < S / 64; kt++) {
        __syncthreads();   // prev PV done before overwriting K/V & Ps
        for (int i = tid; i < 64 * 64; i += 256) {
            int r = i >> 6, d4 = i & 63;
            ((float4*)(Ks + r * LDQ))[d4] =
                ((const float4*)(Kg + (size_t)(kt * 64 + r) * H))[d4];
            ((float4*)(Vs + r * LDQ))[d4] =
                ((const float4*)(Vg + (size_t)(kt * 64 + r) * H))[d4];
        }
        __syncthreads();

        // ---- scores: S(64x64) = Q @ K^T ----
        {
            wmma::fragment<wmma::matrix_a, 16, 16, 8, wmma::precision::tf32,
                           wmma::row_major> af;
            wmma::fragment<wmma::matrix_b, 16, 16, 8, wmma::precision::tf32,
                           wmma::col_major> bf;
            wmma::fragment<wmma::accumulator, 16, 16, 8, float> c[2];
            wmma::fill_fragment(c[0], 0.0f);
            wmma::fill_fragment(c[1], 0.0f);
#pragma unroll 4
            for (int k = 0; k < 32; k++) {
                wmma::load_matrix_sync(af, Qs + (wm * 16) * LDQ + k * 8, LDQ);
#pragma unroll
                for (int e = 0; e < af.num_elements; e++)
                    af.x[e] = wmma::__float_to_tf32(af.x[e]);
#pragma unroll
                for (int nf = 0; nf < 2; nf++) {
                    wmma::load_matrix_sync(
                        bf, Ks + (wn * 32 + nf * 16) * LDQ + k * 8, LDQ);
#pragma unroll
                    for (int e = 0; e < bf.num_elements; e++)
                        bf.x[e] = wmma::__float_to_tf32(bf.x[e]);
                    wmma::mma_sync(c[nf], af, bf, c[nf]);
                }
            }
#pragma unroll
            for (int nf = 0; nf < 2; nf++)
                wmma::store_matrix_sync(
                    Ps + (wm * 16) * LDP + wn * 32 + nf * 16, c[nf], LDP,
                    wmma::mem_row_major);
        }
        __syncthreads();

        // ---- exp in place + row-sum partials ----
        {
            float* pr = Ps + lrow * LDP + lcol0;
            float ssum = 0.f;
#pragma unroll
            for (int j = 0; j < 16; j++) {
                float e = __expf(pr[j] * inv_scale);
                pr[j] = e;
                ssum += e;
            }
            l_part += ssum;
        }
        __syncthreads();

        // ---- PV: O(64x256) += P(64x64) @ V(64x256) ----
        {
            wmma::fragment<wmma::matrix_a, 16, 16, 8, wmma::precision::tf32,
                           wmma::row_major> pa;
            wmma::fragment<wmma::matrix_b, 16, 16, 8, wmma::precision::tf32,
                           wmma::row_major> vb;
#pragma unroll
            for (int k = 0; k < 8; k++) {
                wmma::load_matrix_sync(pa, Ps + (wm * 16) * LDP + k * 8, LDP);
#pragma unroll
                for (int e = 0; e < pa.num_elements; e++)
                    pa.x[e] = wmma::__float_to_tf32(pa.x[e]);
#pragma unroll
                for (int nf = 0; nf < 8; nf++) {
                    wmma::load_matrix_sync(
                        vb, Vs + (k * 8) * LDQ + wn * 128 + nf * 16, LDQ);
#pragma unroll
                    for (int e = 0; e < vb.num_elements; e++)
                        vb.x[e] = wmma::__float_to_tf32(vb.x[e]);
                    wmma::mma_sync(o_frag[nf], pa, vb, o_frag[nf]);
                }
            }
        }
    }

    // row-sum finalize (4 partial owners per row are consecutive lanes)
    l_part += __shfl_xor_sync(0xffffffffu, l_part, 1);
    l_part += __shfl_xor_sync(0xffffffffu, l_part, 2);
    if ((tid & 3) == 0) Ls[lrow] = l_part;

    // stage O fragments into Qs (no longer needed)
#pragma unroll
    for (int nf = 0; nf < 8; nf++)
        wmma::store_matrix_sync(Qs + (wm * 16) * LDQ + wn * 128 + nf * 16,
                                o_frag[nf], LDQ, wmma::mem_row_major);
    __syncthreads();

    // normalize + write out
    float* Og = O + ((size_t)h * S + q0) * H;
    for (int i = tid; i < 64 * 64; i += 256) {
        int q = i >> 6, d4 = i & 63;
        float inv_l = __frcp_rn(Ls[q]);
        float4 v = ((float4*)(Qs + q * LDQ))[d4];
        v.x *= inv_l; v.y *= inv_l; v.z *= inv_l; v.w *= inv_l;
        ((float4*)(Og + (size_t)q * H))[d4] = v;
    }
}

// ---------------- LayerNorm (one warp per row) ----------------
__global__ __launch_bounds__(256) void ln_kernel(const float* __restrict__ yin,
                                                 const float* __restrict__ g,
                                                 const float* __restrict__ b,
                                                 float* __restrict__ yout) {
    int row = blockIdx.x * 8 + (threadIdx.x >> 5);
    int lane = threadIdx.x & 31;
    const float* yr = yin + (size_t)row * H;
    float v[8], s = 0.f, sq = 0.f;
#pragma unroll
    for (int i = 0; i < 8; i++) {
        v[i] = yr[lane + i * 32];
        s += v[i];
        sq += v[i] * v[i];
    }
#pragma unroll
    for (int m = 16; m >= 1; m >>= 1) {
        s += __shfl_xor_sync(0xffffffffu, s, m);
        sq += __shfl_xor_sync(0xffffffffu, sq, m);
    }
    float mu = s * (1.f / H);
    float var = sq * (1.f / H) - mu * mu;
    float rstd = rsqrtf(var + EPS);
    float* yo = yout + (size_t)row * H;
#pragma unroll
    for (int i = 0; i < 8; i++) {
        int c = lane + i * 32;
        yo[c] = (v[i] - mu) * rstd * g[c] + b[c];
    }
}

// ---------------- GRU recurrence: 8-CTA cluster, DSMEM h-exchange ------------
#define RB 8
#define RT 768

__device__ __forceinline__ void cluster_arrive_wait() {
    asm volatile("barrier.cluster.arrive.aligned;" ::: "memory");
    asm volatile("barrier.cluster.wait.aligned;" ::: "memory");
}

__global__ void __cluster_dims__(RB, 1, 1) __launch_bounds__(RT, 1)
rnn_kernel(const float* __restrict__ gi,
           const float* __restrict__ Whh,
           const float* __restrict__ bhh,
           float* __restrict__ out,
           int out_size) {
    __shared__ __align__(16) float hbuf[2][H];
    __shared__ float smg[96];

    int blk = blockIdx.x;
    int tid = threadIdx.x;
    int grp = tid >> 3, lane = tid & 7;
    int gate = grp >> 5, jj = grp & 31;
    int row = gate * 256 + blk * 32 + jj;
    int col0 = lane * 32;

    unsigned long long w2[16];
    {
        const unsigned long long* wsrc =
            (const unsigned long long*)(Whh + (size_t)row * H + col0);
#pragma unroll
        for (int i = 0; i < 16; i++) w2[i] = wsrc[i];
    }

    for (int i = tid; i < 2 * H; i += RT) ((float*)hbuf)[i] = 0.f;

    int j = blk * 32 + tid;
    float ir = 0.f, iz = 0.f, inn = 0.f, bh_r = 0.f, bh_z = 0.f, bh_n = 0.f;
    unsigned int laddr0 = 0, laddr1 = 0;
    if (tid < 32) {
        ir = gi[j];
        iz = gi[256 + j];
        inn = gi[512 + j];
        bh_r = bhh[j];
        bh_z = bhh[256 + j];
        bh_n = bhh[512 + j];
        unsigned int a0, a1;
        asm("{ .reg .u64 t; cvta.to.shared.u64 t, %1; cvt.u32.u64 %0, t; }"
            : "=r"(a0) : "l"(&hbuf[0][j]));
        asm("{ .reg .u64 t; cvta.to.shared.u64 t, %1; cvt.u32.u64 %0, t; }"
            : "=r"(a1) : "l"(&hbuf[1][j]));
        laddr0 = a0; laddr1 = a1;
    }
    __syncthreads();
    cluster_arrive_wait();

    for (int t = 0; t < S; t++) {
        int p = t & 1;

        const unsigned long long* hq =
            (const unsigned long long*)(&hbuf[p][col0]);
        unsigned long long acc2 = 0ull;
#pragma unroll
        for (int i = 0; i < 16; i++) {
            asm("fma.rn.f32x2 %0, %1, %2, %0;"
                : "+l"(acc2) : "l"(w2[i]), "l"(hq[i]));
        }
        float lo, hi;
        asm("mov.b64 {%0, %1}, %2;" : "=f"(lo), "=f"(hi) : "l"(acc2));
        float acc = lo + hi;
        acc += __shfl_xor_sync(0xffffffffu, acc, 1);
        acc += __shfl_xor_sync(0xffffffffu, acc, 2);
        acc += __shfl_xor_sync(0xffffffffu, acc, 4);
        if (lane == 0) smg[grp] = acc;
        __syncthreads();

        if (tid < 32) {
            float ghr = smg[tid] + bh_r;
            float ghz = smg[32 + tid] + bh_z;
            float ghn = smg[64 + tid] + bh_n;
            float hold = hbuf[p][j];
            float r = 1.f / (1.f + __expf(-(ir + ghr)));
            float z = 1.f / (1.f + __expf(-(iz + ghz)));
            float narg = inn + r * ghn;
            float n = 1.f - 2.f / (1.f + __expf(2.f * narg));
            float hnew = (1.f - z) * n + z * hold;

            unsigned int la = p ? laddr0 : laddr1;
#pragma unroll
            for (int r2 = 0; r2 < RB; r2++) {
                unsigned int pa;
                asm volatile("mapa.shared::cluster.u32 %0, %1, %2;"
                             : "=r"(pa) : "r"(la), "r"(r2));
                asm volatile("st.shared::cluster.f32 [%0], %1;"
                             :: "r"(pa), "f"(hnew) : "memory");
            }
            int tn = (t + 1 < S) ? (t + 1) : t;
            ir = gi[(size_t)tn * G3 + j];
            iz = gi[(size_t)tn * G3 + 256 + j];
            inn = gi[(size_t)tn * G3 + 512 + j];
        }
        cluster_arrive_wait();
    }

    if (blk == 0) {
        for (int i = tid; i < out_size; i += RT)
            out[i] = hbuf[0][i & 255];
    }
}

// ---------------- host launcher ----------------
extern "C" void kernel_launch(void* const* d_in, const int* in_sizes, int n_in,
                              void* d_out, int out_size) {
    const int* tokens = (const int*)d_in[0];
    const float* emb = (const float*)d_in[1];
    const float* Wq = (const float*)d_in[2];
    const float* bq = (const float*)d_in[3];
    const float* Wk = (const float*)d_in[4];
    const float* bk = (const float*)d_in[5];
    const float* Wv = (const float*)d_in[6];
    const float* bv = (const float*)d_in[7];
    const float* Wo = (const float*)d_in[8];
    const float* bo = (const float*)d_in[9];
    const float* ln_g = (const float*)d_in[10];
    const float* ln_b = (const float*)d_in[11];
    const float* W_ih = (const float*)d_in[12];
    const float* W_hh = (const float*)d_in[13];
    const float* b_ih = (const float*)d_in[14];
    const float* b_hh = (const float*)d_in[15];
    float* out = (float*)d_out;

    float* px; cudaGetSymbolAddress((void**)&px, g_x);
    float* pq; cudaGetSymbolAddress((void**)&pq, g_q);
    float* pk; cudaGetSymbolAddress((void**)&pk, g_k);
    float* pv; cudaGetSymbolAddress((void**)&pv, g_v);
    float* po; cudaGetSymbolAddress((void**)&po, g_o);
    float* pypre; cudaGetSymbolAddress((void**)&pypre, g_ypre);
    float* py; cudaGetSymbolAddress((void**)&py, g_y);
    float* pgi; cudaGetSymbolAddress((void**)&pgi, g_gi);

    size_t attn_smem = (size_t)(3 * 64 * LDQ + 64 * LDP + 64) * sizeof(float);
    cudaFuncSetAttribute(attn_kernel, cudaFuncAttributeMaxDynamicSharedMemorySize,
                         (int)attn_smem);

    embed_kernel<<<S, 64>>>(tokens, emb);

    dim3 gqkv(4, 64, NH);
    gemm_k<0><<<gqkv, 256>>>(px, Wq, bq, nullptr, pq);
    gemm_k<0><<<gqkv, 256>>>(px, Wk, bk, nullptr, pk);
    gemm_k<0><<<gqkv, 256>>>(px, Wv, bv, nullptr, pv);

    dim3 gatt(S / 64, NH);
    attn_kernel<<<gatt, 256, attn_smem>>>(pq, pk, pv, po);

    dim3 gop(4, 64, 1);
    gemm_k<1><<<gop, 256>>>(po, Wo, bo, px, pypre);

    ln_kernel<<<S / 8, 256>>>(pypre, ln_g, ln_b, py);

    dim3 ggi(12, 64, 1);
    gemm_k<2><<<ggi, 256>>>(py, W_ih, b_ih, nullptr, pgi);

    rnn_kernel<<<RB, RT>>>(pgi, W_hh, b_hh, out, out_size);
}

// round 5
// speedup vs baseline: 1.8129x; 1.2913x over previous
#include <cuda_runtime.h>
#include <cuda_bf16.h>
#include <mma.h>
#include <math.h>
#include <stddef.h>

using namespace nvcuda;

#define S 4096
#define H 256
#define NH 6
#define G3 768
#define EPS 1e-5f

// ---------------- scratch (static device arrays; no allocation) ----------------
__device__ float g_x[S * H];            // embedded tokens
__device__ float g_q[NH * S * H];
__device__ float g_k[NH * S * H];
__device__ float g_v[NH * S * H];
__device__ float g_o[NH * S * H];       // attention output per head
__device__ float g_ypre[S * H];         // x + attn_proj (pre-LN)
__device__ float g_y[S * H];            // post-LN
__device__ float g_gi[S * G3];          // y @ W_ih^T + b_ih

// ---------------- embedding gather ----------------
__global__ void embed_kernel(const int* __restrict__ tokens,
                             const float* __restrict__ emb) {
    int s = blockIdx.x;
    int tok = tokens[s];
    const float4* src = (const float4*)(emb + (size_t)tok * H);
    float4* dst = (float4*)(g_x + (size_t)s * H);
    dst[threadIdx.x] = src[threadIdx.x];   // 64 threads * 4
}

// ---------------- generic tiled GEMM (64x64 tile, 256 threads, 4x4 micro) ----
template <int MODE>
__global__ __launch_bounds__(256) void gemm_k(const float* __restrict__ A,
                                              const float* __restrict__ B,
                                              const float* __restrict__ bias,
                                              const float* __restrict__ resid,
                                              float* __restrict__ C) {
    const int KTOT = (MODE == 1) ? 1536 : 256;
    const int NTOT = (MODE == 2) ? 768 : 256;
    __shared__ float As[64][65];
    __shared__ float Bs[64][65];
    int tid = threadIdx.x;
    int m0 = blockIdx.y * 64, n0 = blockIdx.x * 64;
    int z = blockIdx.z;
    const float* Bb = (MODE == 0) ? (B + (size_t)z * 256 * 256) : B;

    float acc[4][4];
#pragma unroll
    for (int i = 0; i < 4; i++)
#pragma unroll
        for (int j = 0; j < 4; j++) acc[i][j] = 0.f;

    int ty = tid >> 4, tx = tid & 15;

    for (int k0 = 0; k0 < KTOT; k0 += 64) {
        const float* Asrc;
        if (MODE == 1) {
            int head = k0 >> 8;
            int d0 = k0 & 255;
            Asrc = A + (size_t)head * (S * 256) + d0;
        } else {
            Asrc = A + k0;
        }
#pragma unroll
        for (int i = 0; i < 16; i++) {
            int lin = i * 256 + tid;
            int m = lin >> 6, kk = lin & 63;
            As[m][kk] = Asrc[(size_t)(m0 + m) * 256 + kk];
        }
        if (MODE == 2) {
#pragma unroll
            for (int i = 0; i < 16; i++) {
                int lin = i * 256 + tid;
                int n = lin >> 6, kk = lin & 63;
                Bs[kk][n] = Bb[(size_t)(n0 + n) * 256 + (k0 + kk)];
            }
        } else {
#pragma unroll
            for (int i = 0; i < 16; i++) {
                int lin = i * 256 + tid;
                int kk = lin >> 6, n = lin & 63;
                Bs[kk][n] = Bb[(size_t)(k0 + kk) * NTOT + n0 + n];
            }
        }
        __syncthreads();
#pragma unroll 8
        for (int kk = 0; kk < 64; kk++) {
            float a[4], b[4];
#pragma unroll
            for (int i = 0; i < 4; i++) a[i] = As[ty * 4 + i][kk];
#pragma unroll
            for (int j = 0; j < 4; j++) b[j] = Bs[kk][tx * 4 + j];
#pragma unroll
            for (int i = 0; i < 4; i++)
#pragma unroll
                for (int j = 0; j < 4; j++) acc[i][j] += a[i] * b[j];
        }
        __syncthreads();
    }

#pragma unroll
    for (int i = 0; i < 4; i++) {
        int m = m0 + ty * 4 + i;
#pragma unroll
        for (int j = 0; j < 4; j++) {
            int n = n0 + tx * 4 + j;
            float v = acc[i][j];
            if (MODE == 0) {
                v += bias[z * 256 + n];
                C[(size_t)z * S * 256 + (size_t)m * 256 + n] = v;
            } else if (MODE == 1) {
                v += bias[n] + resid[(size_t)m * 256 + n];
                C[(size_t)m * 256 + n] = v;
            } else {
                v += bias[n];
                C[(size_t)m * 768 + n] = v;
            }
        }
    }
}

// ---------------- WMMA tf32 streaming attention ------------------------------
#define LDQ 268
#define LDP 76
__global__ __launch_bounds__(256) void attn_kernel(const float* __restrict__ Q,
                                                   const float* __restrict__ K,
                                                   const float* __restrict__ V,
                                                   float* __restrict__ O) {
    extern __shared__ float sm[];
    float* Qs = sm;
    float* Ks = Qs + 64 * LDQ;
    float* Vs = Ks + 64 * LDQ;
    float* Ps = Vs + 64 * LDQ;
    float* Ls = Ps + 64 * LDP;

    int h = blockIdx.y;
    int q0 = blockIdx.x * 64;
    int tid = threadIdx.x;
    int warp = tid >> 5;
    int wm = warp & 3;
    int wn = warp >> 2;

    const float* Qg = Q + ((size_t)h * S + q0) * H;
    const float* Kg = K + (size_t)h * S * H;
    const float* Vg = V + (size_t)h * S * H;

    for (int i = tid; i < 64 * 64; i += 256) {
        int q = i >> 6, d4 = i & 63;
        ((float4*)(Qs + q * LDQ))[d4] = ((const float4*)(Qg + (size_t)q * H))[d4];
    }

    wmma::fragment<wmma::accumulator, 16, 16, 8, float> o_frag[8];
#pragma unroll
    for (int f = 0; f < 8; f++) wmma::fill_fragment(o_frag[f], 0.0f);

    int lrow = tid >> 2;
    int lcol0 = (tid & 3) * 16;
    float l_part = 0.f;
    const float inv_scale = 0.0625f;

    for (int kt = 0; kt < S / 64; kt++) {
        __syncthreads();
        for (int i = tid; i < 64 * 64; i += 256) {
            int r = i >> 6, d4 = i & 63;
            ((float4*)(Ks + r * LDQ))[d4] =
                ((const float4*)(Kg + (size_t)(kt * 64 + r) * H))[d4];
            ((float4*)(Vs + r * LDQ))[d4] =
                ((const float4*)(Vg + (size_t)(kt * 64 + r) * H))[d4];
        }
        __syncthreads();

        {
            wmma::fragment<wmma::matrix_a, 16, 16, 8, wmma::precision::tf32,
                           wmma::row_major> af;
            wmma::fragment<wmma::matrix_b, 16, 16, 8, wmma::precision::tf32,
                           wmma::col_major> bf;
            wmma::fragment<wmma::accumulator, 16, 16, 8, float> c[2];
            wmma::fill_fragment(c[0], 0.0f);
            wmma::fill_fragment(c[1], 0.0f);
#pragma unroll 4
            for (int k = 0; k < 32; k++) {
                wmma::load_matrix_sync(af, Qs + (wm * 16) * LDQ + k * 8, LDQ);
#pragma unroll
                for (int e = 0; e < af.num_elements; e++)
                    af.x[e] = wmma::__float_to_tf32(af.x[e]);
#pragma unroll
                for (int nf = 0; nf < 2; nf++) {
                    wmma::load_matrix_sync(
                        bf, Ks + (wn * 32 + nf * 16) * LDQ + k * 8, LDQ);
#pragma unroll
                    for (int e = 0; e < bf.num_elements; e++)
                        bf.x[e] = wmma::__float_to_tf32(bf.x[e]);
                    wmma::mma_sync(c[nf], af, bf, c[nf]);
                }
            }
#pragma unroll
            for (int nf = 0; nf < 2; nf++)
                wmma::store_matrix_sync(
                    Ps + (wm * 16) * LDP + wn * 32 + nf * 16, c[nf], LDP,
                    wmma::mem_row_major);
        }
        __syncthreads();

        {
            float* pr = Ps + lrow * LDP + lcol0;
            float ssum = 0.f;
#pragma unroll
            for (int j = 0; j < 16; j++) {
                float e = __expf(pr[j] * inv_scale);
                pr[j] = e;
                ssum += e;
            }
            l_part += ssum;
        }
        __syncthreads();

        {
            wmma::fragment<wmma::matrix_a, 16, 16, 8, wmma::precision::tf32,
                           wmma::row_major> pa;
            wmma::fragment<wmma::matrix_b, 16, 16, 8, wmma::precision::tf32,
                           wmma::row_major> vb;
#pragma unroll
            for (int k = 0; k < 8; k++) {
                wmma::load_matrix_sync(pa, Ps + (wm * 16) * LDP + k * 8, LDP);
#pragma unroll
                for (int e = 0; e < pa.num_elements; e++)
                    pa.x[e] = wmma::__float_to_tf32(pa.x[e]);
#pragma unroll
                for (int nf = 0; nf < 8; nf++) {
                    wmma::load_matrix_sync(
                        vb, Vs + (k * 8) * LDQ + wn * 128 + nf * 16, LDQ);
#pragma unroll
                    for (int e = 0; e < vb.num_elements; e++)
                        vb.x[e] = wmma::__float_to_tf32(vb.x[e]);
                    wmma::mma_sync(o_frag[nf], pa, vb, o_frag[nf]);
                }
            }
        }
    }

    l_part += __shfl_xor_sync(0xffffffffu, l_part, 1);
    l_part += __shfl_xor_sync(0xffffffffu, l_part, 2);
    if ((tid & 3) == 0) Ls[lrow] = l_part;

#pragma unroll
    for (int nf = 0; nf < 8; nf++)
        wmma::store_matrix_sync(Qs + (wm * 16) * LDQ + wn * 128 + nf * 16,
                                o_frag[nf], LDQ, wmma::mem_row_major);
    __syncthreads();

    float* Og = O + ((size_t)h * S + q0) * H;
    for (int i = tid; i < 64 * 64; i += 256) {
        int q = i >> 6, d4 = i & 63;
        float inv_l = __frcp_rn(Ls[q]);
        float4 v = ((float4*)(Qs + q * LDQ))[d4];
        v.x *= inv_l; v.y *= inv_l; v.z *= inv_l; v.w *= inv_l;
        ((float4*)(Og + (size_t)q * H))[d4] = v;
    }
}

// ---------------- LayerNorm (one warp per row) ----------------
__global__ __launch_bounds__(256) void ln_kernel(const float* __restrict__ yin,
                                                 const float* __restrict__ g,
                                                 const float* __restrict__ b,
                                                 float* __restrict__ yout) {
    int row = blockIdx.x * 8 + (threadIdx.x >> 5);
    int lane = threadIdx.x & 31;
    const float* yr = yin + (size_t)row * H;
    float v[8], s = 0.f, sq = 0.f;
#pragma unroll
    for (int i = 0; i < 8; i++) {
        v[i] = yr[lane + i * 32];
        s += v[i];
        sq += v[i] * v[i];
    }
#pragma unroll
    for (int m = 16; m >= 1; m >>= 1) {
        s += __shfl_xor_sync(0xffffffffu, s, m);
        sq += __shfl_xor_sync(0xffffffffu, sq, m);
    }
    float mu = s * (1.f / H);
    float var = sq * (1.f / H) - mu * mu;
    float rstd = rsqrtf(var + EPS);
    float* yo = yout + (size_t)row * H;
#pragma unroll
    for (int i = 0; i < 8; i++) {
        int c = lane + i * 32;
        yo[c] = (v[i] - mu) * rstd * g[c] + b[c];
    }
}

// ---------------- GRU recurrence: 8-CTA cluster, mbarrier p/c sync -----------
// Each CTA owns 32 h-dims (96 rows of W_hh). Warp layout: warp w (0..23) holds
// rows w*4..w*4+3; lane holds 8 cols (lane*8..+7) -> 32 weights/thread, but h
// read is only 32B/thread (24KB/step, was 98KB). Per-step sync: producers
// (warp 0) DSMEM-store their 32 h values to all 8 CTAs, elected lane fences +
// issues 8 remote mbarrier arrives; everyone waits local mbar parity (acquire
// cluster). No full cluster rendezvous in the loop.
#define RB 8
#define RT 768

__device__ __forceinline__ unsigned int smem_u32(const void* p) {
    unsigned int a;
    asm("{ .reg .u64 t; cvta.to.shared.u64 t, %1; cvt.u32.u64 %0, t; }"
        : "=r"(a) : "l"(p));
    return a;
}

__device__ __forceinline__ void cluster_arrive_wait() {
    asm volatile("barrier.cluster.arrive.aligned;" ::: "memory");
    asm volatile("barrier.cluster.wait.aligned;" ::: "memory");
}

__device__ __forceinline__ void mbar_wait_cluster(unsigned int mb,
                                                  unsigned int parity) {
    asm volatile(
        "{\n\t"
        ".reg .pred P;\n\t"
        "WL%=:\n\t"
        "mbarrier.try_wait.parity.acquire.cluster.shared::cta.b64 P, [%0], %1, 0x989680;\n\t"
        "@!P bra WL%=;\n\t"
        "}"
        :: "r"(mb), "r"(parity) : "memory");
}

__global__ void __cluster_dims__(RB, 1, 1) __launch_bounds__(RT, 1)
rnn_kernel(const float* __restrict__ gi,
           const float* __restrict__ Whh,
           const float* __restrict__ bhh,
           float* __restrict__ out,
           int out_size) {
    __shared__ __align__(16) float hbuf[2][H];
    __shared__ float smg[96];
    __shared__ __align__(8) unsigned long long mbar;

    int blk = blockIdx.x;
    int tid = threadIdx.x;
    int w = tid >> 5;                 // warp 0..23
    int lane = tid & 31;

    // weights: rows lr = w*4+r (0..95), cols lane*8..lane*8+7, packed f32x2
    unsigned long long w2[4][4];
#pragma unroll
    for (int r = 0; r < 4; r++) {
        int lr = w * 4 + r;
        int rowg = (lr >> 5) * 256 + blk * 32 + (lr & 31);
        const unsigned long long* src =
            (const unsigned long long*)(Whh + (size_t)rowg * H + lane * 8);
#pragma unroll
        for (int i = 0; i < 4; i++) w2[r][i] = src[i];
    }

    for (int i = tid; i < 2 * H; i += RT) ((float*)hbuf)[i] = 0.f;

    unsigned int mb = smem_u32(&mbar);
    if (tid == 0) {
        asm volatile("mbarrier.init.shared.b64 [%0], %1;"
                     :: "r"(mb), "r"(RB) : "memory");
    }

    int j = blk * 32 + tid;           // valid for tid < 32 (warp 0 = producers)
    float ir = 0.f, iz = 0.f, inn = 0.f, bh_r = 0.f, bh_z = 0.f, bh_n = 0.f;
    unsigned int laddr0 = 0, laddr1 = 0;
    if (tid < 32) {
        ir = gi[j];
        iz = gi[256 + j];
        inn = gi[512 + j];
        bh_r = bhh[j];
        bh_z = bhh[256 + j];
        bh_n = bhh[512 + j];
        laddr0 = smem_u32(&hbuf[0][j]);
        laddr1 = smem_u32(&hbuf[1][j]);
    }
    unsigned int hb0 = smem_u32(&hbuf[0][lane * 8]);
    unsigned int hb1 = smem_u32(&hbuf[1][lane * 8]);
    __syncthreads();
    cluster_arrive_wait();   // hbufs zeroed + mbarriers initialized everywhere

    for (int t = 0; t < S; t++) {
        int p = t & 1;

        // ---- dot: 4 rows x 8 cols per thread (f32x2) ----
        unsigned int haddr = p ? hb1 : hb0;
        unsigned long long h2[4];
        asm volatile("ld.shared.v2.b64 {%0, %1}, [%4];\n\t"
                     "ld.shared.v2.b64 {%2, %3}, [%4 + 16];"
                     : "=l"(h2[0]), "=l"(h2[1]), "=l"(h2[2]), "=l"(h2[3])
                     : "r"(haddr));
        float a[4];
#pragma unroll
        for (int r = 0; r < 4; r++) {
            unsigned long long acc2 = 0ull;
#pragma unroll
            for (int i = 0; i < 4; i++) {
                asm("fma.rn.f32x2 %0, %1, %2, %0;"
                    : "+l"(acc2) : "l"(w2[r][i]), "l"(h2[i]));
            }
            float lo, hi;
            asm("mov.b64 {%0, %1}, %2;" : "=f"(lo), "=f"(hi) : "l"(acc2));
            a[r] = lo + hi;
        }
        // butterfly over 32 lanes (all 4 rows)
#pragma unroll
        for (int m = 16; m >= 1; m >>= 1) {
#pragma unroll
            for (int r = 0; r < 4; r++)
                a[r] += __shfl_xor_sync(0xffffffffu, a[r], m);
        }
        if (lane < 4) smg[w * 4 + lane] = a[lane];
        __syncthreads();

        // ---- gate math + DSMEM broadcast (warp 0 only) ----
        if (tid < 32) {
            float ghr = smg[tid] + bh_r;
            float ghz = smg[32 + tid] + bh_z;
            float ghn = smg[64 + tid] + bh_n;
            float hold = hbuf[p][j];
            float r = 1.f / (1.f + __expf(-(ir + ghr)));
            float z = 1.f / (1.f + __expf(-(iz + ghz)));
            float narg = inn + r * ghn;
            float n = 1.f - 2.f / (1.f + __expf(2.f * narg));
            float hnew = (1.f - z) * n + z * hold;

            unsigned int la = p ? laddr0 : laddr1;   // write buffer p^1
#pragma unroll
            for (int r2 = 0; r2 < RB; r2++) {
                unsigned int pa;
                asm volatile("mapa.shared::cluster.u32 %0, %1, %2;"
                             : "=r"(pa) : "r"(la), "r"(r2));
                asm volatile("st.shared::cluster.f32 [%0], %1;"
                             :: "r"(pa), "f"(hnew) : "memory");
            }
            __syncwarp();
            if (tid == 0) {
                asm volatile("fence.acq_rel.cluster;" ::: "memory");
#pragma unroll
                for (int r2 = 0; r2 < RB; r2++) {
                    unsigned int pm;
                    asm volatile("mapa.shared::cluster.u32 %0, %1, %2;"
                                 : "=r"(pm) : "r"(mb), "r"(r2));
                    asm volatile(
                        "mbarrier.arrive.release.cluster.shared::cluster.b64 _, [%0];"
                        :: "r"(pm) : "memory");
                }
            }
            // prefetch next token's gi (hidden by wait)
            int tn = (t + 1 < S) ? (t + 1) : t;
            ir = gi[(size_t)tn * G3 + j];
            iz = gi[(size_t)tn * G3 + 256 + j];
            inn = gi[(size_t)tn * G3 + 512 + j];
        }

        // ---- wait for all 8 CTAs' h-slices (acquire cluster) ----
        mbar_wait_cluster(mb, (unsigned int)(t & 1));
    }

    if (blk == 0) {
        for (int i = tid; i < out_size; i += RT)
            out[i] = hbuf[0][i & 255];
    }
}

// ---------------- host launcher ----------------
extern "C" void kernel_launch(void* const* d_in, const int* in_sizes, int n_in,
                              void* d_out, int out_size) {
    const int* tokens = (const int*)d_in[0];
    const float* emb = (const float*)d_in[1];
    const float* Wq = (const float*)d_in[2];
    const float* bq = (const float*)d_in[3];
    const float* Wk = (const float*)d_in[4];
    const float* bk = (const float*)d_in[5];
    const float* Wv = (const float*)d_in[6];
    const float* bv = (const float*)d_in[7];
    const float* Wo = (const float*)d_in[8];
    const float* bo = (const float*)d_in[9];
    const float* ln_g = (const float*)d_in[10];
    const float* ln_b = (const float*)d_in[11];
    const float* W_ih = (const float*)d_in[12];
    const float* W_hh = (const float*)d_in[13];
    const float* b_ih = (const float*)d_in[14];
    const float* b_hh = (const float*)d_in[15];
    float* out = (float*)d_out;

    float* px; cudaGetSymbolAddress((void**)&px, g_x);
    float* pq; cudaGetSymbolAddress((void**)&pq, g_q);
    float* pk; cudaGetSymbolAddress((void**)&pk, g_k);
    float* pv; cudaGetSymbolAddress((void**)&pv, g_v);
    float* po; cudaGetSymbolAddress((void**)&po, g_o);
    float* pypre; cudaGetSymbolAddress((void**)&pypre, g_ypre);
    float* py; cudaGetSymbolAddress((void**)&py, g_y);
    float* pgi; cudaGetSymbolAddress((void**)&pgi, g_gi);

    size_t attn_smem = (size_t)(3 * 64 * LDQ + 64 * LDP + 64) * sizeof(float);
    cudaFuncSetAttribute(attn_kernel, cudaFuncAttributeMaxDynamicSharedMemorySize,
                         (int)attn_smem);

    embed_kernel<<<S, 64>>>(tokens, emb);

    dim3 gqkv(4, 64, NH);
    gemm_k<0><<<gqkv, 256>>>(px, Wq, bq, nullptr, pq);
    gemm_k<0><<<gqkv, 256>>>(px, Wk, bk, nullptr, pk);
    gemm_k<0><<<gqkv, 256>>>(px, Wv, bv, nullptr, pv);

    dim3 gatt(S / 64, NH);
    attn_kernel<<<gatt, 256, attn_smem>>>(pq, pk, pv, po);

    dim3 gop(4, 64, 1);
    gemm_k<1><<<gop, 256>>>(po, Wo, bo, px, pypre);

    ln_kernel<<<S / 8, 256>>>(pypre, ln_g, ln_b, py);

    dim3 ggi(12, 64, 1);
    gemm_k<2><<<ggi, 256>>>(py, W_ih, b_ih, nullptr, pgi);

    rnn_kernel<<<RB, RT>>>(pgi, W_hh, b_hh, out, out_size);
}

// round 6
// speedup vs baseline: 3.3713x; 1.8597x over previous
#include <cuda_runtime.h>
#include <cuda_bf16.h>
#include <mma.h>
#include <math.h>
#include <stddef.h>

using namespace nvcuda;

#define S 4096
#define H 256
#define NH 6
#define G3 768
#define EPS 1e-5f

// ---------------- scratch (static device arrays; no allocation) ----------------
__device__ float g_x[S * H];            // embedded tokens
__device__ float g_q[NH * S * H];
__device__ float g_k[NH * S * H];
__device__ float g_v[NH * S * H];
__device__ float g_o[NH * S * H];       // attention output per head
__device__ float g_ypre[S * H];         // x + attn_proj (pre-LN)
__device__ float g_y[S * H];            // post-LN
__device__ float g_gi[S * G3];          // y @ W_ih^T + b_ih

// ---------------- embedding gather ----------------
__global__ void embed_kernel(const int* __restrict__ tokens,
                             const float* __restrict__ emb) {
    int s = blockIdx.x;
    int tok = tokens[s];
    const float4* src = (const float4*)(emb + (size_t)tok * H);
    float4* dst = (float4*)(g_x + (size_t)s * H);
    dst[threadIdx.x] = src[threadIdx.x];   // 64 threads * 4
}

// ---------------- generic tiled GEMM (64x64 tile, 256 threads, 4x4 micro) ----
template <int MODE>
__global__ __launch_bounds__(256) void gemm_k(const float* __restrict__ A,
                                              const float* __restrict__ B,
                                              const float* __restrict__ bias,
                                              const float* __restrict__ resid,
                                              float* __restrict__ C) {
    const int KTOT = (MODE == 1) ? 1536 : 256;
    const int NTOT = (MODE == 2) ? 768 : 256;
    __shared__ float As[64][65];
    __shared__ float Bs[64][65];
    int tid = threadIdx.x;
    int m0 = blockIdx.y * 64, n0 = blockIdx.x * 64;
    int z = blockIdx.z;
    const float* Bb = (MODE == 0) ? (B + (size_t)z * 256 * 256) : B;

    float acc[4][4];
#pragma unroll
    for (int i = 0; i < 4; i++)
#pragma unroll
        for (int j = 0; j < 4; j++) acc[i][j] = 0.f;

    int ty = tid >> 4, tx = tid & 15;

    for (int k0 = 0; k0 < KTOT; k0 += 64) {
        const float* Asrc;
        if (MODE == 1) {
            int head = k0 >> 8;
            int d0 = k0 & 255;
            Asrc = A + (size_t)head * (S * 256) + d0;
        } else {
            Asrc = A + k0;
        }
#pragma unroll
        for (int i = 0; i < 16; i++) {
            int lin = i * 256 + tid;
            int m = lin >> 6, kk = lin & 63;
            As[m][kk] = Asrc[(size_t)(m0 + m) * 256 + kk];
        }
        if (MODE == 2) {
#pragma unroll
            for (int i = 0; i < 16; i++) {
                int lin = i * 256 + tid;
                int n = lin >> 6, kk = lin & 63;
                Bs[kk][n] = Bb[(size_t)(n0 + n) * 256 + (k0 + kk)];
            }
        } else {
#pragma unroll
            for (int i = 0; i < 16; i++) {
                int lin = i * 256 + tid;
                int kk = lin >> 6, n = lin & 63;
                Bs[kk][n] = Bb[(size_t)(k0 + kk) * NTOT + n0 + n];
            }
        }
        __syncthreads();
#pragma unroll 8
        for (int kk = 0; kk < 64; kk++) {
            float a[4], b[4];
#pragma unroll
            for (int i = 0; i < 4; i++) a[i] = As[ty * 4 + i][kk];
#pragma unroll
            for (int j = 0; j < 4; j++) b[j] = Bs[kk][tx * 4 + j];
#pragma unroll
            for (int i = 0; i < 4; i++)
#pragma unroll
                for (int j = 0; j < 4; j++) acc[i][j] += a[i] * b[j];
        }
        __syncthreads();
    }

#pragma unroll
    for (int i = 0; i < 4; i++) {
        int m = m0 + ty * 4 + i;
#pragma unroll
        for (int j = 0; j < 4; j++) {
            int n = n0 + tx * 4 + j;
            float v = acc[i][j];
            if (MODE == 0) {
                v += bias[z * 256 + n];
                C[(size_t)z * S * 256 + (size_t)m * 256 + n] = v;
            } else if (MODE == 1) {
                v += bias[n] + resid[(size_t)m * 256 + n];
                C[(size_t)m * 256 + n] = v;
            } else {
                v += bias[n];
                C[(size_t)m * 768 + n] = v;
            }
        }
    }
}

// ---------------- WMMA tf32 streaming attention ------------------------------
#define LDQ 268
#define LDP 76
__global__ __launch_bounds__(256) void attn_kernel(const float* __restrict__ Q,
                                                   const float* __restrict__ K,
                                                   const float* __restrict__ V,
                                                   float* __restrict__ O) {
    extern __shared__ float sm[];
    float* Qs = sm;
    float* Ks = Qs + 64 * LDQ;
    float* Vs = Ks + 64 * LDQ;
    float* Ps = Vs + 64 * LDQ;
    float* Ls = Ps + 64 * LDP;

    int h = blockIdx.y;
    int q0 = blockIdx.x * 64;
    int tid = threadIdx.x;
    int warp = tid >> 5;
    int wm = warp & 3;
    int wn = warp >> 2;

    const float* Qg = Q + ((size_t)h * S + q0) * H;
    const float* Kg = K + (size_t)h * S * H;
    const float* Vg = V + (size_t)h * S * H;

    for (int i = tid; i < 64 * 64; i += 256) {
        int q = i >> 6, d4 = i & 63;
        ((float4*)(Qs + q * LDQ))[d4] = ((const float4*)(Qg + (size_t)q * H))[d4];
    }

    wmma::fragment<wmma::accumulator, 16, 16, 8, float> o_frag[8];
#pragma unroll
    for (int f = 0; f < 8; f++) wmma::fill_fragment(o_frag[f], 0.0f);

    int lrow = tid >> 2;
    int lcol0 = (tid & 3) * 16;
    float l_part = 0.f;
    const float inv_scale = 0.0625f;

    for (int kt = 0; kt < S / 64; kt++) {
        __syncthreads();
        for (int i = tid; i < 64 * 64; i += 256) {
            int r = i >> 6, d4 = i & 63;
            ((float4*)(Ks + r * LDQ))[d4] =
                ((const float4*)(Kg + (size_t)(kt * 64 + r) * H))[d4];
            ((float4*)(Vs + r * LDQ))[d4] =
                ((const float4*)(Vg + (size_t)(kt * 64 + r) * H))[d4];
        }
        __syncthreads();

        {
            wmma::fragment<wmma::matrix_a, 16, 16, 8, wmma::precision::tf32,
                           wmma::row_major> af;
            wmma::fragment<wmma::matrix_b, 16, 16, 8, wmma::precision::tf32,
                           wmma::col_major> bf;
            wmma::fragment<wmma::accumulator, 16, 16, 8, float> c[2];
            wmma::fill_fragment(c[0], 0.0f);
            wmma::fill_fragment(c[1], 0.0f);
#pragma unroll 4
            for (int k = 0; k < 32; k++) {
                wmma::load_matrix_sync(af, Qs + (wm * 16) * LDQ + k * 8, LDQ);
#pragma unroll
                for (int e = 0; e < af.num_elements; e++)
                    af.x[e] = wmma::__float_to_tf32(af.x[e]);
#pragma unroll
                for (int nf = 0; nf < 2; nf++) {
                    wmma::load_matrix_sync(
                        bf, Ks + (wn * 32 + nf * 16) * LDQ + k * 8, LDQ);
#pragma unroll
                    for (int e = 0; e < bf.num_elements; e++)
                        bf.x[e] = wmma::__float_to_tf32(bf.x[e]);
                    wmma::mma_sync(c[nf], af, bf, c[nf]);
                }
            }
#pragma unroll
            for (int nf = 0; nf < 2; nf++)
                wmma::store_matrix_sync(
                    Ps + (wm * 16) * LDP + wn * 32 + nf * 16, c[nf], LDP,
                    wmma::mem_row_major);
        }
        __syncthreads();

        {
            float* pr = Ps + lrow * LDP + lcol0;
            float ssum = 0.f;
#pragma unroll
            for (int j = 0; j < 16; j++) {
                float e = __expf(pr[j] * inv_scale);
                pr[j] = e;
                ssum += e;
            }
            l_part += ssum;
        }
        __syncthreads();

        {
            wmma::fragment<wmma::matrix_a, 16, 16, 8, wmma::precision::tf32,
                           wmma::row_major> pa;
            wmma::fragment<wmma::matrix_b, 16, 16, 8, wmma::precision::tf32,
                           wmma::row_major> vb;
#pragma unroll
            for (int k = 0; k < 8; k++) {
                wmma::load_matrix_sync(pa, Ps + (wm * 16) * LDP + k * 8, LDP);
#pragma unroll
                for (int e = 0; e < pa.num_elements; e++)
                    pa.x[e] = wmma::__float_to_tf32(pa.x[e]);
#pragma unroll
                for (int nf = 0; nf < 8; nf++) {
                    wmma::load_matrix_sync(
                        vb, Vs + (k * 8) * LDQ + wn * 128 + nf * 16, LDQ);
#pragma unroll
                    for (int e = 0; e < vb.num_elements; e++)
                        vb.x[e] = wmma::__float_to_tf32(vb.x[e]);
                    wmma::mma_sync(o_frag[nf], pa, vb, o_frag[nf]);
                }
            }
        }
    }

    l_part += __shfl_xor_sync(0xffffffffu, l_part, 1);
    l_part += __shfl_xor_sync(0xffffffffu, l_part, 2);
    if ((tid & 3) == 0) Ls[lrow] = l_part;

#pragma unroll
    for (int nf = 0; nf < 8; nf++)
        wmma::store_matrix_sync(Qs + (wm * 16) * LDQ + wn * 128 + nf * 16,
                                o_frag[nf], LDQ, wmma::mem_row_major);
    __syncthreads();

    float* Og = O + ((size_t)h * S + q0) * H;
    for (int i = tid; i < 64 * 64; i += 256) {
        int q = i >> 6, d4 = i & 63;
        float inv_l = __frcp_rn(Ls[q]);
        float4 v = ((float4*)(Qs + q * LDQ))[d4];
        v.x *= inv_l; v.y *= inv_l; v.z *= inv_l; v.w *= inv_l;
        ((float4*)(Og + (size_t)q * H))[d4] = v;
    }
}

// ---------------- LayerNorm (one warp per row) ----------------
__global__ __launch_bounds__(256) void ln_kernel(const float* __restrict__ yin,
                                                 const float* __restrict__ g,
                                                 const float* __restrict__ b,
                                                 float* __restrict__ yout) {
    int row = blockIdx.x * 8 + (threadIdx.x >> 5);
    int lane = threadIdx.x & 31;
    const float* yr = yin + (size_t)row * H;
    float v[8], s = 0.f, sq = 0.f;
#pragma unroll
    for (int i = 0; i < 8; i++) {
        v[i] = yr[lane + i * 32];
        s += v[i];
        sq += v[i] * v[i];
    }
#pragma unroll
    for (int m = 16; m >= 1; m >>= 1) {
        s += __shfl_xor_sync(0xffffffffu, s, m);
        sq += __shfl_xor_sync(0xffffffffu, sq, m);
    }
    float mu = s * (1.f / H);
    float var = sq * (1.f / H) - mu * mu;
    float rstd = rsqrtf(var + EPS);
    float* yo = yout + (size_t)row * H;
#pragma unroll
    for (int i = 0; i < 8; i++) {
        int c = lane + i * 32;
        yo[c] = (v[i] - mu) * rstd * g[c] + b[c];
    }
}

// ---------------- GRU recurrence: 8-CTA cluster, bulk-copy exchange ----------
// Per step: all warps dot W_hh-slice (regs) with h (own smem). Warp 0 computes
// the 32 new h-dims, writes them to local hbuf + a parity-staged 128B buffer,
// then ONE lane issues 7 cp.async.bulk S2S copies (data + complete_tx fused at
// each remote mbar). Only tid0 waits the mbar (expect_tx 7*128B), then a
// bar.sync releases the CTA. No fences, no remote atomics, no 24-warp polling.
#define RB 8
#define RT 768

__device__ __forceinline__ unsigned int smem_u32(const void* p) {
    unsigned int a;
    asm("{ .reg .u64 t; cvta.to.shared.u64 t, %1; cvt.u32.u64 %0, t; }"
        : "=r"(a) : "l"(p));
    return a;
}

__device__ __forceinline__ void cluster_arrive_wait() {
    asm volatile("barrier.cluster.arrive.aligned;" ::: "memory");
    asm volatile("barrier.cluster.wait.aligned;" ::: "memory");
}

__device__ __forceinline__ void mbar_wait_parity(unsigned int mb,
                                                 unsigned int parity) {
    asm volatile(
        "{\n\t"
        ".reg .pred P;\n\t"
        "WL%=:\n\t"
        "mbarrier.try_wait.parity.acquire.cta.shared::cta.b64 P, [%0], %1, 0x989680;\n\t"
        "@!P bra WL%=;\n\t"
        "}"
        :: "r"(mb), "r"(parity) : "memory");
}

__global__ void __cluster_dims__(RB, 1, 1) __launch_bounds__(RT, 1)
rnn_kernel(const float* __restrict__ gi,
           const float* __restrict__ Whh,
           const float* __restrict__ bhh,
           float* __restrict__ out,
           int out_size) {
    __shared__ __align__(16) float hbuf[2][H];
    __shared__ __align__(16) float hstage[2][32];   // parity-staged bulk source
    __shared__ float smg[96];
    __shared__ __align__(8) unsigned long long mbar;

    int blk = blockIdx.x;
    int tid = threadIdx.x;
    int w = tid >> 5;                 // warp 0..23
    int lane = tid & 31;

    // weights: rows lr = w*4+r (0..95), cols lane*8..lane*8+7, packed f32x2
    unsigned long long w2[4][4];
#pragma unroll
    for (int r = 0; r < 4; r++) {
        int lr = w * 4 + r;
        int rowg = (lr >> 5) * 256 + blk * 32 + (lr & 31);
        const unsigned long long* src =
            (const unsigned long long*)(Whh + (size_t)rowg * H + lane * 8);
#pragma unroll
        for (int i = 0; i < 4; i++) w2[r][i] = src[i];
    }

    for (int i = tid; i < 2 * H; i += RT) ((float*)hbuf)[i] = 0.f;

    unsigned int mb = smem_u32(&mbar);
    if (tid == 0) {
        asm volatile("mbarrier.init.shared.b64 [%0], %1;"
                     :: "r"(mb), "r"(1) : "memory");
    }

    int j = blk * 32 + tid;           // valid for tid < 32 (warp 0 = producers)
    float ir = 0.f, iz = 0.f, inn = 0.f, bh_r = 0.f, bh_z = 0.f, bh_n = 0.f;
    if (tid < 32) {
        ir = gi[j];
        iz = gi[256 + j];
        inn = gi[512 + j];
        bh_r = bhh[j];
        bh_z = bhh[256 + j];
        bh_n = bhh[512 + j];
    }
    unsigned int hb0 = smem_u32(&hbuf[0][lane * 8]);
    unsigned int hb1 = smem_u32(&hbuf[1][lane * 8]);
    unsigned int dst0 = smem_u32(&hbuf[0][blk * 32]);   // our slice in hbuf[0]
    unsigned int dst1 = smem_u32(&hbuf[1][blk * 32]);
    unsigned int st0 = smem_u32(&hstage[0][0]);
    unsigned int st1 = smem_u32(&hstage[1][0]);
    __syncthreads();
    cluster_arrive_wait();   // hbufs zeroed + mbarriers initialized everywhere

    for (int t = 0; t < S; t++) {
        int p = t & 1;

        if (tid == 0) {
            // expect this phase's incoming bytes (7 remote CTAs x 128B)
            asm volatile("mbarrier.arrive.expect_tx.shared.b64 _, [%0], %1;"
                         :: "r"(mb), "r"(7 * 128) : "memory");
        }

        // ---- dot: 4 rows x 8 cols per thread (f32x2) ----
        unsigned int haddr = p ? hb1 : hb0;
        unsigned long long h2[4];
        asm volatile("ld.shared.v2.b64 {%0, %1}, [%4];\n\t"
                     "ld.shared.v2.b64 {%2, %3}, [%4 + 16];"
                     : "=l"(h2[0]), "=l"(h2[1]), "=l"(h2[2]), "=l"(h2[3])
                     : "r"(haddr));
        float a[4];
#pragma unroll
        for (int r = 0; r < 4; r++) {
            unsigned long long acc2 = 0ull;
#pragma unroll
            for (int i = 0; i < 4; i++) {
                asm("fma.rn.f32x2 %0, %1, %2, %0;"
                    : "+l"(acc2) : "l"(w2[r][i]), "l"(h2[i]));
            }
            float lo, hi;
            asm("mov.b64 {%0, %1}, %2;" : "=f"(lo), "=f"(hi) : "l"(acc2));
            a[r] = lo + hi;
        }
#pragma unroll
        for (int m = 16; m >= 1; m >>= 1) {
#pragma unroll
            for (int r = 0; r < 4; r++)
                a[r] += __shfl_xor_sync(0xffffffffu, a[r], m);
        }
        if (lane < 4) smg[w * 4 + lane] = a[lane];
        __syncthreads();

        // ---- gate math + exchange (warp 0 only) ----
        if (tid < 32) {
            float ghr = smg[tid] + bh_r;
            float ghz = smg[32 + tid] + bh_z;
            float ghn = smg[64 + tid] + bh_n;
            float hold = hbuf[p][j];
            float r = 1.f / (1.f + __expf(-(ir + ghr)));
            float z = 1.f / (1.f + __expf(-(iz + ghz)));
            float narg = inn + r * ghn;
            float n = 1.f - 2.f / (1.f + __expf(2.f * narg));
            float hnew = (1.f - z) * n + z * hold;

            // self-delivery (plain smem store) + bulk-copy source staging
            hbuf[p ^ 1][j] = hnew;
            hstage[p ^ 1][tid] = hnew;
            __syncwarp();
            if (tid == 0) {
                asm volatile("fence.proxy.async.shared::cta;" ::: "memory");
                unsigned int src = p ? st0 : st1;          // hstage[p^1]
                unsigned int dstl = p ? dst0 : dst1;       // hbuf[p^1] slice
#pragma unroll
                for (int r2 = 0; r2 < RB; r2++) {
                    if (r2 == blk) continue;
                    unsigned int pd, pm;
                    asm volatile("mapa.shared::cluster.u32 %0, %1, %2;"
                                 : "=r"(pd) : "r"(dstl), "r"(r2));
                    asm volatile("mapa.shared::cluster.u32 %0, %1, %2;"
                                 : "=r"(pm) : "r"(mb), "r"(r2));
                    asm volatile(
                        "cp.async.bulk.shared::cluster.shared::cta.mbarrier::complete_tx::bytes "
                        "[%0], [%1], 128, [%2];"
                        :: "r"(pd), "r"(src), "r"(pm) : "memory");
                }
            }
            // prefetch next token's gi (hidden by wait)
            int tn = (t + 1 < S) ? (t + 1) : t;
            ir = gi[(size_t)tn * G3 + j];
            iz = gi[(size_t)tn * G3 + 256 + j];
            inn = gi[(size_t)tn * G3 + 512 + j];
        }

        // ---- single waiter, then CTA-wide release ----
        if (tid == 0) mbar_wait_parity(mb, (unsigned int)(t & 1));
        __syncthreads();
    }

    if (blk == 0) {
        for (int i = tid; i < out_size; i += RT)
            out[i] = hbuf[0][i & 255];
    }
}

// ---------------- host launcher ----------------
extern "C" void kernel_launch(void* const* d_in, const int* in_sizes, int n_in,
                              void* d_out, int out_size) {
    const int* tokens = (const int*)d_in[0];
    const float* emb = (const float*)d_in[1];
    const float* Wq = (const float*)d_in[2];
    const float* bq = (const float*)d_in[3];
    const float* Wk = (const float*)d_in[4];
    const float* bk = (const float*)d_in[5];
    const float* Wv = (const float*)d_in[6];
    const float* bv = (const float*)d_in[7];
    const float* Wo = (const float*)d_in[8];
    const float* bo = (const float*)d_in[9];
    const float* ln_g = (const float*)d_in[10];
    const float* ln_b = (const float*)d_in[11];
    const float* W_ih = (const float*)d_in[12];
    const float* W_hh = (const float*)d_in[13];
    const float* b_ih = (const float*)d_in[14];
    const float* b_hh = (const float*)d_in[15];
    float* out = (float*)d_out;

    float* px; cudaGetSymbolAddress((void**)&px, g_x);
    float* pq; cudaGetSymbolAddress((void**)&pq, g_q);
    float* pk; cudaGetSymbolAddress((void**)&pk, g_k);
    float* pv; cudaGetSymbolAddress((void**)&pv, g_v);
    float* po; cudaGetSymbolAddress((void**)&po, g_o);
    float* pypre; cudaGetSymbolAddress((void**)&pypre, g_ypre);
    float* py; cudaGetSymbolAddress((void**)&py, g_y);
    float* pgi; cudaGetSymbolAddress((void**)&pgi, g_gi);

    size_t attn_smem = (size_t)(3 * 64 * LDQ + 64 * LDP + 64) * sizeof(float);
    cudaFuncSetAttribute(attn_kernel, cudaFuncAttributeMaxDynamicSharedMemorySize,
                         (int)attn_smem);

    embed_kernel<<<S, 64>>>(tokens, emb);

    dim3 gqkv(4, 64, NH);
    gemm_k<0><<<gqkv, 256>>>(px, Wq, bq, nullptr, pq);
    gemm_k<0><<<gqkv, 256>>>(px, Wk, bk, nullptr, pk);
    gemm_k<0><<<gqkv, 256>>>(px, Wv, bv, nullptr, pv);

    dim3 gatt(S / 64, NH);
    attn_kernel<<<gatt, 256, attn_smem>>>(pq, pk, pv, po);

    dim3 gop(4, 64, 1);
    gemm_k<1><<<gop, 256>>>(po, Wo, bo, px, pypre);

    ln_kernel<<<S / 8, 256>>>(pypre, ln_g, ln_b, py);

    dim3 ggi(12, 64, 1);
    gemm_k<2><<<ggi, 256>>>(py, W_ih, b_ih, nullptr, pgi);

    rnn_kernel<<<RB, RT>>>(pgi, W_hh, b_hh, out, out_size);
}

// round 7
// speedup vs baseline: 3.4117x; 1.0120x over previous
#include <cuda_runtime.h>
#include <cuda_bf16.h>
#include <mma.h>
#include <math.h>
#include <stddef.h>

using namespace nvcuda;

#define S 4096
#define H 256
#define NH 6
#define G3 768
#define EPS 1e-5f

// ---------------- scratch (static device arrays; no allocation) ----------------
__device__ float g_x[S * H];            // embedded tokens
__device__ float g_q[NH * S * H];
__device__ float g_k[NH * S * H];
__device__ float g_v[NH * S * H];
__device__ float g_o[NH * S * H];       // attention output per head
__device__ float g_ypre[S * H];         // x + attn_proj (pre-LN)
__device__ float g_y[S * H];            // post-LN
__device__ float g_gi[S * G3];          // y @ W_ih^T + b_ih

// ---------------- embedding gather ----------------
__global__ void embed_kernel(const int* __restrict__ tokens,
                             const float* __restrict__ emb) {
    int s = blockIdx.x;
    int tok = tokens[s];
    const float4* src = (const float4*)(emb + (size_t)tok * H);
    float4* dst = (float4*)(g_x + (size_t)s * H);
    dst[threadIdx.x] = src[threadIdx.x];   // 64 threads * 4
}

// ---------------- generic tiled GEMM (64x64 tile, 256 threads, 4x4 micro) ----
template <int MODE>
__global__ __launch_bounds__(256) void gemm_k(const float* __restrict__ A,
                                              const float* __restrict__ B,
                                              const float* __restrict__ bias,
                                              const float* __restrict__ resid,
                                              float* __restrict__ C) {
    const int KTOT = (MODE == 1) ? 1536 : 256;
    const int NTOT = (MODE == 2) ? 768 : 256;
    __shared__ float As[64][65];
    __shared__ float Bs[64][65];
    int tid = threadIdx.x;
    int m0 = blockIdx.y * 64, n0 = blockIdx.x * 64;
    int z = blockIdx.z;
    const float* Bb = (MODE == 0) ? (B + (size_t)z * 256 * 256) : B;

    float acc[4][4];
#pragma unroll
    for (int i = 0; i < 4; i++)
#pragma unroll
        for (int j = 0; j < 4; j++) acc[i][j] = 0.f;

    int ty = tid >> 4, tx = tid & 15;

    for (int k0 = 0; k0 < KTOT; k0 += 64) {
        const float* Asrc;
        if (MODE == 1) {
            int head = k0 >> 8;
            int d0 = k0 & 255;
            Asrc = A + (size_t)head * (S * 256) + d0;
        } else {
            Asrc = A + k0;
        }
#pragma unroll
        for (int i = 0; i < 16; i++) {
            int lin = i * 256 + tid;
            int m = lin >> 6, kk = lin & 63;
            As[m][kk] = Asrc[(size_t)(m0 + m) * 256 + kk];
        }
        if (MODE == 2) {
#pragma unroll
            for (int i = 0; i < 16; i++) {
                int lin = i * 256 + tid;
                int n = lin >> 6, kk = lin & 63;
                Bs[kk][n] = Bb[(size_t)(n0 + n) * 256 + (k0 + kk)];
            }
        } else {
#pragma unroll
            for (int i = 0; i < 16; i++) {
                int lin = i * 256 + tid;
                int kk = lin >> 6, n = lin & 63;
                Bs[kk][n] = Bb[(size_t)(k0 + kk) * NTOT + n0 + n];
            }
        }
        __syncthreads();
#pragma unroll 8
        for (int kk = 0; kk < 64; kk++) {
            float a[4], b[4];
#pragma unroll
            for (int i = 0; i < 4; i++) a[i] = As[ty * 4 + i][kk];
#pragma unroll
            for (int j = 0; j < 4; j++) b[j] = Bs[kk][tx * 4 + j];
#pragma unroll
            for (int i = 0; i < 4; i++)
#pragma unroll
                for (int j = 0; j < 4; j++) acc[i][j] += a[i] * b[j];
        }
        __syncthreads();
    }

#pragma unroll
    for (int i = 0; i < 4; i++) {
        int m = m0 + ty * 4 + i;
#pragma unroll
        for (int j = 0; j < 4; j++) {
            int n = n0 + tx * 4 + j;
            float v = acc[i][j];
            if (MODE == 0) {
                v += bias[z * 256 + n];
                C[(size_t)z * S * 256 + (size_t)m * 256 + n] = v;
            } else if (MODE == 1) {
                v += bias[n] + resid[(size_t)m * 256 + n];
                C[(size_t)m * 256 + n] = v;
            } else {
                v += bias[n];
                C[(size_t)m * 768 + n] = v;
            }
        }
    }
}

// ---------------- WMMA tf32 streaming attention ------------------------------
#define LDQ 268
#define LDP 76
__global__ __launch_bounds__(256) void attn_kernel(const float* __restrict__ Q,
                                                   const float* __restrict__ K,
                                                   const float* __restrict__ V,
                                                   float* __restrict__ O) {
    extern __shared__ float sm[];
    float* Qs = sm;
    float* Ks = Qs + 64 * LDQ;
    float* Vs = Ks + 64 * LDQ;
    float* Ps = Vs + 64 * LDQ;
    float* Ls = Ps + 64 * LDP;

    int h = blockIdx.y;
    int q0 = blockIdx.x * 64;
    int tid = threadIdx.x;
    int warp = tid >> 5;
    int wm = warp & 3;
    int wn = warp >> 2;

    const float* Qg = Q + ((size_t)h * S + q0) * H;
    const float* Kg = K + (size_t)h * S * H;
    const float* Vg = V + (size_t)h * S * H;

    for (int i = tid; i < 64 * 64; i += 256) {
        int q = i >> 6, d4 = i & 63;
        ((float4*)(Qs + q * LDQ))[d4] = ((const float4*)(Qg + (size_t)q * H))[d4];
    }

    wmma::fragment<wmma::accumulator, 16, 16, 8, float> o_frag[8];
#pragma unroll
    for (int f = 0; f < 8; f++) wmma::fill_fragment(o_frag[f], 0.0f);

    int lrow = tid >> 2;
    int lcol0 = (tid & 3) * 16;
    float l_part = 0.f;
    const float inv_scale = 0.0625f;

    for (int kt = 0; kt < S / 64; kt++) {
        __syncthreads();
        for (int i = tid; i < 64 * 64; i += 256) {
            int r = i >> 6, d4 = i & 63;
            ((float4*)(Ks + r * LDQ))[d4] =
                ((const float4*)(Kg + (size_t)(kt * 64 + r) * H))[d4];
            ((float4*)(Vs + r * LDQ))[d4] =
                ((const float4*)(Vg + (size_t)(kt * 64 + r) * H))[d4];
        }
        __syncthreads();

        {
            wmma::fragment<wmma::matrix_a, 16, 16, 8, wmma::precision::tf32,
                           wmma::row_major> af;
            wmma::fragment<wmma::matrix_b, 16, 16, 8, wmma::precision::tf32,
                           wmma::col_major> bf;
            wmma::fragment<wmma::accumulator, 16, 16, 8, float> c[2];
            wmma::fill_fragment(c[0], 0.0f);
            wmma::fill_fragment(c[1], 0.0f);
#pragma unroll 4
            for (int k = 0; k < 32; k++) {
                wmma::load_matrix_sync(af, Qs + (wm * 16) * LDQ + k * 8, LDQ);
#pragma unroll
                for (int e = 0; e < af.num_elements; e++)
                    af.x[e] = wmma::__float_to_tf32(af.x[e]);
#pragma unroll
                for (int nf = 0; nf < 2; nf++) {
                    wmma::load_matrix_sync(
                        bf, Ks + (wn * 32 + nf * 16) * LDQ + k * 8, LDQ);
#pragma unroll
                    for (int e = 0; e < bf.num_elements; e++)
                        bf.x[e] = wmma::__float_to_tf32(bf.x[e]);
                    wmma::mma_sync(c[nf], af, bf, c[nf]);
                }
            }
#pragma unroll
            for (int nf = 0; nf < 2; nf++)
                wmma::store_matrix_sync(
                    Ps + (wm * 16) * LDP + wn * 32 + nf * 16, c[nf], LDP,
                    wmma::mem_row_major);
        }
        __syncthreads();

        {
            float* pr = Ps + lrow * LDP + lcol0;
            float ssum = 0.f;
#pragma unroll
            for (int j = 0; j < 16; j++) {
                float e = __expf(pr[j] * inv_scale);
                pr[j] = e;
                ssum += e;
            }
            l_part += ssum;
        }
        __syncthreads();

        {
            wmma::fragment<wmma::matrix_a, 16, 16, 8, wmma::precision::tf32,
                           wmma::row_major> pa;
            wmma::fragment<wmma::matrix_b, 16, 16, 8, wmma::precision::tf32,
                           wmma::row_major> vb;
#pragma unroll
            for (int k = 0; k < 8; k++) {
                wmma::load_matrix_sync(pa, Ps + (wm * 16) * LDP + k * 8, LDP);
#pragma unroll
                for (int e = 0; e < pa.num_elements; e++)
                    pa.x[e] = wmma::__float_to_tf32(pa.x[e]);
#pragma unroll
                for (int nf = 0; nf < 8; nf++) {
                    wmma::load_matrix_sync(
                        vb, Vs + (k * 8) * LDQ + wn * 128 + nf * 16, LDQ);
#pragma unroll
                    for (int e = 0; e < vb.num_elements; e++)
                        vb.x[e] = wmma::__float_to_tf32(vb.x[e]);
                    wmma::mma_sync(o_frag[nf], pa, vb, o_frag[nf]);
                }
            }
        }
    }

    l_part += __shfl_xor_sync(0xffffffffu, l_part, 1);
    l_part += __shfl_xor_sync(0xffffffffu, l_part, 2);
    if ((tid & 3) == 0) Ls[lrow] = l_part;

#pragma unroll
    for (int nf = 0; nf < 8; nf++)
        wmma::store_matrix_sync(Qs + (wm * 16) * LDQ + wn * 128 + nf * 16,
                                o_frag[nf], LDQ, wmma::mem_row_major);
    __syncthreads();

    float* Og = O + ((size_t)h * S + q0) * H;
    for (int i = tid; i < 64 * 64; i += 256) {
        int q = i >> 6, d4 = i & 63;
        float inv_l = __frcp_rn(Ls[q]);
        float4 v = ((float4*)(Qs + q * LDQ))[d4];
        v.x *= inv_l; v.y *= inv_l; v.z *= inv_l; v.w *= inv_l;
        ((float4*)(Og + (size_t)q * H))[d4] = v;
    }
}

// ---------------- LayerNorm (one warp per row) ----------------
__global__ __launch_bounds__(256) void ln_kernel(const float* __restrict__ yin,
                                                 const float* __restrict__ g,
                                                 const float* __restrict__ b,
                                                 float* __restrict__ yout) {
    int row = blockIdx.x * 8 + (threadIdx.x >> 5);
    int lane = threadIdx.x & 31;
    const float* yr = yin + (size_t)row * H;
    float v[8], s = 0.f, sq = 0.f;
#pragma unroll
    for (int i = 0; i < 8; i++) {
        v[i] = yr[lane + i * 32];
        s += v[i];
        sq += v[i] * v[i];
    }
#pragma unroll
    for (int m = 16; m >= 1; m >>= 1) {
        s += __shfl_xor_sync(0xffffffffu, s, m);
        sq += __shfl_xor_sync(0xffffffffu, sq, m);
    }
    float mu = s * (1.f / H);
    float var = sq * (1.f / H) - mu * mu;
    float rstd = rsqrtf(var + EPS);
    float* yo = yout + (size_t)row * H;
#pragma unroll
    for (int i = 0; i < 8; i++) {
        int c = lane + i * 32;
        yo[c] = (v[i] - mu) * rstd * g[c] + b[c];
    }
}

// ---------------- GRU recurrence: 8-CTA cluster, bulk-copy exchange ----------
// 512 threads / 16 warps per CTA. Warp w owns h-dims {w*2, w*2+1}: all 6 gate
// rows (r,z,n x 2) live in that warp's registers (24 f32x2 each thread, cols
// lane*8..+7). After the dot + 5-level butterfly, EVERY lane holds all 6 row
// totals, so lanes 0..1 do the complete gate math for their dim in-warp — no
// smem staging of partials, no dedicated producer warp, one barrier before the
// bulk-copy exchange. Exchange identical to R6: tid0 fence.proxy + 7
// cp.async.bulk S2S (data + complete_tx fused), single waiter, bar release.
#define RB 8
#define RT 512

__device__ __forceinline__ unsigned int smem_u32(const void* p) {
    unsigned int a;
    asm("{ .reg .u64 t; cvta.to.shared.u64 t, %1; cvt.u32.u64 %0, t; }"
        : "=r"(a) : "l"(p));
    return a;
}

__device__ __forceinline__ void cluster_arrive_wait() {
    asm volatile("barrier.cluster.arrive.aligned;" ::: "memory");
    asm volatile("barrier.cluster.wait.aligned;" ::: "memory");
}

__device__ __forceinline__ void mbar_wait_parity(unsigned int mb,
                                                 unsigned int parity) {
    asm volatile(
        "{\n\t"
        ".reg .pred P;\n\t"
        "WL%=:\n\t"
        "mbarrier.try_wait.parity.acquire.cta.shared::cta.b64 P, [%0], %1, 0x989680;\n\t"
        "@!P bra WL%=;\n\t"
        "}"
        :: "r"(mb), "r"(parity) : "memory");
}

__global__ void __cluster_dims__(RB, 1, 1) __launch_bounds__(RT, 1)
rnn_kernel(const float* __restrict__ gi,
           const float* __restrict__ Whh,
           const float* __restrict__ bhh,
           float* __restrict__ out,
           int out_size) {
    __shared__ __align__(16) float hbuf[2][H];
    __shared__ __align__(16) float hstage[2][32];   // parity-staged bulk source
    __shared__ __align__(8) unsigned long long mbar;

    int blk = blockIdx.x;
    int tid = threadIdx.x;
    int w = tid >> 5;                 // warp 0..15
    int lane = tid & 31;

    // weights: rows (g, dd) -> global row g*256 + blk*32 + w*2 + dd,
    // cols lane*8..lane*8+7, packed f32x2. 6 rows x 4 ull = 24 ull.
    unsigned long long w2[6][4];
#pragma unroll
    for (int g = 0; g < 3; g++) {
#pragma unroll
        for (int dd = 0; dd < 2; dd++) {
            int rowg = g * 256 + blk * 32 + w * 2 + dd;
            const unsigned long long* src =
                (const unsigned long long*)(Whh + (size_t)rowg * H + lane * 8);
#pragma unroll
            for (int i = 0; i < 4; i++) w2[g * 2 + dd][i] = src[i];
        }
    }

    for (int i = tid; i < 2 * H; i += RT) ((float*)hbuf)[i] = 0.f;

    unsigned int mb = smem_u32(&mbar);
    if (tid == 0) {
        asm volatile("mbarrier.init.shared.b64 [%0], %1;"
                     :: "r"(mb), "r"(1) : "memory");
    }

    // gate-owner lanes: lane 0/1 of each warp own dim d = w*2 + lane
    int d = w * 2 + lane;             // local dim, valid for lane < 2
    int j = blk * 32 + d;             // global dim
    bool owner = (lane < 2);
    float ir = 0.f, iz = 0.f, inn = 0.f, bh_r = 0.f, bh_z = 0.f, bh_n = 0.f;
    if (owner) {
        ir = gi[j];
        iz = gi[256 + j];
        inn = gi[512 + j];
        bh_r = bhh[j];
        bh_z = bhh[256 + j];
        bh_n = bhh[512 + j];
    }
    unsigned int hb0 = smem_u32(&hbuf[0][lane * 8]);
    unsigned int hb1 = smem_u32(&hbuf[1][lane * 8]);
    unsigned int dst0 = smem_u32(&hbuf[0][blk * 32]);   // our slice in hbuf[0]
    unsigned int dst1 = smem_u32(&hbuf[1][blk * 32]);
    unsigned int st0 = smem_u32(&hstage[0][0]);
    unsigned int st1 = smem_u32(&hstage[1][0]);
    __syncthreads();
    cluster_arrive_wait();   // hbufs zeroed + mbarriers initialized everywhere

    for (int t = 0; t < S; t++) {
        int p = t & 1;

        if (tid == 0) {
            // expect this phase's incoming bytes (7 remote CTAs x 128B)
            asm volatile("mbarrier.arrive.expect_tx.shared.b64 _, [%0], %1;"
                         :: "r"(mb), "r"(7 * 128) : "memory");
        }

        // ---- dot: 6 rows x 8 cols per thread (f32x2) ----
        unsigned int haddr = p ? hb1 : hb0;
        unsigned long long h2[4];
        asm volatile("ld.shared.v2.b64 {%0, %1}, [%4];\n\t"
                     "ld.shared.v2.b64 {%2, %3}, [%4 + 16];"
                     : "=l"(h2[0]), "=l"(h2[1]), "=l"(h2[2]), "=l"(h2[3])
                     : "r"(haddr));
        float a[6];
#pragma unroll
        for (int r = 0; r < 6; r++) {
            unsigned long long acc2 = 0ull;
#pragma unroll
            for (int i = 0; i < 4; i++) {
                asm("fma.rn.f32x2 %0, %1, %2, %0;"
                    : "+l"(acc2) : "l"(w2[r][i]), "l"(h2[i]));
            }
            float lo, hi;
            asm("mov.b64 {%0, %1}, %2;" : "=f"(lo), "=f"(hi) : "l"(acc2));
            a[r] = lo + hi;
        }
        // butterfly: afterwards every lane has all 6 totals
#pragma unroll
        for (int m = 16; m >= 1; m >>= 1) {
#pragma unroll
            for (int r = 0; r < 6; r++)
                a[r] += __shfl_xor_sync(0xffffffffu, a[r], m);
        }

        // ---- gate math in-warp (lanes 0..1 of every warp) ----
        if (owner) {
            float ghr = a[0 + lane] + bh_r;      // row index g*2+dd, dd==lane
            float ghz = a[2 + lane] + bh_z;
            float ghn = a[4 + lane] + bh_n;
            float hold = hbuf[p][j];
            float r = 1.f / (1.f + __expf(-(ir + ghr)));
            float z = 1.f / (1.f + __expf(-(iz + ghz)));
            float narg = inn + r * ghn;
            float n = 1.f - 2.f / (1.f + __expf(2.f * narg));
            float hnew = (1.f - z) * n + z * hold;

            hbuf[p ^ 1][j] = hnew;      // self-delivery
            hstage[p ^ 1][d] = hnew;    // bulk-copy source
            // prefetch next token's gi (hidden by exchange wait)
            int tn = (t + 1 < S) ? (t + 1) : t;
            ir = gi[(size_t)tn * G3 + j];
            iz = gi[(size_t)tn * G3 + 256 + j];
            inn = gi[(size_t)tn * G3 + 512 + j];
        }
        __syncthreads();   // all 32 staged values visible

        if (tid == 0) {
            asm volatile("fence.proxy.async.shared::cta;" ::: "memory");
            unsigned int src = p ? st0 : st1;          // hstage[p^1]
            unsigned int dstl = p ? dst0 : dst1;       // hbuf[p^1] slice
#pragma unroll
            for (int r2 = 0; r2 < RB; r2++) {
                if (r2 == blk) continue;
                unsigned int pd, pm;
                asm volatile("mapa.shared::cluster.u32 %0, %1, %2;"
                             : "=r"(pd) : "r"(dstl), "r"(r2));
                asm volatile("mapa.shared::cluster.u32 %0, %1, %2;"
                             : "=r"(pm) : "r"(mb), "r"(r2));
                asm volatile(
                    "cp.async.bulk.shared::cluster.shared::cta.mbarrier::complete_tx::bytes "
                    "[%0], [%1], 128, [%2];"
                    :: "r"(pd), "r"(src), "r"(pm) : "memory");
            }
            mbar_wait_parity(mb, (unsigned int)(t & 1));
        }
        __syncthreads();   // release CTA once all 7 slices arrived
    }

    if (blk == 0) {
        for (int i = tid; i < out_size; i += RT)
            out[i] = hbuf[0][i & 255];
    }
}

// ---------------- host launcher ----------------
extern "C" void kernel_launch(void* const* d_in, const int* in_sizes, int n_in,
                              void* d_out, int out_size) {
    const int* tokens = (const int*)d_in[0];
    const float* emb = (const float*)d_in[1];
    const float* Wq = (const float*)d_in[2];
    const float* bq = (const float*)d_in[3];
    const float* Wk = (const float*)d_in[4];
    const float* bk = (const float*)d_in[5];
    const float* Wv = (const float*)d_in[6];
    const float* bv = (const float*)d_in[7];
    const float* Wo = (const float*)d_in[8];
    const float* bo = (const float*)d_in[9];
    const float* ln_g = (const float*)d_in[10];
    const float* ln_b = (const float*)d_in[11];
    const float* W_ih = (const float*)d_in[12];
    const float* W_hh = (const float*)d_in[13];
    const float* b_ih = (const float*)d_in[14];
    const float* b_hh = (const float*)d_in[15];
    float* out = (float*)d_out;

    float* px; cudaGetSymbolAddress((void**)&px, g_x);
    float* pq; cudaGetSymbolAddress((void**)&pq, g_q);
    float* pk; cudaGetSymbolAddress((void**)&pk, g_k);
    float* pv; cudaGetSymbolAddress((void**)&pv, g_v);
    float* po; cudaGetSymbolAddress((void**)&po, g_o);
    float* pypre; cudaGetSymbolAddress((void**)&pypre, g_ypre);
    float* py; cudaGetSymbolAddress((void**)&py, g_y);
    float* pgi; cudaGetSymbolAddress((void**)&pgi, g_gi);

    size_t attn_smem = (size_t)(3 * 64 * LDQ + 64 * LDP + 64) * sizeof(float);
    cudaFuncSetAttribute(attn_kernel, cudaFuncAttributeMaxDynamicSharedMemorySize,
                         (int)attn_smem);

    embed_kernel<<<S, 64>>>(tokens, emb);

    dim3 gqkv(4, 64, NH);
    gemm_k<0><<<gqkv, 256>>>(px, Wq, bq, nullptr, pq);
    gemm_k<0><<<gqkv, 256>>>(px, Wk, bk, nullptr, pk);
    gemm_k<0><<<gqkv, 256>>>(px, Wv, bv, nullptr, pv);

    dim3 gatt(S / 64, NH);
    attn_kernel<<<gatt, 256, attn_smem>>>(pq, pk, pv, po);

    dim3 gop(4, 64, 1);
    gemm_k<1><<<gop, 256>>>(po, Wo, bo, px, pypre);

    ln_kernel<<<S / 8, 256>>>(pypre, ln_g, ln_b, py);

    dim3 ggi(12, 64, 1);
    gemm_k<2><<<ggi, 256>>>(py, W_ih, b_ih, nullptr, pgi);

    rnn_kernel<<<RB, RT>>>(pgi, W_hh, b_hh, out, out_size);
}

// round 8
// speedup vs baseline: 3.4225x; 1.0032x over previous
#include <cuda_runtime.h>
#include <cuda_bf16.h>
#include <mma.h>
#include <math.h>
#include <stddef.h>

using namespace nvcuda;

#define S 4096
#define H 256
#define NH 6
#define G3 768
#define EPS 1e-5f

// ---------------- scratch (static device arrays; no allocation) ----------------
__device__ float g_x[S * H];            // embedded tokens
__device__ float g_q[NH * S * H];
__device__ float g_k[NH * S * H];
__device__ float g_v[NH * S * H];
__device__ float g_o[NH * S * H];       // attention output per head
__device__ float g_ypre[S * H];         // x + attn_proj (pre-LN)
__device__ float g_y[S * H];            // post-LN
__device__ float g_gi[S * G3];          // y @ W_ih^T + b_ih

// ---------------- embedding gather ----------------
__global__ void embed_kernel(const int* __restrict__ tokens,
                             const float* __restrict__ emb) {
    int s = blockIdx.x;
    int tok = tokens[s];
    const float4* src = (const float4*)(emb + (size_t)tok * H);
    float4* dst = (float4*)(g_x + (size_t)s * H);
    dst[threadIdx.x] = src[threadIdx.x];   // 64 threads * 4
}

// ---------------- generic tiled GEMM (64x64 tile, 256 threads, 4x4 micro) ----
template <int MODE>
__global__ __launch_bounds__(256) void gemm_k(const float* __restrict__ A,
                                              const float* __restrict__ B,
                                              const float* __restrict__ bias,
                                              const float* __restrict__ resid,
                                              float* __restrict__ C) {
    const int KTOT = (MODE == 1) ? 1536 : 256;
    const int NTOT = (MODE == 2) ? 768 : 256;
    __shared__ float As[64][65];
    __shared__ float Bs[64][65];
    int tid = threadIdx.x;
    int m0 = blockIdx.y * 64, n0 = blockIdx.x * 64;
    int z = blockIdx.z;
    const float* Bb = (MODE == 0) ? (B + (size_t)z * 256 * 256) : B;

    float acc[4][4];
#pragma unroll
    for (int i = 0; i < 4; i++)
#pragma unroll
        for (int j = 0; j < 4; j++) acc[i][j] = 0.f;

    int ty = tid >> 4, tx = tid & 15;

    for (int k0 = 0; k0 < KTOT; k0 += 64) {
        const float* Asrc;
        if (MODE == 1) {
            int head = k0 >> 8;
            int d0 = k0 & 255;
            Asrc = A + (size_t)head * (S * 256) + d0;
        } else {
            Asrc = A + k0;
        }
#pragma unroll
        for (int i = 0; i < 16; i++) {
            int lin = i * 256 + tid;
            int m = lin >> 6, kk = lin & 63;
            As[m][kk] = Asrc[(size_t)(m0 + m) * 256 + kk];
        }
        if (MODE == 2) {
#pragma unroll
            for (int i = 0; i < 16; i++) {
                int lin = i * 256 + tid;
                int n = lin >> 6, kk = lin & 63;
                Bs[kk][n] = Bb[(size_t)(n0 + n) * 256 + (k0 + kk)];
            }
        } else {
#pragma unroll
            for (int i = 0; i < 16; i++) {
                int lin = i * 256 + tid;
                int kk = lin >> 6, n = lin & 63;
                Bs[kk][n] = Bb[(size_t)(k0 + kk) * NTOT + n0 + n];
            }
        }
        __syncthreads();
#pragma unroll 8
        for (int kk = 0; kk < 64; kk++) {
            float a[4], b[4];
#pragma unroll
            for (int i = 0; i < 4; i++) a[i] = As[ty * 4 + i][kk];
#pragma unroll
            for (int j = 0; j < 4; j++) b[j] = Bs[kk][tx * 4 + j];
#pragma unroll
            for (int i = 0; i < 4; i++)
#pragma unroll
                for (int j = 0; j < 4; j++) acc[i][j] += a[i] * b[j];
        }
        __syncthreads();
    }

#pragma unroll
    for (int i = 0; i < 4; i++) {
        int m = m0 + ty * 4 + i;
#pragma unroll
        for (int j = 0; j < 4; j++) {
            int n = n0 + tx * 4 + j;
            float v = acc[i][j];
            if (MODE == 0) {
                v += bias[z * 256 + n];
                C[(size_t)z * S * 256 + (size_t)m * 256 + n] = v;
            } else if (MODE == 1) {
                v += bias[n] + resid[(size_t)m * 256 + n];
                C[(size_t)m * 256 + n] = v;
            } else {
                v += bias[n];
                C[(size_t)m * 768 + n] = v;
            }
        }
    }
}

// ---------------- WMMA tf32 streaming attention ------------------------------
#define LDQ 268
#define LDP 76
__global__ __launch_bounds__(256) void attn_kernel(const float* __restrict__ Q,
                                                   const float* __restrict__ K,
                                                   const float* __restrict__ V,
                                                   float* __restrict__ O) {
    extern __shared__ float sm[];
    float* Qs = sm;
    float* Ks = Qs + 64 * LDQ;
    float* Vs = Ks + 64 * LDQ;
    float* Ps = Vs + 64 * LDQ;
    float* Ls = Ps + 64 * LDP;

    int h = blockIdx.y;
    int q0 = blockIdx.x * 64;
    int tid = threadIdx.x;
    int warp = tid >> 5;
    int wm = warp & 3;
    int wn = warp >> 2;

    const float* Qg = Q + ((size_t)h * S + q0) * H;
    const float* Kg = K + (size_t)h * S * H;
    const float* Vg = V + (size_t)h * S * H;

    for (int i = tid; i < 64 * 64; i += 256) {
        int q = i >> 6, d4 = i & 63;
        ((float4*)(Qs + q * LDQ))[d4] = ((const float4*)(Qg + (size_t)q * H))[d4];
    }

    wmma::fragment<wmma::accumulator, 16, 16, 8, float> o_frag[8];
#pragma unroll
    for (int f = 0; f < 8; f++) wmma::fill_fragment(o_frag[f], 0.0f);

    int lrow = tid >> 2;
    int lcol0 = (tid & 3) * 16;
    float l_part = 0.f;
    const float inv_scale = 0.0625f;

    for (int kt = 0; kt < S / 64; kt++) {
        __syncthreads();
        for (int i = tid; i < 64 * 64; i += 256) {
            int r = i >> 6, d4 = i & 63;
            ((float4*)(Ks + r * LDQ))[d4] =
                ((const float4*)(Kg + (size_t)(kt * 64 + r) * H))[d4];
            ((float4*)(Vs + r * LDQ))[d4] =
                ((const float4*)(Vg + (size_t)(kt * 64 + r) * H))[d4];
        }
        __syncthreads();

        {
            wmma::fragment<wmma::matrix_a, 16, 16, 8, wmma::precision::tf32,
                           wmma::row_major> af;
            wmma::fragment<wmma::matrix_b, 16, 16, 8, wmma::precision::tf32,
                           wmma::col_major> bf;
            wmma::fragment<wmma::accumulator, 16, 16, 8, float> c[2];
            wmma::fill_fragment(c[0], 0.0f);
            wmma::fill_fragment(c[1], 0.0f);
#pragma unroll 4
            for (int k = 0; k < 32; k++) {
                wmma::load_matrix_sync(af, Qs + (wm * 16) * LDQ + k * 8, LDQ);
#pragma unroll
                for (int e = 0; e < af.num_elements; e++)
                    af.x[e] = wmma::__float_to_tf32(af.x[e]);
#pragma unroll
                for (int nf = 0; nf < 2; nf++) {
                    wmma::load_matrix_sync(
                        bf, Ks + (wn * 32 + nf * 16) * LDQ + k * 8, LDQ);
#pragma unroll
                    for (int e = 0; e < bf.num_elements; e++)
                        bf.x[e] = wmma::__float_to_tf32(bf.x[e]);
                    wmma::mma_sync(c[nf], af, bf, c[nf]);
                }
            }
#pragma unroll
            for (int nf = 0; nf < 2; nf++)
                wmma::store_matrix_sync(
                    Ps + (wm * 16) * LDP + wn * 32 + nf * 16, c[nf], LDP,
                    wmma::mem_row_major);
        }
        __syncthreads();

        {
            float* pr = Ps + lrow * LDP + lcol0;
            float ssum = 0.f;
#pragma unroll
            for (int j = 0; j < 16; j++) {
                float e = __expf(pr[j] * inv_scale);
                pr[j] = e;
                ssum += e;
            }
            l_part += ssum;
        }
        __syncthreads();

        {
            wmma::fragment<wmma::matrix_a, 16, 16, 8, wmma::precision::tf32,
                           wmma::row_major> pa;
            wmma::fragment<wmma::matrix_b, 16, 16, 8, wmma::precision::tf32,
                           wmma::row_major> vb;
#pragma unroll
            for (int k = 0; k < 8; k++) {
                wmma::load_matrix_sync(pa, Ps + (wm * 16) * LDP + k * 8, LDP);
#pragma unroll
                for (int e = 0; e < pa.num_elements; e++)
                    pa.x[e] = wmma::__float_to_tf32(pa.x[e]);
#pragma unroll
                for (int nf = 0; nf < 8; nf++) {
                    wmma::load_matrix_sync(
                        vb, Vs + (k * 8) * LDQ + wn * 128 + nf * 16, LDQ);
#pragma unroll
                    for (int e = 0; e < vb.num_elements; e++)
                        vb.x[e] = wmma::__float_to_tf32(vb.x[e]);
                    wmma::mma_sync(o_frag[nf], pa, vb, o_frag[nf]);
                }
            }
        }
    }

    l_part += __shfl_xor_sync(0xffffffffu, l_part, 1);
    l_part += __shfl_xor_sync(0xffffffffu, l_part, 2);
    if ((tid & 3) == 0) Ls[lrow] = l_part;

#pragma unroll
    for (int nf = 0; nf < 8; nf++)
        wmma::store_matrix_sync(Qs + (wm * 16) * LDQ + wn * 128 + nf * 16,
                                o_frag[nf], LDQ, wmma::mem_row_major);
    __syncthreads();

    float* Og = O + ((size_t)h * S + q0) * H;
    for (int i = tid; i < 64 * 64; i += 256) {
        int q = i >> 6, d4 = i & 63;
        float inv_l = __frcp_rn(Ls[q]);
        float4 v = ((float4*)(Qs + q * LDQ))[d4];
        v.x *= inv_l; v.y *= inv_l; v.z *= inv_l; v.w *= inv_l;
        ((float4*)(Og + (size_t)q * H))[d4] = v;
    }
}

// ---------------- LayerNorm (one warp per row) ----------------
__global__ __launch_bounds__(256) void ln_kernel(const float* __restrict__ yin,
                                                 const float* __restrict__ g,
                                                 const float* __restrict__ b,
                                                 float* __restrict__ yout) {
    int row = blockIdx.x * 8 + (threadIdx.x >> 5);
    int lane = threadIdx.x & 31;
    const float* yr = yin + (size_t)row * H;
    float v[8], s = 0.f, sq = 0.f;
#pragma unroll
    for (int i = 0; i < 8; i++) {
        v[i] = yr[lane + i * 32];
        s += v[i];
        sq += v[i] * v[i];
    }
#pragma unroll
    for (int m = 16; m >= 1; m >>= 1) {
        s += __shfl_xor_sync(0xffffffffu, s, m);
        sq += __shfl_xor_sync(0xffffffffu, sq, m);
    }
    float mu = s * (1.f / H);
    float var = sq * (1.f / H) - mu * mu;
    float rstd = rsqrtf(var + EPS);
    float* yo = yout + (size_t)row * H;
#pragma unroll
    for (int i = 0; i < 8; i++) {
        int c = lane + i * 32;
        yo[c] = (v[i] - mu) * rstd * g[c] + b[c];
    }
}

// ---------------- GRU recurrence: 8-CTA cluster, parallel bulk exchange ------
// As R7, except the 7 cp.async.bulk S2S copies are issued by 7 DIFFERENT
// threads (tid<8, tid!=blk), one copy each, so the transfers proceed
// concurrently instead of serializing behind tid0's issue stream / the
// engine's descriptor queue.
#define RB 8
#define RT 512

__device__ __forceinline__ unsigned int smem_u32(const void* p) {
    unsigned int a;
    asm("{ .reg .u64 t; cvta.to.shared.u64 t, %1; cvt.u32.u64 %0, t; }"
        : "=r"(a) : "l"(p));
    return a;
}

__device__ __forceinline__ void cluster_arrive_wait() {
    asm volatile("barrier.cluster.arrive.aligned;" ::: "memory");
    asm volatile("barrier.cluster.wait.aligned;" ::: "memory");
}

__device__ __forceinline__ void mbar_wait_parity(unsigned int mb,
                                                 unsigned int parity) {
    asm volatile(
        "{\n\t"
        ".reg .pred P;\n\t"
        "WL%=:\n\t"
        "mbarrier.try_wait.parity.acquire.cta.shared::cta.b64 P, [%0], %1, 0x989680;\n\t"
        "@!P bra WL%=;\n\t"
        "}"
        :: "r"(mb), "r"(parity) : "memory");
}

__global__ void __cluster_dims__(RB, 1, 1) __launch_bounds__(RT, 1)
rnn_kernel(const float* __restrict__ gi,
           const float* __restrict__ Whh,
           const float* __restrict__ bhh,
           float* __restrict__ out,
           int out_size) {
    __shared__ __align__(16) float hbuf[2][H];
    __shared__ __align__(16) float hstage[2][32];   // parity-staged bulk source
    __shared__ __align__(8) unsigned long long mbar;

    int blk = blockIdx.x;
    int tid = threadIdx.x;
    int w = tid >> 5;                 // warp 0..15
    int lane = tid & 31;

    // weights: rows (g, dd) -> global row g*256 + blk*32 + w*2 + dd,
    // cols lane*8..lane*8+7, packed f32x2. 6 rows x 4 ull = 24 ull.
    unsigned long long w2[6][4];
#pragma unroll
    for (int g = 0; g < 3; g++) {
#pragma unroll
        for (int dd = 0; dd < 2; dd++) {
            int rowg = g * 256 + blk * 32 + w * 2 + dd;
            const unsigned long long* src =
                (const unsigned long long*)(Whh + (size_t)rowg * H + lane * 8);
#pragma unroll
            for (int i = 0; i < 4; i++) w2[g * 2 + dd][i] = src[i];
        }
    }

    for (int i = tid; i < 2 * H; i += RT) ((float*)hbuf)[i] = 0.f;

    unsigned int mb = smem_u32(&mbar);
    if (tid == 0) {
        asm volatile("mbarrier.init.shared.b64 [%0], %1;"
                     :: "r"(mb), "r"(1) : "memory");
    }

    // gate-owner lanes: lane 0/1 of each warp own dim d = w*2 + lane
    int d = w * 2 + lane;             // local dim, valid for lane < 2
    int j = blk * 32 + d;             // global dim
    bool owner = (lane < 2);
    float ir = 0.f, iz = 0.f, inn = 0.f, bh_r = 0.f, bh_z = 0.f, bh_n = 0.f;
    if (owner) {
        ir = gi[j];
        iz = gi[256 + j];
        inn = gi[512 + j];
        bh_r = bhh[j];
        bh_z = bhh[256 + j];
        bh_n = bhh[512 + j];
    }
    unsigned int hb0 = smem_u32(&hbuf[0][lane * 8]);
    unsigned int hb1 = smem_u32(&hbuf[1][lane * 8]);
    unsigned int dst0 = smem_u32(&hbuf[0][blk * 32]);   // our slice in hbuf[0]
    unsigned int dst1 = smem_u32(&hbuf[1][blk * 32]);
    unsigned int st0 = smem_u32(&hstage[0][0]);
    unsigned int st1 = smem_u32(&hstage[1][0]);
    __syncthreads();
    cluster_arrive_wait();   // hbufs zeroed + mbarriers initialized everywhere

    for (int t = 0; t < S; t++) {
        int p = t & 1;

        if (tid == 0) {
            // expect this phase's incoming bytes (7 remote CTAs x 128B)
            asm volatile("mbarrier.arrive.expect_tx.shared.b64 _, [%0], %1;"
                         :: "r"(mb), "r"(7 * 128) : "memory");
        }

        // ---- dot: 6 rows x 8 cols per thread (f32x2) ----
        unsigned int haddr = p ? hb1 : hb0;
        unsigned long long h2[4];
        asm volatile("ld.shared.v2.b64 {%0, %1}, [%4];\n\t"
                     "ld.shared.v2.b64 {%2, %3}, [%4 + 16];"
                     : "=l"(h2[0]), "=l"(h2[1]), "=l"(h2[2]), "=l"(h2[3])
                     : "r"(haddr));
        float a[6];
#pragma unroll
        for (int r = 0; r < 6; r++) {
            unsigned long long acc2 = 0ull;
#pragma unroll
            for (int i = 0; i < 4; i++) {
                asm("fma.rn.f32x2 %0, %1, %2, %0;"
                    : "+l"(acc2) : "l"(w2[r][i]), "l"(h2[i]));
            }
            float lo, hi;
            asm("mov.b64 {%0, %1}, %2;" : "=f"(lo), "=f"(hi) : "l"(acc2));
            a[r] = lo + hi;
        }
        // butterfly: afterwards every lane has all 6 totals
#pragma unroll
        for (int m = 16; m >= 1; m >>= 1) {
#pragma unroll
            for (int r = 0; r < 6; r++)
                a[r] += __shfl_xor_sync(0xffffffffu, a[r], m);
        }

        // ---- gate math in-warp (lanes 0..1 of every warp) ----
        if (owner) {
            float ghr = a[0 + lane] + bh_r;      // row index g*2+dd, dd==lane
            float ghz = a[2 + lane] + bh_z;
            float ghn = a[4 + lane] + bh_n;
            float hold = hbuf[p][j];
            float r = 1.f / (1.f + __expf(-(ir + ghr)));
            float z = 1.f / (1.f + __expf(-(iz + ghz)));
            float narg = inn + r * ghn;
            float n = 1.f - 2.f / (1.f + __expf(2.f * narg));
            float hnew = (1.f - z) * n + z * hold;

            hbuf[p ^ 1][j] = hnew;      // self-delivery
            hstage[p ^ 1][d] = hnew;    // bulk-copy source
            // prefetch next token's gi (hidden by exchange wait)
            int tn = (t + 1 < S) ? (t + 1) : t;
            ir = gi[(size_t)tn * G3 + j];
            iz = gi[(size_t)tn * G3 + 256 + j];
            inn = gi[(size_t)tn * G3 + 512 + j];
        }
        __syncthreads();   // all 32 staged values visible (bar drains STS)

        // ---- parallel-issue exchange: 7 lanes, one bulk copy each ----
        if (tid < RB && tid != blk) {
            asm volatile("fence.proxy.async.shared::cta;" ::: "memory");
            unsigned int src = p ? st0 : st1;          // hstage[p^1]
            unsigned int dstl = p ? dst0 : dst1;       // hbuf[p^1] slice
            unsigned int pd, pm;
            asm volatile("mapa.shared::cluster.u32 %0, %1, %2;"
                         : "=r"(pd) : "r"(dstl), "r"(tid));
            asm volatile("mapa.shared::cluster.u32 %0, %1, %2;"
                         : "=r"(pm) : "r"(mb), "r"(tid));
            asm volatile(
                "cp.async.bulk.shared::cluster.shared::cta.mbarrier::complete_tx::bytes "
                "[%0], [%1], 128, [%2];"
                :: "r"(pd), "r"(src), "r"(pm) : "memory");
        }
        if (tid == 0) mbar_wait_parity(mb, (unsigned int)(t & 1));
        __syncthreads();   // release CTA once all 7 slices arrived
    }

    if (blk == 0) {
        for (int i = tid; i < out_size; i += RT)
            out[i] = hbuf[0][i & 255];
    }
}

// ---------------- host launcher ----------------
extern "C" void kernel_launch(void* const* d_in, const int* in_sizes, int n_in,
                              void* d_out, int out_size) {
    const int* tokens = (const int*)d_in[0];
    const float* emb = (const float*)d_in[1];
    const float* Wq = (const float*)d_in[2];
    const float* bq = (const float*)d_in[3];
    const float* Wk = (const float*)d_in[4];
    const float* bk = (const float*)d_in[5];
    const float* Wv = (const float*)d_in[6];
    const float* bv = (const float*)d_in[7];
    const float* Wo = (const float*)d_in[8];
    const float* bo = (const float*)d_in[9];
    const float* ln_g = (const float*)d_in[10];
    const float* ln_b = (const float*)d_in[11];
    const float* W_ih = (const float*)d_in[12];
    const float* W_hh = (const float*)d_in[13];
    const float* b_ih = (const float*)d_in[14];
    const float* b_hh = (const float*)d_in[15];
    float* out = (float*)d_out;

    float* px; cudaGetSymbolAddress((void**)&px, g_x);
    float* pq; cudaGetSymbolAddress((void**)&pq, g_q);
    float* pk; cudaGetSymbolAddress((void**)&pk, g_k);
    float* pv; cudaGetSymbolAddress((void**)&pv, g_v);
    float* po; cudaGetSymbolAddress((void**)&po, g_o);
    float* pypre; cudaGetSymbolAddress((void**)&pypre, g_ypre);
    float* py; cudaGetSymbolAddress((void**)&py, g_y);
    float* pgi; cudaGetSymbolAddress((void**)&pgi, g_gi);

    size_t attn_smem = (size_t)(3 * 64 * LDQ + 64 * LDP + 64) * sizeof(float);
    cudaFuncSetAttribute(attn_kernel, cudaFuncAttributeMaxDynamicSharedMemorySize,
                         (int)attn_smem);

    embed_kernel<<<S, 64>>>(tokens, emb);

    dim3 gqkv(4, 64, NH);
    gemm_k<0><<<gqkv, 256>>>(px, Wq, bq, nullptr, pq);
    gemm_k<0><<<gqkv, 256>>>(px, Wk, bk, nullptr, pk);
    gemm_k<0><<<gqkv, 256>>>(px, Wv, bv, nullptr, pv);

    dim3 gatt(S / 64, NH);
    attn_kernel<<<gatt, 256, attn_smem>>>(pq, pk, pv, po);

    dim3 gop(4, 64, 1);
    gemm_k<1><<<gop, 256>>>(po, Wo, bo, px, pypre);

    ln_kernel<<<S / 8, 256>>>(pypre, ln_g, ln_b, py);

    dim3 ggi(12, 64, 1);
    gemm_k<2><<<ggi, 256>>>(py, W_ih, b_ih, nullptr, pgi);

    rnn_kernel<<<RB, RT>>>(pgi, W_hh, b_hh, out, out_size);
}

// round 9
// speedup vs baseline: 3.8770x; 1.1328x over previous
#include <cuda_runtime.h>
#include <cuda_bf16.h>
#include <mma.h>
#include <math.h>
#include <stddef.h>

using namespace nvcuda;

#define S 4096
#define H 256
#define NH 6
#define G3 768
#define EPS 1e-5f

// ---------------- scratch (static device arrays; no allocation) ----------------
__device__ float g_x[S * H];            // embedded tokens
__device__ float g_q[NH * S * H];
__device__ float g_k[NH * S * H];
__device__ float g_v[NH * S * H];
__device__ float g_o[NH * S * H];       // attention output per head
__device__ float g_ypre[S * H];         // x + attn_proj (pre-LN)
__device__ float g_y[S * H];            // post-LN
__device__ float g_gi[S * G3];          // y @ W_ih^T + b_ih

// ---------------- embedding gather ----------------
__global__ void embed_kernel(const int* __restrict__ tokens,
                             const float* __restrict__ emb) {
    int s = blockIdx.x;
    int tok = tokens[s];
    const float4* src = (const float4*)(emb + (size_t)tok * H);
    float4* dst = (float4*)(g_x + (size_t)s * H);
    dst[threadIdx.x] = src[threadIdx.x];   // 64 threads * 4
}

// ---------------- WMMA tf32 GEMM (64x64 tile, 8 warps, 4x2 warp grid) --------
// MODE 0: C[z] = X @ W[z] + bias[z]         (QKV; K=256, N=256, z=head)
// MODE 1: C = gather(g_o) @ Wo + bo + g_x   (out-proj + residual; K=1536)
// MODE 2: C = y @ W_ih^T + b_ih             (K=256, N=768; B = W_ih rows)
#define LDG_ 68
template <int MODE>
__global__ __launch_bounds__(256) void gemm_w(const float* __restrict__ A,
                                              const float* __restrict__ B,
                                              const float* __restrict__ bias,
                                              const float* __restrict__ resid,
                                              float* __restrict__ C) {
    const int KTOT = (MODE == 1) ? 1536 : 256;
    const int NTOT = (MODE == 2) ? 768 : 256;
    __shared__ float As[64 * LDG_];
    __shared__ float Bs[64 * LDG_];
    int tid = threadIdx.x;
    int warp = tid >> 5;
    int wm = warp & 3;                  // m-tile 0..3
    int wn = warp >> 2;                 // n-group 0..1
    int m0 = blockIdx.y * 64, n0 = blockIdx.x * 64;
    int z = blockIdx.z;
    const float* Bb = (MODE == 0) ? (B + (size_t)z * 256 * 256) : B;

    wmma::fragment<wmma::accumulator, 16, 16, 8, float> c[2];
    wmma::fill_fragment(c[0], 0.0f);
    wmma::fill_fragment(c[1], 0.0f);

    for (int k0 = 0; k0 < KTOT; k0 += 64) {
        const float* Asrc;
        if (MODE == 1) {
            Asrc = A + (size_t)(k0 >> 8) * (S * 256) + (k0 & 255);
        } else {
            Asrc = A + k0;
        }
        // A tile: As[m][kk] (row-major), float4 over kk
        for (int i = tid; i < 64 * 16; i += 256) {
            int m = i >> 4, k4 = i & 15;
            float4 v = *(const float4*)(Asrc + (size_t)(m0 + m) * 256 + k4 * 4);
            *(float4*)(As + m * LDG_ + k4 * 4) = v;
        }
        // B tile
        if (MODE == 2) {
            // W_ih rows: Bs[n][kk] (k contiguous) -> col_major fragment
            for (int i = tid; i < 64 * 16; i += 256) {
                int n = i >> 4, k4 = i & 15;
                float4 v = *(const float4*)(Bb + (size_t)(n0 + n) * 256 + k0 + k4 * 4);
                *(float4*)(Bs + n * LDG_ + k4 * 4) = v;
            }
        } else {
            // B[k][n] row-major: Bs[kk][n], float4 over n
            for (int i = tid; i < 64 * 16; i += 256) {
                int kk = i >> 4, n4 = i & 15;
                float4 v = *(const float4*)(Bb + (size_t)(k0 + kk) * NTOT + n0 + n4 * 4);
                *(float4*)(Bs + kk * LDG_ + n4 * 4) = v;
            }
        }
        __syncthreads();

        wmma::fragment<wmma::matrix_a, 16, 16, 8, wmma::precision::tf32,
                       wmma::row_major> af;
#pragma unroll
        for (int k = 0; k < 8; k++) {
            wmma::load_matrix_sync(af, As + (wm * 16) * LDG_ + k * 8, LDG_);
#pragma unroll
            for (int e = 0; e < af.num_elements; e++)
                af.x[e] = wmma::__float_to_tf32(af.x[e]);
            if (MODE == 2) {
                wmma::fragment<wmma::matrix_b, 16, 16, 8, wmma::precision::tf32,
                               wmma::col_major> bf;
#pragma unroll
                for (int nf = 0; nf < 2; nf++) {
                    wmma::load_matrix_sync(
                        bf, Bs + (wn * 32 + nf * 16) * LDG_ + k * 8, LDG_);
#pragma unroll
                    for (int e = 0; e < bf.num_elements; e++)
                        bf.x[e] = wmma::__float_to_tf32(bf.x[e]);
                    wmma::mma_sync(c[nf], af, bf, c[nf]);
                }
            } else {
                wmma::fragment<wmma::matrix_b, 16, 16, 8, wmma::precision::tf32,
                               wmma::row_major> bf;
#pragma unroll
                for (int nf = 0; nf < 2; nf++) {
                    wmma::load_matrix_sync(
                        bf, Bs + (k * 8) * LDG_ + wn * 32 + nf * 16, LDG_);
#pragma unroll
                    for (int e = 0; e < bf.num_elements; e++)
                        bf.x[e] = wmma::__float_to_tf32(bf.x[e]);
                    wmma::mma_sync(c[nf], af, bf, c[nf]);
                }
            }
        }
        __syncthreads();
    }

    // stage result in As, then epilogue
#pragma unroll
    for (int nf = 0; nf < 2; nf++)
        wmma::store_matrix_sync(As + (wm * 16) * LDG_ + wn * 32 + nf * 16,
                                c[nf], LDG_, wmma::mem_row_major);
    __syncthreads();

    for (int i = tid; i < 64 * 64; i += 256) {
        int m = i >> 6, n = i & 63;
        float v = As[m * LDG_ + n];
        int gm = m0 + m, gn = n0 + n;
        if (MODE == 0) {
            v += bias[z * 256 + gn];
            C[(size_t)z * S * 256 + (size_t)gm * 256 + gn] = v;
        } else if (MODE == 1) {
            v += bias[gn] + resid[(size_t)gm * 256 + gn];
            C[(size_t)gm * 256 + gn] = v;
        } else {
            v += bias[gn];
            C[(size_t)gm * 768 + gn] = v;
        }
    }
}

// ---------------- WMMA tf32 streaming attention ------------------------------
#define LDQ 268
#define LDP 76
__global__ __launch_bounds__(256) void attn_kernel(const float* __restrict__ Q,
                                                   const float* __restrict__ K,
                                                   const float* __restrict__ V,
                                                   float* __restrict__ O) {
    extern __shared__ float sm[];
    float* Qs = sm;
    float* Ks = Qs + 64 * LDQ;
    float* Vs = Ks + 64 * LDQ;
    float* Ps = Vs + 64 * LDQ;
    float* Ls = Ps + 64 * LDP;

    int h = blockIdx.y;
    int q0 = blockIdx.x * 64;
    int tid = threadIdx.x;
    int warp = tid >> 5;
    int wm = warp & 3;
    int wn = warp >> 2;

    const float* Qg = Q + ((size_t)h * S + q0) * H;
    const float* Kg = K + (size_t)h * S * H;
    const float* Vg = V + (size_t)h * S * H;

    for (int i = tid; i < 64 * 64; i += 256) {
        int q = i >> 6, d4 = i & 63;
        ((float4*)(Qs + q * LDQ))[d4] = ((const float4*)(Qg + (size_t)q * H))[d4];
    }

    wmma::fragment<wmma::accumulator, 16, 16, 8, float> o_frag[8];
#pragma unroll
    for (int f = 0; f < 8; f++) wmma::fill_fragment(o_frag[f], 0.0f);

    int lrow = tid >> 2;
    int lcol0 = (tid & 3) * 16;
    float l_part = 0.f;
    const float inv_scale = 0.0625f;

    for (int kt = 0; kt < S / 64; kt++) {
        __syncthreads();
        for (int i = tid; i < 64 * 64; i += 256) {
            int r = i >> 6, d4 = i & 63;
            ((float4*)(Ks + r * LDQ))[d4] =
                ((const float4*)(Kg + (size_t)(kt * 64 + r) * H))[d4];
            ((float4*)(Vs + r * LDQ))[d4] =
                ((const float4*)(Vg + (size_t)(kt * 64 + r) * H))[d4];
        }
        __syncthreads();

        {
            wmma::fragment<wmma::matrix_a, 16, 16, 8, wmma::precision::tf32,
                           wmma::row_major> af;
            wmma::fragment<wmma::matrix_b, 16, 16, 8, wmma::precision::tf32,
                           wmma::col_major> bf;
            wmma::fragment<wmma::accumulator, 16, 16, 8, float> c[2];
            wmma::fill_fragment(c[0], 0.0f);
            wmma::fill_fragment(c[1], 0.0f);
#pragma unroll 4
            for (int k = 0; k < 32; k++) {
                wmma::load_matrix_sync(af, Qs + (wm * 16) * LDQ + k * 8, LDQ);
#pragma unroll
                for (int e = 0; e < af.num_elements; e++)
                    af.x[e] = wmma::__float_to_tf32(af.x[e]);
#pragma unroll
                for (int nf = 0; nf < 2; nf++) {
                    wmma::load_matrix_sync(
                        bf, Ks + (wn * 32 + nf * 16) * LDQ + k * 8, LDQ);
#pragma unroll
                    for (int e = 0; e < bf.num_elements; e++)
                        bf.x[e] = wmma::__float_to_tf32(bf.x[e]);
                    wmma::mma_sync(c[nf], af, bf, c[nf]);
                }
            }
#pragma unroll
            for (int nf = 0; nf < 2; nf++)
                wmma::store_matrix_sync(
                    Ps + (wm * 16) * LDP + wn * 32 + nf * 16, c[nf], LDP,
                    wmma::mem_row_major);
        }
        __syncthreads();

        {
            float* pr = Ps + lrow * LDP + lcol0;
            float ssum = 0.f;
#pragma unroll
            for (int j = 0; j < 16; j++) {
                float e = __expf(pr[j] * inv_scale);
                pr[j] = e;
                ssum += e;
            }
            l_part += ssum;
        }
        __syncthreads();

        {
            wmma::fragment<wmma::matrix_a, 16, 16, 8, wmma::precision::tf32,
                           wmma::row_major> pa;
            wmma::fragment<wmma::matrix_b, 16, 16, 8, wmma::precision::tf32,
                           wmma::row_major> vb;
#pragma unroll
            for (int k = 0; k < 8; k++) {
                wmma::load_matrix_sync(pa, Ps + (wm * 16) * LDP + k * 8, LDP);
#pragma unroll
                for (int e = 0; e < pa.num_elements; e++)
                    pa.x[e] = wmma::__float_to_tf32(pa.x[e]);
#pragma unroll
                for (int nf = 0; nf < 8; nf++) {
                    wmma::load_matrix_sync(
                        vb, Vs + (k * 8) * LDQ + wn * 128 + nf * 16, LDQ);
#pragma unroll
                    for (int e = 0; e < vb.num_elements; e++)
                        vb.x[e] = wmma::__float_to_tf32(vb.x[e]);
                    wmma::mma_sync(o_frag[nf], pa, vb, o_frag[nf]);
                }
            }
        }
    }

    l_part += __shfl_xor_sync(0xffffffffu, l_part, 1);
    l_part += __shfl_xor_sync(0xffffffffu, l_part, 2);
    if ((tid & 3) == 0) Ls[lrow] = l_part;

#pragma unroll
    for (int nf = 0; nf < 8; nf++)
        wmma::store_matrix_sync(Qs + (wm * 16) * LDQ + wn * 128 + nf * 16,
                                o_frag[nf], LDQ, wmma::mem_row_major);
    __syncthreads();

    float* Og = O + ((size_t)h * S + q0) * H;
    for (int i = tid; i < 64 * 64; i += 256) {
        int q = i >> 6, d4 = i & 63;
        float inv_l = __frcp_rn(Ls[q]);
        float4 v = ((float4*)(Qs + q * LDQ))[d4];
        v.x *= inv_l; v.y *= inv_l; v.z *= inv_l; v.w *= inv_l;
        ((float4*)(Og + (size_t)q * H))[d4] = v;
    }
}

// ---------------- LayerNorm (one warp per row) ----------------
__global__ __launch_bounds__(256) void ln_kernel(const float* __restrict__ yin,
                                                 const float* __restrict__ g,
                                                 const float* __restrict__ b,
                                                 float* __restrict__ yout) {
    int row = blockIdx.x * 8 + (threadIdx.x >> 5);
    int lane = threadIdx.x & 31;
    const float* yr = yin + (size_t)row * H;
    float v[8], s = 0.f, sq = 0.f;
#pragma unroll
    for (int i = 0; i < 8; i++) {
        v[i] = yr[lane + i * 32];
        s += v[i];
        sq += v[i] * v[i];
    }
#pragma unroll
    for (int m = 16; m >= 1; m >>= 1) {
        s += __shfl_xor_sync(0xffffffffu, s, m);
        sq += __shfl_xor_sync(0xffffffffu, sq, m);
    }
    float mu = s * (1.f / H);
    float var = sq * (1.f / H) - mu * mu;
    float rstd = rsqrtf(var + EPS);
    float* yo = yout + (size_t)row * H;
#pragma unroll
    for (int i = 0; i < 8; i++) {
        int c = lane + i * 32;
        yo[c] = (v[i] - mu) * rstd * g[c] + b[c];
    }
}

// ---------------- GRU recurrence: 8-CTA cluster, bulk-copy exchange ----------
// R9 RNN changes vs R8: (1) role-swap butterfly — fold the 6 row-partials to
// 3 at level 1 with FSEL swaps, so the reduction is 3+12=15 shfls instead of
// 30; totals land directly on owner lanes 0/1. (2) hstage dropped — the bulk
// copy sources the CTA's own hbuf[p^1] slice (double-buffering transitively
// protects it from rewrite while in flight).
#define RB 8
#define RT 512

__device__ __forceinline__ unsigned int smem_u32(const void* p) {
    unsigned int a;
    asm("{ .reg .u64 t; cvta.to.shared.u64 t, %1; cvt.u32.u64 %0, t; }"
        : "=r"(a) : "l"(p));
    return a;
}

__device__ __forceinline__ void cluster_arrive_wait() {
    asm volatile("barrier.cluster.arrive.aligned;" ::: "memory");
    asm volatile("barrier.cluster.wait.aligned;" ::: "memory");
}

__device__ __forceinline__ void mbar_wait_parity(unsigned int mb,
                                                 unsigned int parity) {
    asm volatile(
        "{\n\t"
        ".reg .pred P;\n\t"
        "WL%=:\n\t"
        "mbarrier.try_wait.parity.acquire.cta.shared::cta.b64 P, [%0], %1, 0x989680;\n\t"
        "@!P bra WL%=;\n\t"
        "}"
        :: "r"(mb), "r"(parity) : "memory");
}

__global__ void __cluster_dims__(RB, 1, 1) __launch_bounds__(RT, 1)
rnn_kernel(const float* __restrict__ gi,
           const float* __restrict__ Whh,
           const float* __restrict__ bhh,
           float* __restrict__ out,
           int out_size) {
    __shared__ __align__(16) float hbuf[2][H];
    __shared__ __align__(8) unsigned long long mbar;

    int blk = blockIdx.x;
    int tid = threadIdx.x;
    int w = tid >> 5;                 // warp 0..15
    int lane = tid & 31;

    // weights: rows (g, dd) -> global row g*256 + blk*32 + w*2 + dd,
    // cols lane*8..lane*8+7, packed f32x2. 6 rows x 4 ull = 24 ull.
    unsigned long long w2[6][4];
#pragma unroll
    for (int g = 0; g < 3; g++) {
#pragma unroll
        for (int dd = 0; dd < 2; dd++) {
            int rowg = g * 256 + blk * 32 + w * 2 + dd;
            const unsigned long long* src =
                (const unsigned long long*)(Whh + (size_t)rowg * H + lane * 8);
#pragma unroll
            for (int i = 0; i < 4; i++) w2[g * 2 + dd][i] = src[i];
        }
    }

    for (int i = tid; i < 2 * H; i += RT) ((float*)hbuf)[i] = 0.f;

    unsigned int mb = smem_u32(&mbar);
    if (tid == 0) {
        asm volatile("mbarrier.init.shared.b64 [%0], %1;"
                     :: "r"(mb), "r"(1) : "memory");
    }

    // gate-owner lanes: lane 0/1 of each warp own dim d = w*2 + lane
    int d = w * 2 + lane;             // local dim, valid for lane < 2
    int j = blk * 32 + d;             // global dim
    bool owner = (lane < 2);
    float ir = 0.f, iz = 0.f, inn = 0.f, bh_r = 0.f, bh_z = 0.f, bh_n = 0.f;
    if (owner) {
        ir = gi[j];
        iz = gi[256 + j];
        inn = gi[512 + j];
        bh_r = bhh[j];
        bh_z = bhh[256 + j];
        bh_n = bhh[512 + j];
    }
    unsigned int hb0 = smem_u32(&hbuf[0][lane * 8]);
    unsigned int hb1 = smem_u32(&hbuf[1][lane * 8]);
    unsigned int sl0 = smem_u32(&hbuf[0][blk * 32]);   // our slice in hbuf[0]
    unsigned int sl1 = smem_u32(&hbuf[1][blk * 32]);
    __syncthreads();
    cluster_arrive_wait();   // hbufs zeroed + mbarriers initialized everywhere

    for (int t = 0; t < S; t++) {
        int p = t & 1;

        if (tid == 0) {
            // expect this phase's incoming bytes (7 remote CTAs x 128B)
            asm volatile("mbarrier.arrive.expect_tx.shared.b64 _, [%0], %1;"
                         :: "r"(mb), "r"(7 * 128) : "memory");
        }

        // ---- dot: 6 rows x 8 cols per thread (f32x2) ----
        unsigned int haddr = p ? hb1 : hb0;
        unsigned long long h2[4];
        asm volatile("ld.shared.v2.b64 {%0, %1}, [%4];\n\t"
                     "ld.shared.v2.b64 {%2, %3}, [%4 + 16];"
                     : "=l"(h2[0]), "=l"(h2[1]), "=l"(h2[2]), "=l"(h2[3])
                     : "r"(haddr));
        float a[6];
#pragma unroll
        for (int r = 0; r < 6; r++) {
            unsigned long long acc2 = 0ull;
#pragma unroll
            for (int i = 0; i < 4; i++) {
                asm("fma.rn.f32x2 %0, %1, %2, %0;"
                    : "+l"(acc2) : "l"(w2[r][i]), "l"(h2[i]));
            }
            float lo, hi;
            asm("mov.b64 {%0, %1}, %2;" : "=f"(lo), "=f"(hi) : "l"(acc2));
            a[r] = lo + hi;
        }

        // ---- role-swap reduction: 6 arrays -> 3 at level 1, then 4 levels ----
        bool odd = (lane & 1);
        float z3[3];
#pragma unroll
        for (int g = 0; g < 3; g++) {
            float x = a[2 * g], y = a[2 * g + 1];
            float keep = odd ? y : x;
            float send = odd ? x : y;
            z3[g] = keep + __shfl_xor_sync(0xffffffffu, send, 1);
        }
#pragma unroll
        for (int m = 2; m <= 16; m <<= 1) {
#pragma unroll
            for (int g = 0; g < 3; g++)
                z3[g] += __shfl_xor_sync(0xffffffffu, z3[g], m);
        }
        // lane dd now holds totals of rows {2g+dd}: z3[0]=r, z3[1]=z, z3[2]=n

        // ---- gate math in-warp (lanes 0..1 of every warp) ----
        if (owner) {
            float ghr = z3[0] + bh_r;
            float ghz = z3[1] + bh_z;
            float ghn = z3[2] + bh_n;
            float hold = hbuf[p][j];
            float r = 1.f / (1.f + __expf(-(ir + ghr)));
            float z = 1.f / (1.f + __expf(-(iz + ghz)));
            float narg = inn + r * ghn;
            float n = 1.f - 2.f / (1.f + __expf(2.f * narg));
            float hnew = (1.f - z) * n + z * hold;

            hbuf[p ^ 1][j] = hnew;      // self-delivery + bulk source
            // prefetch next token's gi (hidden by exchange wait)
            int tn = (t + 1 < S) ? (t + 1) : t;
            ir = gi[(size_t)tn * G3 + j];
            iz = gi[(size_t)tn * G3 + 256 + j];
            inn = gi[(size_t)tn * G3 + 512 + j];
        }
        __syncthreads();   // all 32 slice values visible (bar drains STS)

        // ---- parallel-issue exchange: 7 lanes, one bulk copy each ----
        if (tid < RB && tid != blk) {
            asm volatile("fence.proxy.async.shared::cta;" ::: "memory");
            unsigned int src = p ? sl0 : sl1;          // hbuf[p^1] local slice
            unsigned int pd, pm;
            asm volatile("mapa.shared::cluster.u32 %0, %1, %2;"
                         : "=r"(pd) : "r"(src), "r"(tid));
            asm volatile("mapa.shared::cluster.u32 %0, %1, %2;"
                         : "=r"(pm) : "r"(mb), "r"(tid));
            asm volatile(
                "cp.async.bulk.shared::cluster.shared::cta.mbarrier::complete_tx::bytes "
                "[%0], [%1], 128, [%2];"
                :: "r"(pd), "r"(src), "r"(pm) : "memory");
        }
        if (tid == 0) mbar_wait_parity(mb, (unsigned int)(t & 1));
        __syncthreads();   // release CTA once all 7 slices arrived
    }

    if (blk == 0) {
        for (int i = tid; i < out_size; i += RT)
            out[i] = hbuf[0][i & 255];
    }
}

// ---------------- host launcher ----------------
extern "C" void kernel_launch(void* const* d_in, const int* in_sizes, int n_in,
                              void* d_out, int out_size) {
    const int* tokens = (const int*)d_in[0];
    const float* emb = (const float*)d_in[1];
    const float* Wq = (const float*)d_in[2];
    const float* bq = (const float*)d_in[3];
    const float* Wk = (const float*)d_in[4];
    const float* bk = (const float*)d_in[5];
    const float* Wv = (const float*)d_in[6];
    const float* bv = (const float*)d_in[7];
    const float* Wo = (const float*)d_in[8];
    const float* bo = (const float*)d_in[9];
    const float* ln_g = (const float*)d_in[10];
    const float* ln_b = (const float*)d_in[11];
    const float* W_ih = (const float*)d_in[12];
    const float* W_hh = (const float*)d_in[13];
    const float* b_ih = (const float*)d_in[14];
    const float* b_hh = (const float*)d_in[15];
    float* out = (float*)d_out;

    float* px; cudaGetSymbolAddress((void**)&px, g_x);
    float* pq; cudaGetSymbolAddress((void**)&pq, g_q);
    float* pk; cudaGetSymbolAddress((void**)&pk, g_k);
    float* pv; cudaGetSymbolAddress((void**)&pv, g_v);
    float* po; cudaGetSymbolAddress((void**)&po, g_o);
    float* pypre; cudaGetSymbolAddress((void**)&pypre, g_ypre);
    float* py; cudaGetSymbolAddress((void**)&py, g_y);
    float* pgi; cudaGetSymbolAddress((void**)&pgi, g_gi);

    size_t attn_smem = (size_t)(3 * 64 * LDQ + 64 * LDP + 64) * sizeof(float);
    cudaFuncSetAttribute(attn_kernel, cudaFuncAttributeMaxDynamicSharedMemorySize,
                         (int)attn_smem);

    embed_kernel<<<S, 64>>>(tokens, emb);

    dim3 gqkv(4, 64, NH);
    gemm_w<0><<<gqkv, 256>>>(px, Wq, bq, nullptr, pq);
    gemm_w<0><<<gqkv, 256>>>(px, Wk, bk, nullptr, pk);
    gemm_w<0><<<gqkv, 256>>>(px, Wv, bv, nullptr, pv);

    dim3 gatt(S / 64, NH);
    attn_kernel<<<gatt, 256, attn_smem>>>(pq, pk, pv, po);

    dim3 gop(4, 64, 1);
    gemm_w<1><<<gop, 256>>>(po, Wo, bo, px, pypre);

    ln_kernel<<<S / 8, 256>>>(pypre, ln_g, ln_b, py);

    dim3 ggi(12, 64, 1);
    gemm_w<2><<<ggi, 256>>>(py, W_ih, b_ih, nullptr, pgi);

    rnn_kernel<<<RB, RT>>>(pgi, W_hh, b_hh, out, out_size);
}

// round 10
// speedup vs baseline: 3.9073x; 1.0078x over previous
#include <cuda_runtime.h>
#include <cuda_bf16.h>
#include <mma.h>
#include <math.h>
#include <stddef.h>

using namespace nvcuda;

#define S 4096
#define H 256
#define NH 6
#define G3 768
#define EPS 1e-5f

// ---------------- scratch (static device arrays; no allocation) ----------------
__device__ float g_x[S * H];            // embedded tokens
__device__ float g_q[NH * S * H];
__device__ float g_k[NH * S * H];
__device__ float g_v[NH * S * H];
__device__ float g_o[NH * S * H];       // attention output per head
__device__ float g_ypre[S * H];         // x + attn_proj (pre-LN)
__device__ float g_y[S * H];            // post-LN
__device__ float g_gi[S * G3];          // y @ W_ih^T + b_ih

// ---------------- embedding gather ----------------
__global__ void embed_kernel(const int* __restrict__ tokens,
                             const float* __restrict__ emb) {
    int s = blockIdx.x;
    int tok = tokens[s];
    const float4* src = (const float4*)(emb + (size_t)tok * H);
    float4* dst = (float4*)(g_x + (size_t)s * H);
    dst[threadIdx.x] = src[threadIdx.x];   // 64 threads * 4
}

// ---------------- WMMA tf32 GEMM (64x64 tile, 8 warps) -----------------------
// MODE 0: C[z] = X @ W[z] + bias[z]         (QKV; K=256, N=256, z=head)
// MODE 1: C = gather(g_o) @ Wo + bo + g_x   (out-proj + residual; K=1536)
#define LDG_ 68
template <int MODE>
__global__ __launch_bounds__(256) void gemm_w(const float* __restrict__ A,
                                              const float* __restrict__ B,
                                              const float* __restrict__ bias,
                                              const float* __restrict__ resid,
                                              float* __restrict__ C) {
    const int KTOT = (MODE == 1) ? 1536 : 256;
    const int NTOT = 256;
    __shared__ float As[64 * LDG_];
    __shared__ float Bs[64 * LDG_];
    int tid = threadIdx.x;
    int warp = tid >> 5;
    int wm = warp & 3;
    int wn = warp >> 2;
    int m0 = blockIdx.y * 64, n0 = blockIdx.x * 64;
    int z = blockIdx.z;
    const float* Bb = (MODE == 0) ? (B + (size_t)z * 256 * 256) : B;

    wmma::fragment<wmma::accumulator, 16, 16, 8, float> c[2];
    wmma::fill_fragment(c[0], 0.0f);
    wmma::fill_fragment(c[1], 0.0f);

    for (int k0 = 0; k0 < KTOT; k0 += 64) {
        const float* Asrc;
        if (MODE == 1) {
            Asrc = A + (size_t)(k0 >> 8) * (S * 256) + (k0 & 255);
        } else {
            Asrc = A + k0;
        }
        for (int i = tid; i < 64 * 16; i += 256) {
            int m = i >> 4, k4 = i & 15;
            float4 v = *(const float4*)(Asrc + (size_t)(m0 + m) * 256 + k4 * 4);
            *(float4*)(As + m * LDG_ + k4 * 4) = v;
        }
        for (int i = tid; i < 64 * 16; i += 256) {
            int kk = i >> 4, n4 = i & 15;
            float4 v = *(const float4*)(Bb + (size_t)(k0 + kk) * NTOT + n0 + n4 * 4);
            *(float4*)(Bs + kk * LDG_ + n4 * 4) = v;
        }
        __syncthreads();

        wmma::fragment<wmma::matrix_a, 16, 16, 8, wmma::precision::tf32,
                       wmma::row_major> af;
        wmma::fragment<wmma::matrix_b, 16, 16, 8, wmma::precision::tf32,
                       wmma::row_major> bf;
#pragma unroll
        for (int k = 0; k < 8; k++) {
            wmma::load_matrix_sync(af, As + (wm * 16) * LDG_ + k * 8, LDG_);
#pragma unroll
            for (int e = 0; e < af.num_elements; e++)
                af.x[e] = wmma::__float_to_tf32(af.x[e]);
#pragma unroll
            for (int nf = 0; nf < 2; nf++) {
                wmma::load_matrix_sync(
                    bf, Bs + (k * 8) * LDG_ + wn * 32 + nf * 16, LDG_);
#pragma unroll
                for (int e = 0; e < bf.num_elements; e++)
                    bf.x[e] = wmma::__float_to_tf32(bf.x[e]);
                wmma::mma_sync(c[nf], af, bf, c[nf]);
            }
        }
        __syncthreads();
    }

#pragma unroll
    for (int nf = 0; nf < 2; nf++)
        wmma::store_matrix_sync(As + (wm * 16) * LDG_ + wn * 32 + nf * 16,
                                c[nf], LDG_, wmma::mem_row_major);
    __syncthreads();

    for (int i = tid; i < 64 * 64; i += 256) {
        int m = i >> 6, n = i & 63;
        float v = As[m * LDG_ + n];
        int gm = m0 + m, gn = n0 + n;
        if (MODE == 0) {
            v += bias[z * 256 + gn];
            C[(size_t)z * S * 256 + (size_t)gm * 256 + gn] = v;
        } else {
            v += bias[gn] + resid[(size_t)gm * 256 + gn];
            C[(size_t)gm * 256 + gn] = v;
        }
    }
}

// ---------------- fp32 SIMT GEMM for gi = y @ W_ih^T + b_ih ------------------
// (kept fp32: gi feeds every GRU step pre-nonlinearity; tf32 here blew the
// rel_err margin to 3.3e-4 in R9)
__global__ __launch_bounds__(256) void gemm_gi(const float* __restrict__ A,
                                               const float* __restrict__ B,
                                               const float* __restrict__ bias,
                                               float* __restrict__ C) {
    __shared__ float As[64][65];
    __shared__ float Bs[64][65];
    int tid = threadIdx.x;
    int m0 = blockIdx.y * 64, n0 = blockIdx.x * 64;

    float acc[4][4];
#pragma unroll
    for (int i = 0; i < 4; i++)
#pragma unroll
        for (int j = 0; j < 4; j++) acc[i][j] = 0.f;

    int ty = tid >> 4, tx = tid & 15;

    for (int k0 = 0; k0 < 256; k0 += 64) {
#pragma unroll
        for (int i = 0; i < 16; i++) {
            int lin = i * 256 + tid;
            int m = lin >> 6, kk = lin & 63;
            As[m][kk] = A[(size_t)(m0 + m) * 256 + k0 + kk];
        }
#pragma unroll
        for (int i = 0; i < 16; i++) {
            int lin = i * 256 + tid;
            int n = lin >> 6, kk = lin & 63;
            Bs[kk][n] = B[(size_t)(n0 + n) * 256 + (k0 + kk)];
        }
        __syncthreads();
#pragma unroll 8
        for (int kk = 0; kk < 64; kk++) {
            float a[4], b[4];
#pragma unroll
            for (int i = 0; i < 4; i++) a[i] = As[ty * 4 + i][kk];
#pragma unroll
            for (int j = 0; j < 4; j++) b[j] = Bs[kk][tx * 4 + j];
#pragma unroll
            for (int i = 0; i < 4; i++)
#pragma unroll
                for (int j = 0; j < 4; j++) acc[i][j] += a[i] * b[j];
        }
        __syncthreads();
    }

#pragma unroll
    for (int i = 0; i < 4; i++) {
        int m = m0 + ty * 4 + i;
#pragma unroll
        for (int j = 0; j < 4; j++) {
            int n = n0 + tx * 4 + j;
            C[(size_t)m * 768 + n] = acc[i][j] + bias[n];
        }
    }
}

// ---------------- WMMA tf32 streaming attention ------------------------------
#define LDQ 268
#define LDP 76
__global__ __launch_bounds__(256) void attn_kernel(const float* __restrict__ Q,
                                                   const float* __restrict__ K,
                                                   const float* __restrict__ V,
                                                   float* __restrict__ O) {
    extern __shared__ float sm[];
    float* Qs = sm;
    float* Ks = Qs + 64 * LDQ;
    float* Vs = Ks + 64 * LDQ;
    float* Ps = Vs + 64 * LDQ;
    float* Ls = Ps + 64 * LDP;

    int h = blockIdx.y;
    int q0 = blockIdx.x * 64;
    int tid = threadIdx.x;
    int warp = tid >> 5;
    int wm = warp & 3;
    int wn = warp >> 2;

    const float* Qg = Q + ((size_t)h * S + q0) * H;
    const float* Kg = K + (size_t)h * S * H;
    const float* Vg = V + (size_t)h * S * H;

    for (int i = tid; i < 64 * 64; i += 256) {
        int q = i >> 6, d4 = i & 63;
        ((float4*)(Qs + q * LDQ))[d4] = ((const float4*)(Qg + (size_t)q * H))[d4];
    }

    wmma::fragment<wmma::accumulator, 16, 16, 8, float> o_frag[8];
#pragma unroll
    for (int f = 0; f < 8; f++) wmma::fill_fragment(o_frag[f], 0.0f);

    int lrow = tid >> 2;
    int lcol0 = (tid & 3) * 16;
    float l_part = 0.f;
    const float inv_scale = 0.0625f;

    for (int kt = 0; kt < S / 64; kt++) {
        __syncthreads();
        for (int i = tid; i < 64 * 64; i += 256) {
            int r = i >> 6, d4 = i & 63;
            ((float4*)(Ks + r * LDQ))[d4] =
                ((const float4*)(Kg + (size_t)(kt * 64 + r) * H))[d4];
            ((float4*)(Vs + r * LDQ))[d4] =
                ((const float4*)(Vg + (size_t)(kt * 64 + r) * H))[d4];
        }
        __syncthreads();

        {
            wmma::fragment<wmma::matrix_a, 16, 16, 8, wmma::precision::tf32,
                           wmma::row_major> af;
            wmma::fragment<wmma::matrix_b, 16, 16, 8, wmma::precision::tf32,
                           wmma::col_major> bf;
            wmma::fragment<wmma::accumulator, 16, 16, 8, float> c[2];
            wmma::fill_fragment(c[0], 0.0f);
            wmma::fill_fragment(c[1], 0.0f);
#pragma unroll 4
            for (int k = 0; k < 32; k++) {
                wmma::load_matrix_sync(af, Qs + (wm * 16) * LDQ + k * 8, LDQ);
#pragma unroll
                for (int e = 0; e < af.num_elements; e++)
                    af.x[e] = wmma::__float_to_tf32(af.x[e]);
#pragma unroll
                for (int nf = 0; nf < 2; nf++) {
                    wmma::load_matrix_sync(
                        bf, Ks + (wn * 32 + nf * 16) * LDQ + k * 8, LDQ);
#pragma unroll
                    for (int e = 0; e < bf.num_elements; e++)
                        bf.x[e] = wmma::__float_to_tf32(bf.x[e]);
                    wmma::mma_sync(c[nf], af, bf, c[nf]);
                }
            }
#pragma unroll
            for (int nf = 0; nf < 2; nf++)
                wmma::store_matrix_sync(
                    Ps + (wm * 16) * LDP + wn * 32 + nf * 16, c[nf], LDP,
                    wmma::mem_row_major);
        }
        __syncthreads();

        {
            float* pr = Ps + lrow * LDP + lcol0;
            float ssum = 0.f;
#pragma unroll
            for (int j = 0; j < 16; j++) {
                float e = __expf(pr[j] * inv_scale);
                pr[j] = e;
                ssum += e;
            }
            l_part += ssum;
        }
        __syncthreads();

        {
            wmma::fragment<wmma::matrix_a, 16, 16, 8, wmma::precision::tf32,
                           wmma::row_major> pa;
            wmma::fragment<wmma::matrix_b, 16, 16, 8, wmma::precision::tf32,
                           wmma::row_major> vb;
#pragma unroll
            for (int k = 0; k < 8; k++) {
                wmma::load_matrix_sync(pa, Ps + (wm * 16) * LDP + k * 8, LDP);
#pragma unroll
                for (int e = 0; e < pa.num_elements; e++)
                    pa.x[e] = wmma::__float_to_tf32(pa.x[e]);
#pragma unroll
                for (int nf = 0; nf < 8; nf++) {
                    wmma::load_matrix_sync(
                        vb, Vs + (k * 8) * LDQ + wn * 128 + nf * 16, LDQ);
#pragma unroll
                    for (int e = 0; e < vb.num_elements; e++)
                        vb.x[e] = wmma::__float_to_tf32(vb.x[e]);
                    wmma::mma_sync(o_frag[nf], pa, vb, o_frag[nf]);
                }
            }
        }
    }

    l_part += __shfl_xor_sync(0xffffffffu, l_part, 1);
    l_part += __shfl_xor_sync(0xffffffffu, l_part, 2);
    if ((tid & 3) == 0) Ls[lrow] = l_part;

#pragma unroll
    for (int nf = 0; nf < 8; nf++)
        wmma::store_matrix_sync(Qs + (wm * 16) * LDQ + wn * 128 + nf * 16,
                                o_frag[nf], LDQ, wmma::mem_row_major);
    __syncthreads();

    float* Og = O + ((size_t)h * S + q0) * H;
    for (int i = tid; i < 64 * 64; i += 256) {
        int q = i >> 6, d4 = i & 63;
        float inv_l = __frcp_rn(Ls[q]);
        float4 v = ((float4*)(Qs + q * LDQ))[d4];
        v.x *= inv_l; v.y *= inv_l; v.z *= inv_l; v.w *= inv_l;
        ((float4*)(Og + (size_t)q * H))[d4] = v;
    }
}

// ---------------- LayerNorm (one warp per row) ----------------
__global__ __launch_bounds__(256) void ln_kernel(const float* __restrict__ yin,
                                                 const float* __restrict__ g,
                                                 const float* __restrict__ b,
                                                 float* __restrict__ yout) {
    int row = blockIdx.x * 8 + (threadIdx.x >> 5);
    int lane = threadIdx.x & 31;
    const float* yr = yin + (size_t)row * H;
    float v[8], s = 0.f, sq = 0.f;
#pragma unroll
    for (int i = 0; i < 8; i++) {
        v[i] = yr[lane + i * 32];
        s += v[i];
        sq += v[i] * v[i];
    }
#pragma unroll
    for (int m = 16; m >= 1; m >>= 1) {
        s += __shfl_xor_sync(0xffffffffu, s, m);
        sq += __shfl_xor_sync(0xffffffffu, sq, m);
    }
    float mu = s * (1.f / H);
    float var = sq * (1.f / H) - mu * mu;
    float rstd = rsqrtf(var + EPS);
    float* yo = yout + (size_t)row * H;
#pragma unroll
    for (int i = 0; i < 8; i++) {
        int c = lane + i * 32;
        yo[c] = (v[i] - mu) * rstd * g[c] + b[c];
    }
}

// ---------------- GRU recurrence: 8-CTA cluster, bulk-copy exchange ----------
// R10: (1) elected-waiter-per-warp (lane0 try_wait + __syncwarp; no final CTA
// barrier, no tid0 broadcast hop); (2) dual-parity mbarriers mb[0]/mb[1] with
// expect_tx for phase t+2 re-armed off the critical path right after the
// phase-t wait (race-free: any t+2 copy transitively requires our t+1 copies).
#define RB 8
#define RT 512

__device__ __forceinline__ unsigned int smem_u32(const void* p) {
    unsigned int a;
    asm("{ .reg .u64 t; cvta.to.shared.u64 t, %1; cvt.u32.u64 %0, t; }"
        : "=r"(a) : "l"(p));
    return a;
}

__device__ __forceinline__ void cluster_arrive_wait() {
    asm volatile("barrier.cluster.arrive.aligned;" ::: "memory");
    asm volatile("barrier.cluster.wait.aligned;" ::: "memory");
}

__device__ __forceinline__ void mbar_wait_parity(unsigned int mb,
                                                 unsigned int parity) {
    asm volatile(
        "{\n\t"
        ".reg .pred P;\n\t"
        "WL%=:\n\t"
        "mbarrier.try_wait.parity.acquire.cta.shared::cta.b64 P, [%0], %1, 0x989680;\n\t"
        "@!P bra WL%=;\n\t"
        "}"
        :: "r"(mb), "r"(parity) : "memory");
}

__global__ void __cluster_dims__(RB, 1, 1) __launch_bounds__(RT, 1)
rnn_kernel(const float* __restrict__ gi,
           const float* __restrict__ Whh,
           const float* __restrict__ bhh,
           float* __restrict__ out,
           int out_size) {
    __shared__ __align__(16) float hbuf[2][H];
    __shared__ __align__(8) unsigned long long mbar[2];

    int blk = blockIdx.x;
    int tid = threadIdx.x;
    int w = tid >> 5;                 // warp 0..15
    int lane = tid & 31;

    // weights: rows (g, dd) -> global row g*256 + blk*32 + w*2 + dd,
    // cols lane*8..lane*8+7, packed f32x2. 6 rows x 4 ull = 24 ull.
    unsigned long long w2[6][4];
#pragma unroll
    for (int g = 0; g < 3; g++) {
#pragma unroll
        for (int dd = 0; dd < 2; dd++) {
            int rowg = g * 256 + blk * 32 + w * 2 + dd;
            const unsigned long long* src =
                (const unsigned long long*)(Whh + (size_t)rowg * H + lane * 8);
#pragma unroll
            for (int i = 0; i < 4; i++) w2[g * 2 + dd][i] = src[i];
        }
    }

    for (int i = tid; i < 2 * H; i += RT) ((float*)hbuf)[i] = 0.f;

    unsigned int mb0 = smem_u32(&mbar[0]);
    unsigned int mb1 = smem_u32(&mbar[1]);
    if (tid == 0) {
        asm volatile("mbarrier.init.shared.b64 [%0], %1;"
                     :: "r"(mb0), "r"(1) : "memory");
        asm volatile("mbarrier.init.shared.b64 [%0], %1;"
                     :: "r"(mb1), "r"(1) : "memory");
        // pre-arm both parities' first phase
        asm volatile("mbarrier.arrive.expect_tx.shared.b64 _, [%0], %1;"
                     :: "r"(mb0), "r"(7 * 128) : "memory");
        asm volatile("mbarrier.arrive.expect_tx.shared.b64 _, [%0], %1;"
                     :: "r"(mb1), "r"(7 * 128) : "memory");
    }

    // gate-owner lanes: lane 0/1 of each warp own dim d = w*2 + lane
    int d = w * 2 + lane;             // local dim, valid for lane < 2
    int j = blk * 32 + d;             // global dim
    bool owner = (lane < 2);
    float ir = 0.f, iz = 0.f, inn = 0.f, bh_r = 0.f, bh_z = 0.f, bh_n = 0.f;
    if (owner) {
        ir = gi[j];
        iz = gi[256 + j];
        inn = gi[512 + j];
        bh_r = bhh[j];
        bh_z = bhh[256 + j];
        bh_n = bhh[512 + j];
    }
    unsigned int hb0 = smem_u32(&hbuf[0][lane * 8]);
    unsigned int hb1 = smem_u32(&hbuf[1][lane * 8]);
    unsigned int sl0 = smem_u32(&hbuf[0][blk * 32]);   // our slice in hbuf[0]
    unsigned int sl1 = smem_u32(&hbuf[1][blk * 32]);
    __syncthreads();
    cluster_arrive_wait();   // hbufs zeroed + mbarriers armed everywhere

    for (int t = 0; t < S; t++) {
        int p = t & 1;

        // ---- dot: 6 rows x 8 cols per thread (f32x2) ----
        unsigned int haddr = p ? hb1 : hb0;
        unsigned long long h2[4];
        asm volatile("ld.shared.v2.b64 {%0, %1}, [%4];\n\t"
                     "ld.shared.v2.b64 {%2, %3}, [%4 + 16];"
                     : "=l"(h2[0]), "=l"(h2[1]), "=l"(h2[2]), "=l"(h2[3])
                     : "r"(haddr));
        float a[6];
#pragma unroll
        for (int r = 0; r < 6; r++) {
            unsigned long long acc2 = 0ull;
#pragma unroll
            for (int i = 0; i < 4; i++) {
                asm("fma.rn.f32x2 %0, %1, %2, %0;"
                    : "+l"(acc2) : "l"(w2[r][i]), "l"(h2[i]));
            }
            float lo, hi;
            asm("mov.b64 {%0, %1}, %2;" : "=f"(lo), "=f"(hi) : "l"(acc2));
            a[r] = lo + hi;
        }

        // ---- role-swap reduction: 6 -> 3 arrays at level 1, then 4 levels ----
        bool odd = (lane & 1);
        float z3[3];
#pragma unroll
        for (int g = 0; g < 3; g++) {
            float x = a[2 * g], y = a[2 * g + 1];
            float keep = odd ? y : x;
            float send = odd ? x : y;
            z3[g] = keep + __shfl_xor_sync(0xffffffffu, send, 1);
        }
#pragma unroll
        for (int m = 2; m <= 16; m <<= 1) {
#pragma unroll
            for (int g = 0; g < 3; g++)
                z3[g] += __shfl_xor_sync(0xffffffffu, z3[g], m);
        }

        // ---- gate math in-warp (lanes 0..1 of every warp) ----
        if (owner) {
            float ghr = z3[0] + bh_r;
            float ghz = z3[1] + bh_z;
            float ghn = z3[2] + bh_n;
            float hold = hbuf[p][j];
            float r = 1.f / (1.f + __expf(-(ir + ghr)));
            float z = 1.f / (1.f + __expf(-(iz + ghz)));
            float narg = inn + r * ghn;
            float n = 1.f - 2.f / (1.f + __expf(2.f * narg));
            float hnew = (1.f - z) * n + z * hold;

            hbuf[p ^ 1][j] = hnew;      // self-delivery + bulk source
            int tn = (t + 1 < S) ? (t + 1) : t;
            ir = gi[(size_t)tn * G3 + j];
            iz = gi[(size_t)tn * G3 + 256 + j];
            inn = gi[(size_t)tn * G3 + 512 + j];
        }
        __syncthreads();   // all 32 slice values visible (bar drains STS)

        // ---- parallel-issue exchange: 7 lanes, one bulk copy each ----
        unsigned int mbp = p ? mb1 : mb0;
        if (tid < RB && tid != blk) {
            asm volatile("fence.proxy.async.shared::cta;" ::: "memory");
            unsigned int src = p ? sl0 : sl1;          // hbuf[p^1] local slice
            unsigned int pd, pm;
            asm volatile("mapa.shared::cluster.u32 %0, %1, %2;"
                         : "=r"(pd) : "r"(src), "r"(tid));
            asm volatile("mapa.shared::cluster.u32 %0, %1, %2;"
                         : "=r"(pm) : "r"(mbp), "r"(tid));
            asm volatile(
                "cp.async.bulk.shared::cluster.shared::cta.mbarrier::complete_tx::bytes "
                "[%0], [%1], 128, [%2];"
                :: "r"(pd), "r"(src), "r"(pm) : "memory");
        }

        // ---- elected waiter per warp; re-arm this mbar for phase t+2 ----
        if (lane == 0) {
            mbar_wait_parity(mbp, (unsigned int)((t >> 1) & 1));
            if (tid == 0) {
                asm volatile("mbarrier.arrive.expect_tx.shared.b64 _, [%0], %1;"
                             :: "r"(mbp), "r"(7 * 128) : "memory");
            }
        }
        __syncwarp();      // carries lane0's acquire to the whole warp
    }

    if (blk == 0) {
        for (int i = tid; i < out_size; i += RT)
            out[i] = hbuf[0][i & 255];
    }
}

// ---------------- host launcher ----------------
extern "C" void kernel_launch(void* const* d_in, const int* in_sizes, int n_in,
                              void* d_out, int out_size) {
    const int* tokens = (const int*)d_in[0];
    const float* emb = (const float*)d_in[1];
    const float* Wq = (const float*)d_in[2];
    const float* bq = (const float*)d_in[3];
    const float* Wk = (const float*)d_in[4];
    const float* bk = (const float*)d_in[5];
    const float* Wv = (const float*)d_in[6];
    const float* bv = (const float*)d_in[7];
    const float* Wo = (const float*)d_in[8];
    const float* bo = (const float*)d_in[9];
    const float* ln_g = (const float*)d_in[10];
    const float* ln_b = (const float*)d_in[11];
    const float* W_ih = (const float*)d_in[12];
    const float* W_hh = (const float*)d_in[13];
    const float* b_ih = (const float*)d_in[14];
    const float* b_hh = (const float*)d_in[15];
    float* out = (float*)d_out;

    float* px; cudaGetSymbolAddress((void**)&px, g_x);
    float* pq; cudaGetSymbolAddress((void**)&pq, g_q);
    float* pk; cudaGetSymbolAddress((void**)&pk, g_k);
    float* pv; cudaGetSymbolAddress((void**)&pv, g_v);
    float* po; cudaGetSymbolAddress((void**)&po, g_o);
    float* pypre; cudaGetSymbolAddress((void**)&pypre, g_ypre);
    float* py; cudaGetSymbolAddress((void**)&py, g_y);
    float* pgi; cudaGetSymbolAddress((void**)&pgi, g_gi);

    size_t attn_smem = (size_t)(3 * 64 * LDQ + 64 * LDP + 64) * sizeof(float);
    cudaFuncSetAttribute(attn_kernel, cudaFuncAttributeMaxDynamicSharedMemorySize,
                         (int)attn_smem);

    embed_kernel<<<S, 64>>>(tokens, emb);

    dim3 gqkv(4, 64, NH);
    gemm_w<0><<<gqkv, 256>>>(px, Wq, bq, nullptr, pq);
    gemm_w<0><<<gqkv, 256>>>(px, Wk, bk, nullptr, pk);
    gemm_w<0><<<gqkv, 256>>>(px, Wv, bv, nullptr, pv);

    dim3 gatt(S / 64, NH);
    attn_kernel<<<gatt, 256, attn_smem>>>(pq, pk, pv, po);

    dim3 gop(4, 64, 1);
    gemm_w<1><<<gop, 256>>>(po, Wo, bo, px, pypre);

    ln_kernel<<<S / 8, 256>>>(pypre, ln_g, ln_b, py);

    dim3 ggi(12, 64, 1);
    gemm_gi<<<ggi, 256>>>(py, W_ih, b_ih, pgi);

    rnn_kernel<<<RB, RT>>>(pgi, W_hh, b_hh, out, out_size);
}

// round 11
// speedup vs baseline: 4.1187x; 1.0541x over previous
#include <cuda_runtime.h>
#include <cuda_bf16.h>
#include <mma.h>
#include <math.h>
#include <stddef.h>

using namespace nvcuda;

#define S 4096
#define H 256
#define NH 6
#define G3 768
#define EPS 1e-5f

// ---------------- scratch (static device arrays; no allocation) ----------------
__device__ float g_x[S * H];            // embedded tokens
__device__ float g_q[NH * S * H];
__device__ float g_k[NH * S * H];
__device__ float g_v[NH * S * H];
__device__ float g_o[NH * S * H];       // attention output per head
__device__ float g_ypre[S * H];         // x + attn_proj (pre-LN)
__device__ float g_y[S * H];            // post-LN
__device__ float g_gi[S * G3];          // y @ W_ih^T + b_ih

// ---------------- embedding gather ----------------
__global__ void embed_kernel(const int* __restrict__ tokens,
                             const float* __restrict__ emb) {
    int s = blockIdx.x;
    int tok = tokens[s];
    const float4* src = (const float4*)(emb + (size_t)tok * H);
    float4* dst = (float4*)(g_x + (size_t)s * H);
    dst[threadIdx.x] = src[threadIdx.x];   // 64 threads * 4
}

// ---------------- WMMA tf32 GEMM (64x64 tile, 8 warps) -----------------------
// MODE 0: C[z] = X @ W[z] + bias[z]         (QKV; K=256, N=256, z=head)
// MODE 1: C = gather(g_o) @ Wo + bo + g_x   (out-proj + residual; K=1536)
#define LDG_ 68
template <int MODE>
__global__ __launch_bounds__(256) void gemm_w(const float* __restrict__ A,
                                              const float* __restrict__ B,
                                              const float* __restrict__ bias,
                                              const float* __restrict__ resid,
                                              float* __restrict__ C) {
    const int KTOT = (MODE == 1) ? 1536 : 256;
    const int NTOT = 256;
    __shared__ float As[64 * LDG_];
    __shared__ float Bs[64 * LDG_];
    int tid = threadIdx.x;
    int warp = tid >> 5;
    int wm = warp & 3;
    int wn = warp >> 2;
    int m0 = blockIdx.y * 64, n0 = blockIdx.x * 64;
    int z = blockIdx.z;
    const float* Bb = (MODE == 0) ? (B + (size_t)z * 256 * 256) : B;

    wmma::fragment<wmma::accumulator, 16, 16, 8, float> c[2];
    wmma::fill_fragment(c[0], 0.0f);
    wmma::fill_fragment(c[1], 0.0f);

    for (int k0 = 0; k0 < KTOT; k0 += 64) {
        const float* Asrc;
        if (MODE == 1) {
            Asrc = A + (size_t)(k0 >> 8) * (S * 256) + (k0 & 255);
        } else {
            Asrc = A + k0;
        }
        for (int i = tid; i < 64 * 16; i += 256) {
            int m = i >> 4, k4 = i & 15;
            float4 v = *(const float4*)(Asrc + (size_t)(m0 + m) * 256 + k4 * 4);
            *(float4*)(As + m * LDG_ + k4 * 4) = v;
        }
        for (int i = tid; i < 64 * 16; i += 256) {
            int kk = i >> 4, n4 = i & 15;
            float4 v = *(const float4*)(Bb + (size_t)(k0 + kk) * NTOT + n0 + n4 * 4);
            *(float4*)(Bs + kk * LDG_ + n4 * 4) = v;
        }
        __syncthreads();

        wmma::fragment<wmma::matrix_a, 16, 16, 8, wmma::precision::tf32,
                       wmma::row_major> af;
        wmma::fragment<wmma::matrix_b, 16, 16, 8, wmma::precision::tf32,
                       wmma::row_major> bf;
#pragma unroll
        for (int k = 0; k < 8; k++) {
            wmma::load_matrix_sync(af, As + (wm * 16) * LDG_ + k * 8, LDG_);
#pragma unroll
            for (int e = 0; e < af.num_elements; e++)
                af.x[e] = wmma::__float_to_tf32(af.x[e]);
#pragma unroll
            for (int nf = 0; nf < 2; nf++) {
                wmma::load_matrix_sync(
                    bf, Bs + (k * 8) * LDG_ + wn * 32 + nf * 16, LDG_);
#pragma unroll
                for (int e = 0; e < bf.num_elements; e++)
                    bf.x[e] = wmma::__float_to_tf32(bf.x[e]);
                wmma::mma_sync(c[nf], af, bf, c[nf]);
            }
        }
        __syncthreads();
    }

#pragma unroll
    for (int nf = 0; nf < 2; nf++)
        wmma::store_matrix_sync(As + (wm * 16) * LDG_ + wn * 32 + nf * 16,
                                c[nf], LDG_, wmma::mem_row_major);
    __syncthreads();

    for (int i = tid; i < 64 * 64; i += 256) {
        int m = i >> 6, n = i & 63;
        float v = As[m * LDG_ + n];
        int gm = m0 + m, gn = n0 + n;
        if (MODE == 0) {
            v += bias[z * 256 + gn];
            C[(size_t)z * S * 256 + (size_t)gm * 256 + gn] = v;
        } else {
            v += bias[gn] + resid[(size_t)gm * 256 + gn];
            C[(size_t)gm * 256 + gn] = v;
        }
    }
}

// ---------------- fp32 SIMT GEMM for gi = y @ W_ih^T + b_ih ------------------
__global__ __launch_bounds__(256) void gemm_gi(const float* __restrict__ A,
                                               const float* __restrict__ B,
                                               const float* __restrict__ bias,
                                               float* __restrict__ C) {
    __shared__ float As[64][65];
    __shared__ float Bs[64][65];
    int tid = threadIdx.x;
    int m0 = blockIdx.y * 64, n0 = blockIdx.x * 64;

    float acc[4][4];
#pragma unroll
    for (int i = 0; i < 4; i++)
#pragma unroll
        for (int j = 0; j < 4; j++) acc[i][j] = 0.f;

    int ty = tid >> 4, tx = tid & 15;

    for (int k0 = 0; k0 < 256; k0 += 64) {
#pragma unroll
        for (int i = 0; i < 16; i++) {
            int lin = i * 256 + tid;
            int m = lin >> 6, kk = lin & 63;
            As[m][kk] = A[(size_t)(m0 + m) * 256 + k0 + kk];
        }
#pragma unroll
        for (int i = 0; i < 16; i++) {
            int lin = i * 256 + tid;
            int n = lin >> 6, kk = lin & 63;
            Bs[kk][n] = B[(size_t)(n0 + n) * 256 + (k0 + kk)];
        }
        __syncthreads();
#pragma unroll 8
        for (int kk = 0; kk < 64; kk++) {
            float a[4], b[4];
#pragma unroll
            for (int i = 0; i < 4; i++) a[i] = As[ty * 4 + i][kk];
#pragma unroll
            for (int j = 0; j < 4; j++) b[j] = Bs[kk][tx * 4 + j];
#pragma unroll
            for (int i = 0; i < 4; i++)
#pragma unroll
                for (int j = 0; j < 4; j++) acc[i][j] += a[i] * b[j];
        }
        __syncthreads();
    }

#pragma unroll
    for (int i = 0; i < 4; i++) {
        int m = m0 + ty * 4 + i;
#pragma unroll
        for (int j = 0; j < 4; j++) {
            int n = n0 + tx * 4 + j;
            C[(size_t)m * 768 + n] = acc[i][j] + bias[n];
        }
    }
}

// ---------------- WMMA tf32 streaming attention ------------------------------
#define LDQ 268
#define LDP 76
__global__ __launch_bounds__(256) void attn_kernel(const float* __restrict__ Q,
                                                   const float* __restrict__ K,
                                                   const float* __restrict__ V,
                                                   float* __restrict__ O) {
    extern __shared__ float sm[];
    float* Qs = sm;
    float* Ks = Qs + 64 * LDQ;
    float* Vs = Ks + 64 * LDQ;
    float* Ps = Vs + 64 * LDQ;
    float* Ls = Ps + 64 * LDP;

    int h = blockIdx.y;
    int q0 = blockIdx.x * 64;
    int tid = threadIdx.x;
    int warp = tid >> 5;
    int wm = warp & 3;
    int wn = warp >> 2;

    const float* Qg = Q + ((size_t)h * S + q0) * H;
    const float* Kg = K + (size_t)h * S * H;
    const float* Vg = V + (size_t)h * S * H;

    for (int i = tid; i < 64 * 64; i += 256) {
        int q = i >> 6, d4 = i & 63;
        ((float4*)(Qs + q * LDQ))[d4] = ((const float4*)(Qg + (size_t)q * H))[d4];
    }

    wmma::fragment<wmma::accumulator, 16, 16, 8, float> o_frag[8];
#pragma unroll
    for (int f = 0; f < 8; f++) wmma::fill_fragment(o_frag[f], 0.0f);

    int lrow = tid >> 2;
    int lcol0 = (tid & 3) * 16;
    float l_part = 0.f;
    const float inv_scale = 0.0625f;

    for (int kt = 0; kt < S / 64; kt++) {
        __syncthreads();
        for (int i = tid; i < 64 * 64; i += 256) {
            int r = i >> 6, d4 = i & 63;
            ((float4*)(Ks + r * LDQ))[d4] =
                ((const float4*)(Kg + (size_t)(kt * 64 + r) * H))[d4];
            ((float4*)(Vs + r * LDQ))[d4] =
                ((const float4*)(Vg + (size_t)(kt * 64 + r) * H))[d4];
        }
        __syncthreads();

        {
            wmma::fragment<wmma::matrix_a, 16, 16, 8, wmma::precision::tf32,
                           wmma::row_major> af;
            wmma::fragment<wmma::matrix_b, 16, 16, 8, wmma::precision::tf32,
                           wmma::col_major> bf;
            wmma::fragment<wmma::accumulator, 16, 16, 8, float> c[2];
            wmma::fill_fragment(c[0], 0.0f);
            wmma::fill_fragment(c[1], 0.0f);
#pragma unroll 4
            for (int k = 0; k < 32; k++) {
                wmma::load_matrix_sync(af, Qs + (wm * 16) * LDQ + k * 8, LDQ);
#pragma unroll
                for (int e = 0; e < af.num_elements; e++)
                    af.x[e] = wmma::__float_to_tf32(af.x[e]);
#pragma unroll
                for (int nf = 0; nf < 2; nf++) {
                    wmma::load_matrix_sync(
                        bf, Ks + (wn * 32 + nf * 16) * LDQ + k * 8, LDQ);
#pragma unroll
                    for (int e = 0; e < bf.num_elements; e++)
                        bf.x[e] = wmma::__float_to_tf32(bf.x[e]);
                    wmma::mma_sync(c[nf], af, bf, c[nf]);
                }
            }
#pragma unroll
            for (int nf = 0; nf < 2; nf++)
                wmma::store_matrix_sync(
                    Ps + (wm * 16) * LDP + wn * 32 + nf * 16, c[nf], LDP,
                    wmma::mem_row_major);
        }
        __syncthreads();

        {
            float* pr = Ps + lrow * LDP + lcol0;
            float ssum = 0.f;
#pragma unroll
            for (int j = 0; j < 16; j++) {
                float e = __expf(pr[j] * inv_scale);
                pr[j] = e;
                ssum += e;
            }
            l_part += ssum;
        }
        __syncthreads();

        {
            wmma::fragment<wmma::matrix_a, 16, 16, 8, wmma::precision::tf32,
                           wmma::row_major> pa;
            wmma::fragment<wmma::matrix_b, 16, 16, 8, wmma::precision::tf32,
                           wmma::row_major> vb;
#pragma unroll
            for (int k = 0; k < 8; k++) {
                wmma::load_matrix_sync(pa, Ps + (wm * 16) * LDP + k * 8, LDP);
#pragma unroll
                for (int e = 0; e < pa.num_elements; e++)
                    pa.x[e] = wmma::__float_to_tf32(pa.x[e]);
#pragma unroll
                for (int nf = 0; nf < 8; nf++) {
                    wmma::load_matrix_sync(
                        vb, Vs + (k * 8) * LDQ + wn * 128 + nf * 16, LDQ);
#pragma unroll
                    for (int e = 0; e < vb.num_elements; e++)
                        vb.x[e] = wmma::__float_to_tf32(vb.x[e]);
                    wmma::mma_sync(o_frag[nf], pa, vb, o_frag[nf]);
                }
            }
        }
    }

    l_part += __shfl_xor_sync(0xffffffffu, l_part, 1);
    l_part += __shfl_xor_sync(0xffffffffu, l_part, 2);
    if ((tid & 3) == 0) Ls[lrow] = l_part;

#pragma unroll
    for (int nf = 0; nf < 8; nf++)
        wmma::store_matrix_sync(Qs + (wm * 16) * LDQ + wn * 128 + nf * 16,
                                o_frag[nf], LDQ, wmma::mem_row_major);
    __syncthreads();

    float* Og = O + ((size_t)h * S + q0) * H;
    for (int i = tid; i < 64 * 64; i += 256) {
        int q = i >> 6, d4 = i & 63;
        float inv_l = __frcp_rn(Ls[q]);
        float4 v = ((float4*)(Qs + q * LDQ))[d4];
        v.x *= inv_l; v.y *= inv_l; v.z *= inv_l; v.w *= inv_l;
        ((float4*)(Og + (size_t)q * H))[d4] = v;
    }
}

// ---------------- LayerNorm (one warp per row) ----------------
__global__ __launch_bounds__(256) void ln_kernel(const float* __restrict__ yin,
                                                 const float* __restrict__ g,
                                                 const float* __restrict__ b,
                                                 float* __restrict__ yout) {
    int row = blockIdx.x * 8 + (threadIdx.x >> 5);
    int lane = threadIdx.x & 31;
    const float* yr = yin + (size_t)row * H;
    float v[8], s = 0.f, sq = 0.f;
#pragma unroll
    for (int i = 0; i < 8; i++) {
        v[i] = yr[lane + i * 32];
        s += v[i];
        sq += v[i] * v[i];
    }
#pragma unroll
    for (int m = 16; m >= 1; m >>= 1) {
        s += __shfl_xor_sync(0xffffffffu, s, m);
        sq += __shfl_xor_sync(0xffffffffu, sq, m);
    }
    float mu = s * (1.f / H);
    float var = sq * (1.f / H) - mu * mu;
    float rstd = rsqrtf(var + EPS);
    float* yo = yout + (size_t)row * H;
#pragma unroll
    for (int i = 0; i < 8; i++) {
        int c = lane + i * 32;
        yo[c] = (v[i] - mu) * rstd * g[c] + b[c];
    }
}

// ---------------- GRU recurrence: 8-CTA cluster, st.async exchange -----------
// R11: transport = st.async register-operand remote stores (data + tx fused at
// the remote mbar; raw DSMEM latency, no bulk engine, no proxy fence, no
// source staging). Each warp's two new h-dims are packed to b64 and lanes 0..7
// each fire ONE st.async to CTA==lane (self included), so the loop has NO
// CTA-wide barrier at all. expect_tx = 8 CTAs * 16 warps * 8B = 1024B/phase.
#define RB 8
#define RT 512

__device__ __forceinline__ unsigned int smem_u32(const void* p) {
    unsigned int a;
    asm("{ .reg .u64 t; cvta.to.shared.u64 t, %1; cvt.u32.u64 %0, t; }"
        : "=r"(a) : "l"(p));
    return a;
}

__device__ __forceinline__ void cluster_arrive_wait() {
    asm volatile("barrier.cluster.arrive.aligned;" ::: "memory");
    asm volatile("barrier.cluster.wait.aligned;" ::: "memory");
}

__device__ __forceinline__ void mbar_wait_parity(unsigned int mb,
                                                 unsigned int parity) {
    asm volatile(
        "{\n\t"
        ".reg .pred P;\n\t"
        "WL%=:\n\t"
        "mbarrier.try_wait.parity.acquire.cta.shared::cta.b64 P, [%0], %1, 0x989680;\n\t"
        "@!P bra WL%=;\n\t"
        "}"
        :: "r"(mb), "r"(parity) : "memory");
}

__global__ void __cluster_dims__(RB, 1, 1) __launch_bounds__(RT, 1)
rnn_kernel(const float* __restrict__ gi,
           const float* __restrict__ Whh,
           const float* __restrict__ bhh,
           float* __restrict__ out,
           int out_size) {
    __shared__ __align__(16) float hbuf[2][H];
    __shared__ __align__(8) unsigned long long mbar[2];

    int blk = blockIdx.x;
    int tid = threadIdx.x;
    int w = tid >> 5;                 // warp 0..15
    int lane = tid & 31;

    // weights: rows (g, dd) -> global row g*256 + blk*32 + w*2 + dd,
    // cols lane*8..lane*8+7, packed f32x2. 6 rows x 4 ull = 24 ull.
    unsigned long long w2[6][4];
#pragma unroll
    for (int g = 0; g < 3; g++) {
#pragma unroll
        for (int dd = 0; dd < 2; dd++) {
            int rowg = g * 256 + blk * 32 + w * 2 + dd;
            const unsigned long long* src =
                (const unsigned long long*)(Whh + (size_t)rowg * H + lane * 8);
#pragma unroll
            for (int i = 0; i < 4; i++) w2[g * 2 + dd][i] = src[i];
        }
    }

    for (int i = tid; i < 2 * H; i += RT) ((float*)hbuf)[i] = 0.f;

    unsigned int mb0 = smem_u32(&mbar[0]);
    unsigned int mb1 = smem_u32(&mbar[1]);
    if (tid == 0) {
        asm volatile("mbarrier.init.shared.b64 [%0], %1;"
                     :: "r"(mb0), "r"(1) : "memory");
        asm volatile("mbarrier.init.shared.b64 [%0], %1;"
                     :: "r"(mb1), "r"(1) : "memory");
        // pre-arm both parities' first phase (8*16*8 = 1024 bytes each)
        asm volatile("mbarrier.arrive.expect_tx.shared.b64 _, [%0], %1;"
                     :: "r"(mb0), "r"(1024) : "memory");
        asm volatile("mbarrier.arrive.expect_tx.shared.b64 _, [%0], %1;"
                     :: "r"(mb1), "r"(1024) : "memory");
    }

    // gate-owner lanes: lane 0/1 of each warp own dim d = w*2 + lane
    int d = w * 2 + lane;             // local dim, meaningful for lane < 2
    int j = blk * 32 + d;             // global dim (clamped below for lane>=2)
    int jc = j & 255;                 // safe smem index for non-owner lanes
    bool owner = (lane < 2);
    float ir = 0.f, iz = 0.f, inn = 0.f, bh_r = 0.f, bh_z = 0.f, bh_n = 0.f;
    if (owner) {
        ir = gi[j];
        iz = gi[256 + j];
        inn = gi[512 + j];
        bh_r = bhh[j];
        bh_z = bhh[256 + j];
        bh_n = bhh[512 + j];
    }
    unsigned int hb0 = smem_u32(&hbuf[0][lane * 8]);
    unsigned int hb1 = smem_u32(&hbuf[1][lane * 8]);

    // precompute remote addresses for lanes 0..7 (one target CTA per lane)
    unsigned int wl0 = smem_u32(&hbuf[0][blk * 32 + w * 2]);  // our slot
    unsigned int wl1 = smem_u32(&hbuf[1][blk * 32 + w * 2]);
    int rr = lane & 7;                // valid mapa rank for all lanes
    unsigned int pdst0, pdst1, pmb0, pmb1;
    asm("mapa.shared::cluster.u32 %0, %1, %2;" : "=r"(pdst0) : "r"(wl0), "r"(rr));
    asm("mapa.shared::cluster.u32 %0, %1, %2;" : "=r"(pdst1) : "r"(wl1), "r"(rr));
    asm("mapa.shared::cluster.u32 %0, %1, %2;" : "=r"(pmb0) : "r"(mb0), "r"(rr));
    asm("mapa.shared::cluster.u32 %0, %1, %2;" : "=r"(pmb1) : "r"(mb1), "r"(rr));

    __syncthreads();
    cluster_arrive_wait();   // hbufs zeroed + mbarriers armed everywhere

    for (int t = 0; t < S; t++) {
        int p = t & 1;

        // ---- dot: 6 rows x 8 cols per thread (f32x2) ----
        unsigned int haddr = p ? hb1 : hb0;
        unsigned long long h2[4];
        asm volatile("ld.shared.v2.b64 {%0, %1}, [%4];\n\t"
                     "ld.shared.v2.b64 {%2, %3}, [%4 + 16];"
                     : "=l"(h2[0]), "=l"(h2[1]), "=l"(h2[2]), "=l"(h2[3])
                     : "r"(haddr));
        float a[6];
#pragma unroll
        for (int r = 0; r < 6; r++) {
            unsigned long long acc2 = 0ull;
#pragma unroll
            for (int i = 0; i < 4; i++) {
                asm("fma.rn.f32x2 %0, %1, %2, %0;"
                    : "+l"(acc2) : "l"(w2[r][i]), "l"(h2[i]));
            }
            float lo, hi;
            asm("mov.b64 {%0, %1}, %2;" : "=f"(lo), "=f"(hi) : "l"(acc2));
            a[r] = lo + hi;
        }

        // ---- role-swap reduction: 6 -> 3 arrays at level 1, then 4 levels ----
        bool odd = (lane & 1);
        float z3[3];
#pragma unroll
        for (int g = 0; g < 3; g++) {
            float x = a[2 * g], y = a[2 * g + 1];
            float keep = odd ? y : x;
            float send = odd ? x : y;
            z3[g] = keep + __shfl_xor_sync(0xffffffffu, send, 1);
        }
#pragma unroll
        for (int m = 2; m <= 16; m <<= 1) {
#pragma unroll
            for (int g = 0; g < 3; g++)
                z3[g] += __shfl_xor_sync(0xffffffffu, z3[g], m);
        }
        // even lanes: totals of rows {2g}; odd lanes: rows {2g+1}

        // ---- gate math on ALL lanes (SIMT; only lanes 0/1 meaningful) ----
        float ghr = z3[0] + bh_r;
        float ghz = z3[1] + bh_z;
        float ghn = z3[2] + bh_n;
        float hold = hbuf[p][jc];
        float r = 1.f / (1.f + __expf(-(ir + ghr)));
        float z = 1.f / (1.f + __expf(-(iz + ghz)));
        float narg = inn + r * ghn;
        float n = 1.f - 2.f / (1.f + __expf(2.f * narg));
        float hnew = (1.f - z) * n + z * hold;

        // broadcast the warp's two dims, pack to b64
        float h0b = __shfl_sync(0xffffffffu, hnew, 0);
        float h1b = __shfl_sync(0xffffffffu, hnew, 1);
        unsigned long long pk;
        asm("mov.b64 %0, {%1, %2};" : "=l"(pk) : "f"(h0b), "f"(h1b));

        // ---- st.async exchange: lanes 0..7, one remote store each ----
        if (lane < 8) {
            unsigned int pd = p ? pdst0 : pdst1;   // write hbuf[p^1]
            unsigned int pm = p ? pmb1 : pmb0;     // count on mbar[p]
            asm volatile(
                "st.async.shared::cluster.mbarrier::complete_tx::bytes.b64 "
                "[%0], %1, [%2];"
                :: "r"(pd), "l"(pk), "r"(pm) : "memory");
        }

        // prefetch next token's gi (owner lanes; hidden by the wait)
        if (owner) {
            int tn = (t + 1 < S) ? (t + 1) : t;
            ir = gi[(size_t)tn * G3 + j];
            iz = gi[(size_t)tn * G3 + 256 + j];
            inn = gi[(size_t)tn * G3 + 512 + j];
        }

        // ---- elected waiter per warp; tid0 re-arms this mbar for t+2 ----
        unsigned int mbp = p ? mb1 : mb0;
        if (lane == 0) {
            mbar_wait_parity(mbp, (unsigned int)((t >> 1) & 1));
            if (tid == 0) {
                asm volatile("mbarrier.arrive.expect_tx.shared.b64 _, [%0], %1;"
                             :: "r"(mbp), "r"(1024) : "memory");
            }
        }
        __syncwarp();      // carries lane0's acquire to the whole warp
    }

    if (blk == 0) {
        for (int i = tid; i < out_size; i += RT)
            out[i] = hbuf[0][i & 255];
    }
}

// ---------------- host launcher ----------------
extern "C" void kernel_launch(void* const* d_in, const int* in_sizes, int n_in,
                              void* d_out, int out_size) {
    const int* tokens = (const int*)d_in[0];
    const float* emb = (const float*)d_in[1];
    const float* Wq = (const float*)d_in[2];
    const float* bq = (const float*)d_in[3];
    const float* Wk = (const float*)d_in[4];
    const float* bk = (const float*)d_in[5];
    const float* Wv = (const float*)d_in[6];
    const float* bv = (const float*)d_in[7];
    const float* Wo = (const float*)d_in[8];
    const float* bo = (const float*)d_in[9];
    const float* ln_g = (const float*)d_in[10];
    const float* ln_b = (const float*)d_in[11];
    const float* W_ih = (const float*)d_in[12];
    const float* W_hh = (const float*)d_in[13];
    const float* b_ih = (const float*)d_in[14];
    const float* b_hh = (const float*)d_in[15];
    float* out = (float*)d_out;

    float* px; cudaGetSymbolAddress((void**)&px, g_x);
    float* pq; cudaGetSymbolAddress((void**)&pq, g_q);
    float* pk; cudaGetSymbolAddress((void**)&pk, g_k);
    float* pv; cudaGetSymbolAddress((void**)&pv, g_v);
    float* po; cudaGetSymbolAddress((void**)&po, g_o);
    float* pypre; cudaGetSymbolAddress((void**)&pypre, g_ypre);
    float* py; cudaGetSymbolAddress((void**)&py, g_y);
    float* pgi; cudaGetSymbolAddress((void**)&pgi, g_gi);

    size_t attn_smem = (size_t)(3 * 64 * LDQ + 64 * LDP + 64) * sizeof(float);
    cudaFuncSetAttribute(attn_kernel, cudaFuncAttributeMaxDynamicSharedMemorySize,
                         (int)attn_smem);

    embed_kernel<<<S, 64>>>(tokens, emb);

    dim3 gqkv(4, 64, NH);
    gemm_w<0><<<gqkv, 256>>>(px, Wq, bq, nullptr, pq);
    gemm_w<0><<<gqkv, 256>>>(px, Wk, bk, nullptr, pk);
    gemm_w<0><<<gqkv, 256>>>(px, Wv, bv, nullptr, pv);

    dim3 gatt(S / 64, NH);
    attn_kernel<<<gatt, 256, attn_smem>>>(pq, pk, pv, po);

    dim3 gop(4, 64, 1);
    gemm_w<1><<<gop, 256>>>(po, Wo, bo, px, pypre);

    ln_kernel<<<S / 8, 256>>>(pypre, ln_g, ln_b, py);

    dim3 ggi(12, 64, 1);
    gemm_gi<<<ggi, 256>>>(py, W_ih, b_ih, pgi);

    rnn_kernel<<<RB, RT>>>(pgi, W_hh, b_hh, out, out_size);
}